// round 1
// baseline (speedup 1.0000x reference)
#include <cuda_runtime.h>
#include <stdint.h>

#define B_ 8192
#define D_ 256
#define KCODES 8192

// Scratch (device globals: no allocation allowed)
__device__ float g_zeA[B_ * D_];
__device__ float g_zeB[B_ * D_];
__device__ float g_bufA[B_ * D_];
__device__ float g_bufB[B_ * D_];
__device__ float g_e2[KCODES];
__device__ int   g_idxA[B_];
__device__ int   g_idxB[B_];

// ---------------------------------------------------------------------------
// Generic tiled fp32 GEMM: C = epi(A[M,K] @ Bm[K,N] + bias[N])
// EPI 0: bias only; 1: relu(.+bias); 2: Res + relu(.+bias)   (residual block)
// Tiles: BM=BN=64, BK=16, 256 threads, 4x4 micro-tile.
// ---------------------------------------------------------------------------
template <int EPI>
__global__ void __launch_bounds__(256) gemm_k(
    const float* __restrict__ A, const float* __restrict__ Bm,
    const float* __restrict__ bias, const float* __restrict__ Res,
    float* __restrict__ C, int M, int N, int K)
{
    __shared__ float As[16][68];   // pad 4: conflict-light transposed store, 16B-aligned rows
    __shared__ float Bs[16][64];

    const int t  = threadIdx.x;
    const int ty = t >> 4;         // 0..15
    const int tx = t & 15;         // 0..15
    const int m0 = blockIdx.y * 64;
    const int n0 = blockIdx.x * 64;

    const int arow = t >> 2, aseg = t & 3;     // A tile loader mapping
    const int brow = t >> 4, bseg = t & 15;    // B tile loader mapping

    const float* Aptr = A + (size_t)(m0 + arow) * K + aseg * 4;
    const float* Bptr = Bm + (size_t)brow * N + n0 + bseg * 4;

    float acc[4][4];
#pragma unroll
    for (int i = 0; i < 4; i++)
#pragma unroll
        for (int j = 0; j < 4; j++) acc[i][j] = 0.f;

    for (int kb = 0; kb < K; kb += 16) {
        float4 av = *(const float4*)(Aptr + kb);
        float4 bv = *(const float4*)(Bptr + (size_t)kb * N);
        As[aseg * 4 + 0][arow] = av.x;
        As[aseg * 4 + 1][arow] = av.y;
        As[aseg * 4 + 2][arow] = av.z;
        As[aseg * 4 + 3][arow] = av.w;
        *(float4*)&Bs[brow][bseg * 4] = bv;
        __syncthreads();
#pragma unroll
        for (int kk = 0; kk < 16; kk++) {
            float4 a4 = *(const float4*)&As[kk][ty * 4];
            float4 b4 = *(const float4*)&Bs[kk][tx * 4];
            float a[4] = {a4.x, a4.y, a4.z, a4.w};
            float b[4] = {b4.x, b4.y, b4.z, b4.w};
#pragma unroll
            for (int i = 0; i < 4; i++)
#pragma unroll
                for (int j = 0; j < 4; j++) acc[i][j] += a[i] * b[j];
        }
        __syncthreads();
    }

    float4 bb = *(const float4*)&bias[n0 + tx * 4];
    float bcol[4] = {bb.x, bb.y, bb.z, bb.w};
#pragma unroll
    for (int i = 0; i < 4; i++) {
        int m = m0 + ty * 4 + i;
        float v[4];
#pragma unroll
        for (int j = 0; j < 4; j++) {
            v[j] = acc[i][j] + bcol[j];
            if (EPI >= 1) v[j] = fmaxf(v[j], 0.f);
        }
        if (EPI == 2) {
            float4 r = *(const float4*)&Res[(size_t)m * N + n0 + tx * 4];
            v[0] += r.x; v[1] += r.y; v[2] += r.z; v[3] += r.w;
        }
        float4 o = {v[0], v[1], v[2], v[3]};
        *(float4*)&C[(size_t)m * N + n0 + tx * 4] = o;
    }
}

// ---------------------------------------------------------------------------
// Codebook squared norms: e2[k] = sum_d E[k,d]^2  (warp per code)
// ---------------------------------------------------------------------------
__global__ void __launch_bounds__(256) e2_k(const float* __restrict__ E,
                                            float* __restrict__ e2)
{
    int w = threadIdx.x >> 5, lane = threadIdx.x & 31;
    int code = blockIdx.x * 8 + w;
    float s = 0.f;
#pragma unroll
    for (int d = lane; d < 256; d += 32) {
        float v = E[(size_t)code * 256 + d];
        s += v * v;
    }
#pragma unroll
    for (int off = 16; off; off >>= 1) s += __shfl_xor_sync(0xFFFFFFFFu, s, off);
    if (lane == 0) e2[code] = s;
}

// ---------------------------------------------------------------------------
// VQ argmin: per row m, idx = argmin_k fl(fl(z2[m]+e2[k]) - 2*(z_m . E_k))
// Block: 32 rows, all 8192 codes (no cross-block reduction).
// 256 threads = 8(ty) x 32(tx); 4x4 micro-tile over (rows, codes).
// First-index tie-break via packed (score_bits<<32)|idx min-key (scores > 0).
// ---------------------------------------------------------------------------
__global__ void __launch_bounds__(256) vq_argmin_k(
    const float* __restrict__ Z, const float* __restrict__ E,
    const float* __restrict__ e2, int* __restrict__ idxOut)
{
    __shared__ float Zs[32][256];
    __shared__ float Es[16][132];  // pad 4
    __shared__ float z2s[32];

    const int t  = threadIdx.x;
    const int m0 = blockIdx.x * 32;

    // Load 32 z-rows (2048 float4 / 256 threads = 8 each)
#pragma unroll
    for (int i = 0; i < 8; i++) {
        int f = t + i * 256;
        int row = f >> 6, seg = f & 63;
        *(float4*)&Zs[row][seg * 4] =
            *(const float4*)&Z[(size_t)(m0 + row) * 256 + seg * 4];
    }
    __syncthreads();

    const int w = t >> 5, lane = t & 31;
    // z2 per row (warp w handles rows w*4..w*4+3)
#pragma unroll
    for (int i = 0; i < 4; i++) {
        int r = w * 4 + i;
        float s = 0.f;
#pragma unroll
        for (int k2 = lane; k2 < 256; k2 += 32) s += Zs[r][k2] * Zs[r][k2];
#pragma unroll
        for (int off = 16; off; off >>= 1) s += __shfl_xor_sync(0xFFFFFFFFu, s, off);
        if (lane == 0) z2s[r] = s;
    }
    __syncthreads();

    const int ty = w, tx = lane;
    unsigned long long best[4] = {~0ull, ~0ull, ~0ull, ~0ull};

    for (int cb = 0; cb < KCODES; cb += 128) {
        float acc[4][4];
#pragma unroll
        for (int i = 0; i < 4; i++)
#pragma unroll
            for (int j = 0; j < 4; j++) acc[i][j] = 0.f;

        for (int kb = 0; kb < 256; kb += 16) {
            // stage Es[16][128]: 512 float4 / 256 threads = 2 each
#pragma unroll
            for (int l = 0; l < 2; l++) {
                int f = t + l * 256;
                int code = f >> 2, seg = f & 3;
                float4 v = *(const float4*)&E[(size_t)(cb + code) * 256 + kb + seg * 4];
                Es[seg * 4 + 0][code] = v.x;
                Es[seg * 4 + 1][code] = v.y;
                Es[seg * 4 + 2][code] = v.z;
                Es[seg * 4 + 3][code] = v.w;
            }
            __syncthreads();
#pragma unroll
            for (int k4 = 0; k4 < 4; k4++) {
                float4 a[4], b[4];
#pragma unroll
                for (int i = 0; i < 4; i++)
                    a[i] = *(const float4*)&Zs[ty * 4 + i][kb + k4 * 4];
#pragma unroll
                for (int kc = 0; kc < 4; kc++)
                    b[kc] = *(const float4*)&Es[k4 * 4 + kc][tx * 4];
#pragma unroll
                for (int i = 0; i < 4; i++) {
                    float bx[4] = {b[0].x, b[0].y, b[0].z, b[0].w};
                    float by[4] = {b[1].x, b[1].y, b[1].z, b[1].w};
                    float bz[4] = {b[2].x, b[2].y, b[2].z, b[2].w};
                    float bw[4] = {b[3].x, b[3].y, b[3].z, b[3].w};
#pragma unroll
                    for (int j = 0; j < 4; j++) {
                        acc[i][j] += a[i].x * bx[j];
                        acc[i][j] += a[i].y * by[j];
                        acc[i][j] += a[i].z * bz[j];
                        acc[i][j] += a[i].w * bw[j];
                    }
                }
            }
            __syncthreads();
        }

        // Score + running argmin (codes scanned ascending; '<' keeps first index)
#pragma unroll
        for (int i = 0; i < 4; i++) {
            float z2v = z2s[ty * 4 + i];
#pragma unroll
            for (int j = 0; j < 4; j++) {
                int c = cb + tx * 4 + j;
                float t1 = z2v + e2[c];
                float s  = t1 - 2.0f * acc[i][j];   // matches fl(fl(z2+e2)-2*dot)
                unsigned long long key =
                    ((unsigned long long)__float_as_uint(s) << 32) | (unsigned)c;
                if (key < best[i]) best[i] = key;
            }
        }
    }

    // warp-level argmin across the 32 tx threads (each warp owns 4 rows)
#pragma unroll
    for (int i = 0; i < 4; i++) {
        unsigned long long k = best[i];
#pragma unroll
        for (int off = 16; off; off >>= 1) {
            unsigned long long o = __shfl_xor_sync(0xFFFFFFFFu, k, off);
            if (o < k) k = o;
        }
        if (tx == 0) idxOut[m0 + ty * 4 + i] = (int)(k & 0xFFFFFFFFull);
    }
}

// ---------------------------------------------------------------------------
// VQ apply: zOut = z + (q - z) (straight-through, exact expression),
//           loss = ss + 0.25*ss with ss = sum (z-q)^2
// ---------------------------------------------------------------------------
__global__ void __launch_bounds__(256) vq_apply_k(
    const float* __restrict__ Z, const float* __restrict__ E,
    const int* __restrict__ idx, float* __restrict__ zOut,
    float* __restrict__ loss)
{
    __shared__ float red[8];
    int m = blockIdx.x, d = threadIdx.x;
    int k = idx[m];
    float z = Z[(size_t)m * 256 + d];
    float q = E[(size_t)k * 256 + d];
    zOut[(size_t)m * 256 + d] = __fadd_rn(z, __fsub_rn(q, z));
    float diff = z - q;
    float ss = diff * diff;
#pragma unroll
    for (int off = 16; off; off >>= 1) ss += __shfl_xor_sync(0xFFFFFFFFu, ss, off);
    if ((d & 31) == 0) red[d >> 5] = ss;
    __syncthreads();
    if (d < 8) {
        float v = red[d];
#pragma unroll
        for (int off = 4; off; off >>= 1) v += __shfl_xor_sync(0xFFu, v, off);
        if (d == 0) loss[m] = v + 0.25f * v;
    }
}

// ---------------------------------------------------------------------------
// Host orchestration
// ---------------------------------------------------------------------------
extern "C" void kernel_launch(void* const* d_in, const int* in_sizes, int n_in,
                              void* d_out, int out_size)
{
    const float* x_a      = (const float*)d_in[0];
    const float* x_b      = (const float*)d_in[1];
    const float* enc_a_w  = (const float*)d_in[2];
    const float* enc_a_b  = (const float*)d_in[3];
    const float* enc_a_rw = (const float*)d_in[4];
    const float* enc_a_rb = (const float*)d_in[5];
    const float* enc_b_w  = (const float*)d_in[6];
    const float* enc_b_b  = (const float*)d_in[7];
    const float* enc_b_rw = (const float*)d_in[8];
    const float* enc_b_rb = (const float*)d_in[9];
    const float* dec_a_rw = (const float*)d_in[10];
    const float* dec_a_rb = (const float*)d_in[11];
    const float* dec_a_w  = (const float*)d_in[12];
    const float* dec_a_b  = (const float*)d_in[13];
    const float* dec_b_rw = (const float*)d_in[14];
    const float* dec_b_rb = (const float*)d_in[15];
    const float* dec_b_w  = (const float*)d_in[16];
    const float* dec_b_b  = (const float*)d_in[17];
    const float* codebook = (const float*)d_in[18];

    float* out = (float*)d_out;

    float *zeA, *zeB, *bufA, *bufB, *e2;
    int *idxA, *idxB;
    cudaGetSymbolAddress((void**)&zeA,  g_zeA);
    cudaGetSymbolAddress((void**)&zeB,  g_zeB);
    cudaGetSymbolAddress((void**)&bufA, g_bufA);
    cudaGetSymbolAddress((void**)&bufB, g_bufB);
    cudaGetSymbolAddress((void**)&e2,   g_e2);
    cudaGetSymbolAddress((void**)&idxA, g_idxA);
    cudaGetSymbolAddress((void**)&idxB, g_idxB);

    // Output offsets (flattened tuple order)
    const size_t OFF_ZA = 0;
    const size_t OFF_ZB = (size_t)B_ * D_;
    const size_t OFF_LA = 2ull * B_ * D_;
    const size_t OFF_LB = OFF_LA + B_;
    const size_t OFF_RA = OFF_LB + B_;
    const size_t OFF_RB = OFF_RA + (size_t)B_ * 4096;
    const size_t OFF_XA = OFF_RB + (size_t)B_ * 2048;
    const size_t OFF_XB = OFF_XA + (size_t)B_ * 4096;

    const dim3 blk(256);
    const dim3 gSmall(256 / 64, B_ / 64);   // N=256 GEMMs
    const dim3 gDecA(4096 / 64, B_ / 64);
    const dim3 gDecB(2048 / 64, B_ / 64);

    // Codebook norms
    e2_k<<<KCODES / 8, blk>>>(codebook, e2);

    // --- Encoder A ---
    gemm_k<1><<<gSmall, blk>>>(x_a, enc_a_w, enc_a_b, nullptr, bufA, B_, 256, 4096);
    gemm_k<2><<<gSmall, blk>>>(bufA, enc_a_rw,          enc_a_rb,       bufA, bufB, B_, 256, 256);
    gemm_k<2><<<gSmall, blk>>>(bufB, enc_a_rw + 65536,  enc_a_rb + 256, bufB, zeA,  B_, 256, 256);

    // --- Encoder B ---
    gemm_k<1><<<gSmall, blk>>>(x_b, enc_b_w, enc_b_b, nullptr, bufA, B_, 256, 2048);
    gemm_k<2><<<gSmall, blk>>>(bufA, enc_b_rw,          enc_b_rb,       bufA, bufB, B_, 256, 256);
    gemm_k<2><<<gSmall, blk>>>(bufB, enc_b_rw + 65536,  enc_b_rb + 256, bufB, zeB,  B_, 256, 256);

    // --- VQ ---
    vq_argmin_k<<<B_ / 32, blk>>>(zeA, codebook, e2, idxA);
    vq_argmin_k<<<B_ / 32, blk>>>(zeB, codebook, e2, idxB);
    vq_apply_k<<<B_, blk>>>(zeA, codebook, idxA, out + OFF_ZA, out + OFF_LA);
    vq_apply_k<<<B_, blk>>>(zeB, codebook, idxB, out + OFF_ZB, out + OFF_LB);

    // --- Decoder A on z_a -> recon_a ---
    gemm_k<2><<<gSmall, blk>>>(out + OFF_ZA, dec_a_rw,         dec_a_rb,       out + OFF_ZA, bufA, B_, 256, 256);
    gemm_k<2><<<gSmall, blk>>>(bufA,         dec_a_rw + 65536, dec_a_rb + 256, bufA,         bufB, B_, 256, 256);
    gemm_k<0><<<gDecA,  blk>>>(bufB, dec_a_w, dec_a_b, nullptr, out + OFF_RA, B_, 4096, 256);

    // --- Decoder B on z_b -> recon_b ---
    gemm_k<2><<<gSmall, blk>>>(out + OFF_ZB, dec_b_rw,         dec_b_rb,       out + OFF_ZB, bufA, B_, 256, 256);
    gemm_k<2><<<gSmall, blk>>>(bufA,         dec_b_rw + 65536, dec_b_rb + 256, bufA,         bufB, B_, 256, 256);
    gemm_k<0><<<gDecB,  blk>>>(bufB, dec_b_w, dec_b_b, nullptr, out + OFF_RB, B_, 2048, 256);

    // --- Decoder A on z_b -> cross_recon_a ---
    gemm_k<2><<<gSmall, blk>>>(out + OFF_ZB, dec_a_rw,         dec_a_rb,       out + OFF_ZB, bufA, B_, 256, 256);
    gemm_k<2><<<gSmall, blk>>>(bufA,         dec_a_rw + 65536, dec_a_rb + 256, bufA,         bufB, B_, 256, 256);
    gemm_k<0><<<gDecA,  blk>>>(bufB, dec_a_w, dec_a_b, nullptr, out + OFF_XA, B_, 4096, 256);

    // --- Decoder B on z_a -> cross_recon_b ---
    gemm_k<2><<<gSmall, blk>>>(out + OFF_ZA, dec_b_rw,         dec_b_rb,       out + OFF_ZA, bufA, B_, 256, 256);
    gemm_k<2><<<gSmall, blk>>>(bufA,         dec_b_rw + 65536, dec_b_rb + 256, bufA,         bufB, B_, 256, 256);
    gemm_k<0><<<gDecB,  blk>>>(bufB, dec_b_w, dec_b_b, nullptr, out + OFF_XB, B_, 2048, 256);
}

// round 7
// speedup vs baseline: 1.7145x; 1.7145x over previous
#include <cuda_runtime.h>
#include <stdint.h>

#define B_ 8192
#define D_ 256
#define KCODES 8192

typedef unsigned long long ull;

// Scratch (device globals; no allocation allowed)
__device__ float g_ze[2 * B_ * D_];       // [zeA; zeB]
__device__ float g_buf0[2 * B_ * D_];
__device__ float g_buf1[2 * B_ * D_];
__device__ float g_z2[2 * B_];
__device__ float g_e2[KCODES];
__device__ int   g_idx[2 * B_];
__device__ float g_dist[(size_t)2 * B_ * KCODES];   // 536 MB approx scores

// ---------------------------------------------------------------------------
// fp32 SIMT GEMM (round-1, proven zero-flip for encoder path)
// ---------------------------------------------------------------------------
template <int EPI>
__global__ void __launch_bounds__(256) gemm_k(
    const float* __restrict__ A, const float* __restrict__ Bm,
    const float* __restrict__ bias, const float* __restrict__ Res,
    float* __restrict__ C, int M, int N, int K)
{
    __shared__ float As[16][68];
    __shared__ float Bs[16][64];

    const int t  = threadIdx.x;
    const int ty = t >> 4;
    const int tx = t & 15;
    const int m0 = blockIdx.y * 64;
    const int n0 = blockIdx.x * 64;

    const int arow = t >> 2, aseg = t & 3;
    const int brow = t >> 4, bseg = t & 15;

    const float* Aptr = A + (size_t)(m0 + arow) * K + aseg * 4;
    const float* Bptr = Bm + (size_t)brow * N + n0 + bseg * 4;

    float acc[4][4];
#pragma unroll
    for (int i = 0; i < 4; i++)
#pragma unroll
        for (int j = 0; j < 4; j++) acc[i][j] = 0.f;

    for (int kb = 0; kb < K; kb += 16) {
        float4 av = *(const float4*)(Aptr + kb);
        float4 bv = *(const float4*)(Bptr + (size_t)kb * N);
        As[aseg * 4 + 0][arow] = av.x;
        As[aseg * 4 + 1][arow] = av.y;
        As[aseg * 4 + 2][arow] = av.z;
        As[aseg * 4 + 3][arow] = av.w;
        *(float4*)&Bs[brow][bseg * 4] = bv;
        __syncthreads();
#pragma unroll
        for (int kk = 0; kk < 16; kk++) {
            float4 a4 = *(const float4*)&As[kk][ty * 4];
            float4 b4 = *(const float4*)&Bs[kk][tx * 4];
            float a[4] = {a4.x, a4.y, a4.z, a4.w};
            float b[4] = {b4.x, b4.y, b4.z, b4.w};
#pragma unroll
            for (int i = 0; i < 4; i++)
#pragma unroll
                for (int j = 0; j < 4; j++) acc[i][j] += a[i] * b[j];
        }
        __syncthreads();
    }

    float4 bb = *(const float4*)&bias[n0 + tx * 4];
    float bcol[4] = {bb.x, bb.y, bb.z, bb.w};
#pragma unroll
    for (int i = 0; i < 4; i++) {
        int m = m0 + ty * 4 + i;
        float v[4];
#pragma unroll
        for (int j = 0; j < 4; j++) {
            v[j] = acc[i][j] + bcol[j];
            if (EPI >= 1) v[j] = fmaxf(v[j], 0.f);
        }
        if (EPI == 2) {
            float4 r = *(const float4*)&Res[(size_t)m * N + n0 + tx * 4];
            v[0] += r.x; v[1] += r.y; v[2] += r.z; v[3] += r.w;
        }
        float4 o = {v[0], v[1], v[2], v[3]};
        *(float4*)&C[(size_t)m * N + n0 + tx * 4] = o;
    }
}

// ---------------------------------------------------------------------------
// tf32 helpers
// ---------------------------------------------------------------------------
__device__ __forceinline__ uint32_t f2tf32(float x) {
    uint32_t r;
    asm("cvt.rna.tf32.f32 %0, %1;" : "=r"(r) : "f"(x));
    return r;
}

__device__ __forceinline__ void mma_tf32(float* d, const uint32_t* a, const uint32_t* b) {
    asm volatile(
        "mma.sync.aligned.m16n8k8.row.col.f32.tf32.tf32.f32 "
        "{%0,%1,%2,%3}, {%4,%5,%6,%7}, {%8,%9}, {%0,%1,%2,%3};\n"
        : "+f"(d[0]), "+f"(d[1]), "+f"(d[2]), "+f"(d[3])
        : "r"(a[0]), "r"(a[1]), "r"(a[2]), "r"(a[3]), "r"(b[0]), "r"(b[1]));
}

// ---------------------------------------------------------------------------
// Tensor-core GEMM (tf32). PASSES=3: fp32-class; PASSES=1: plain tf32.
// EPI 0: bias; 2: Res + relu(.+bias)
// EPI 3: VQ score  s = fl(fl(z2[m]+e2[n]) - 2*acc), bias=e2, Res=z2, C0=dist.
//        For EPI 3, Bw is the codebook [N rows x K dims] ROW-MAJOR and the
//        B tile is gathered transposed (code-major) — round-2 validated.
// Tile 128x64, BK=16, 8 warps. Rows >= rowSplit go to C1 at (m - rowSplit).
// ---------------------------------------------------------------------------
template <int PASSES, int EPI>
__global__ void __launch_bounds__(256) gemm_tc(
    const float* __restrict__ A, const float* __restrict__ Bw,
    const float* __restrict__ bias, const float* __restrict__ Res,
    float* __restrict__ C0, float* __restrict__ C1, int rowSplit,
    int M, int N, int K)
{
    __shared__ float AsH[16][132];
    __shared__ float BsH[16][68];
    __shared__ float AsL[PASSES == 3 ? 16 : 1][132];
    __shared__ float BsL[PASSES == 3 ? 16 : 1][68];

    const int t = threadIdx.x;
    const int lane = t & 31;
    const int warp = t >> 5;
    const int warpM = warp & 3;
    const int warpN = warp >> 2;
    const int m0 = blockIdx.y * 128;
    const int n0 = blockIdx.x * 64;

    float acc[2][4][4];
#pragma unroll
    for (int mt = 0; mt < 2; mt++)
#pragma unroll
        for (int nt = 0; nt < 4; nt++)
#pragma unroll
            for (int c = 0; c < 4; c++) acc[mt][nt][c] = 0.f;

    const int aRow = t >> 2, aSeg = t & 3;
    const int bRow = t >> 4, bSeg = t & 15;
    const int eCode = t >> 2, eSeg = t & 3;   // EPI==3 transposed B loader

    for (int kb = 0; kb < K; kb += 16) {
#pragma unroll
        for (int h = 0; h < 2; h++) {
            int row = aRow + h * 64;
            float4 v = *(const float4*)&A[(size_t)(m0 + row) * K + kb + aSeg * 4];
            float x[4] = {v.x, v.y, v.z, v.w};
#pragma unroll
            for (int j = 0; j < 4; j++) {
                uint32_t hb = f2tf32(x[j]);
                AsH[aSeg * 4 + j][row] = __uint_as_float(hb);
                if constexpr (PASSES == 3) {
                    float lo = x[j] - __uint_as_float(hb);
                    AsL[aSeg * 4 + j][row] = __uint_as_float(f2tf32(lo));
                }
            }
        }
        if constexpr (EPI == 3) {
            // codebook row-major [N, K]: gather 64 codes x 16 dims, store [k][n]
            float4 v = *(const float4*)&Bw[(size_t)(n0 + eCode) * K + kb + eSeg * 4];
            float x[4] = {v.x, v.y, v.z, v.w};
#pragma unroll
            for (int j = 0; j < 4; j++)
                BsH[eSeg * 4 + j][eCode] = __uint_as_float(f2tf32(x[j]));
        } else {
            float4 v = *(const float4*)&Bw[(size_t)(kb + bRow) * N + n0 + bSeg * 4];
            float x[4] = {v.x, v.y, v.z, v.w};
#pragma unroll
            for (int j = 0; j < 4; j++) {
                uint32_t hb = f2tf32(x[j]);
                BsH[bRow][bSeg * 4 + j] = __uint_as_float(hb);
                if constexpr (PASSES == 3) {
                    float lo = x[j] - __uint_as_float(hb);
                    BsL[bRow][bSeg * 4 + j] = __uint_as_float(f2tf32(lo));
                }
            }
        }
        __syncthreads();

#pragma unroll
        for (int ks = 0; ks < 2; ks++) {
            uint32_t aH[2][4], aL[2][4], bH[4][2], bL[4][2];
            const int ar = warpM * 32 + (lane >> 2);
            const int ac = ks * 8 + (lane & 3);
#pragma unroll
            for (int mt = 0; mt < 2; mt++) {
                aH[mt][0] = __float_as_uint(AsH[ac][ar + mt * 16]);
                aH[mt][1] = __float_as_uint(AsH[ac][ar + mt * 16 + 8]);
                aH[mt][2] = __float_as_uint(AsH[ac + 4][ar + mt * 16]);
                aH[mt][3] = __float_as_uint(AsH[ac + 4][ar + mt * 16 + 8]);
                if constexpr (PASSES == 3) {
                    aL[mt][0] = __float_as_uint(AsL[ac][ar + mt * 16]);
                    aL[mt][1] = __float_as_uint(AsL[ac][ar + mt * 16 + 8]);
                    aL[mt][2] = __float_as_uint(AsL[ac + 4][ar + mt * 16]);
                    aL[mt][3] = __float_as_uint(AsL[ac + 4][ar + mt * 16 + 8]);
                }
            }
            const int bk = ks * 8 + (lane & 3);
#pragma unroll
            for (int nt = 0; nt < 4; nt++) {
                int nn = warpN * 32 + nt * 8 + (lane >> 2);
                bH[nt][0] = __float_as_uint(BsH[bk][nn]);
                bH[nt][1] = __float_as_uint(BsH[bk + 4][nn]);
                if constexpr (PASSES == 3) {
                    bL[nt][0] = __float_as_uint(BsL[bk][nn]);
                    bL[nt][1] = __float_as_uint(BsL[bk + 4][nn]);
                }
            }
#pragma unroll
            for (int mt = 0; mt < 2; mt++)
#pragma unroll
                for (int nt = 0; nt < 4; nt++) {
                    mma_tf32(acc[mt][nt], aH[mt], bH[nt]);
                    if constexpr (PASSES == 3) {
                        mma_tf32(acc[mt][nt], aH[mt], bL[nt]);
                        mma_tf32(acc[mt][nt], aL[mt], bH[nt]);
                    }
                }
        }
        __syncthreads();
    }

    // Epilogue
#pragma unroll
    for (int mt = 0; mt < 2; mt++)
#pragma unroll
        for (int nt = 0; nt < 4; nt++) {
            int n = n0 + warpN * 32 + nt * 8 + 2 * (lane & 3);
            float2 bb = *(const float2*)&bias[n];
#pragma unroll
            for (int h = 0; h < 2; h++) {
                int m = m0 + warpM * 32 + mt * 16 + (lane >> 2) + h * 8;
                if constexpr (EPI == 3) {
                    float z2m = Res[m];
                    float vx = __fadd_rn(__fadd_rn(z2m, bb.x), -2.f * acc[mt][nt][h * 2 + 0]);
                    float vy = __fadd_rn(__fadd_rn(z2m, bb.y), -2.f * acc[mt][nt][h * 2 + 1]);
                    float2 o = {vx, vy};
                    *(float2*)&C0[(size_t)m * N + n] = o;
                } else {
                    float vx = acc[mt][nt][h * 2 + 0] + bb.x;
                    float vy = acc[mt][nt][h * 2 + 1] + bb.y;
                    if constexpr (EPI >= 1) { vx = fmaxf(vx, 0.f); vy = fmaxf(vy, 0.f); }
                    if constexpr (EPI == 2) {
                        float2 r = *(const float2*)&Res[(size_t)m * N + n];
                        vx += r.x; vy += r.y;
                    }
                    float* Cp; size_t mm;
                    if (m < rowSplit) { Cp = C0; mm = (size_t)m; }
                    else              { Cp = C1; mm = (size_t)(m - rowSplit); }
                    float2 o = {vx, vy};
                    *(float2*)&Cp[mm * (size_t)N + n] = o;
                }
            }
        }
}

// ---------------------------------------------------------------------------
// Argmin + exact-fp32 refine. One block per row.
// ---------------------------------------------------------------------------
#define MARGIN 2e-4f
#define MAXCAND 256

__global__ void __launch_bounds__(256) argmin_refine_k(
    const float* __restrict__ dist, const float* __restrict__ Zall,
    const float* __restrict__ E, const float* __restrict__ z2,
    const float* __restrict__ e2, int* __restrict__ idxOut)
{
    __shared__ float smin[8];
    __shared__ int   cands[MAXCAND];
    __shared__ int   cnt;
    __shared__ float zrow[256];

    const int m = blockIdx.x;
    const int t = threadIdx.x;
    const float* drow = dist + (size_t)m * KCODES;

    zrow[t] = Zall[(size_t)m * 256 + t];
    if (t == 0) cnt = 0;

    // pass 1: block min of approx scores
    float lmin = 3.4e38f;
#pragma unroll
    for (int i = 0; i < KCODES / 256; i++)
        lmin = fminf(lmin, drow[t + i * 256]);
#pragma unroll
    for (int off = 16; off; off >>= 1)
        lmin = fminf(lmin, __shfl_xor_sync(0xFFFFFFFFu, lmin, off));
    if ((t & 31) == 0) smin[t >> 5] = lmin;
    __syncthreads();
    if (t < 8) {
        float v = smin[t];
#pragma unroll
        for (int off = 4; off; off >>= 1) v = fminf(v, __shfl_xor_sync(0xFFu, v, off));
        if (t == 0) smin[0] = v;
    }
    __syncthreads();
    const float thresh = smin[0] + MARGIN;

    // pass 2: collect candidates within margin
#pragma unroll
    for (int i = 0; i < KCODES / 256; i++) {
        int n = t + i * 256;
        if (drow[n] <= thresh) {
            int p = atomicAdd(&cnt, 1);
            if (p < MAXCAND) cands[p] = n;
        }
    }
    __syncthreads();

    // pass 3: exact fp32 rescoring of candidates (warp 0),
    // first-index tie-break via packed key
    if (t < 32) {
        int nc = cnt < MAXCAND ? cnt : MAXCAND;
        float z2m = z2[m];
        ull best = ~0ull;
        for (int i = 0; i < nc; i++) {
            int c = cands[i];
            const float* er = E + (size_t)c * 256;
            float dot = 0.f;
#pragma unroll
            for (int d = t; d < 256; d += 32) dot += zrow[d] * er[d];
#pragma unroll
            for (int off = 16; off; off >>= 1)
                dot += __shfl_xor_sync(0xFFFFFFFFu, dot, off);
            if (t == 0) {
                float s = __fadd_rn(__fadd_rn(z2m, e2[c]), -2.f * dot);
                ull key = ((ull)__float_as_uint(s) << 32) | (unsigned)c;
                if (key < best) best = key;
            }
        }
        if (t == 0) idxOut[m] = (int)(best & 0xFFFFFFFFull);
    }
}

// ---------------------------------------------------------------------------
// Small kernels
// ---------------------------------------------------------------------------
__global__ void __launch_bounds__(256) e2_k(const float* __restrict__ E,
                                            float* __restrict__ e2)
{
    int w = threadIdx.x >> 5, lane = threadIdx.x & 31;
    int code = blockIdx.x * 8 + w;
    float s = 0.f;
#pragma unroll
    for (int d = lane; d < 256; d += 32) {
        float v = E[(size_t)code * 256 + d];
        s += v * v;
    }
#pragma unroll
    for (int off = 16; off; off >>= 1) s += __shfl_xor_sync(0xFFFFFFFFu, s, off);
    if (lane == 0) e2[code] = s;
}

__global__ void __launch_bounds__(256) z2_k(const float* __restrict__ Z,
                                            float* __restrict__ z2)
{
    int w = threadIdx.x >> 5, lane = threadIdx.x & 31;
    int row = blockIdx.x * 8 + w;
    const float* zr = Z + (size_t)row * 256;
    float s = 0.f;
#pragma unroll
    for (int d = lane; d < 256; d += 32) { float v = zr[d]; s += v * v; }
#pragma unroll
    for (int off = 16; off; off >>= 1) s += __shfl_xor_sync(0xFFFFFFFFu, s, off);
    if (lane == 0) z2[row] = s;
}

__global__ void __launch_bounds__(256) vq_apply_k(
    const float* __restrict__ Zall, const float* __restrict__ E,
    const int* __restrict__ idx, float* __restrict__ zOut,
    float* __restrict__ loss)
{
    __shared__ float red[8];
    int m = blockIdx.x, d = threadIdx.x;
    int k = idx[m];
    float z = Zall[(size_t)m * 256 + d];
    float q = E[(size_t)k * 256 + d];
    zOut[(size_t)m * 256 + d] = __fadd_rn(z, __fsub_rn(q, z));
    float diff = z - q;
    float ss = diff * diff;
#pragma unroll
    for (int off = 16; off; off >>= 1) ss += __shfl_xor_sync(0xFFFFFFFFu, ss, off);
    if ((d & 31) == 0) red[d >> 5] = ss;
    __syncthreads();
    if (d < 8) {
        float v = red[d];
#pragma unroll
        for (int off = 4; off; off >>= 1) v += __shfl_xor_sync(0xFFu, v, off);
        if (d == 0) loss[m] = v + 0.25f * v;
    }
}

// ---------------------------------------------------------------------------
// Host orchestration
// ---------------------------------------------------------------------------
extern "C" void kernel_launch(void* const* d_in, const int* in_sizes, int n_in,
                              void* d_out, int out_size)
{
    const float* x_a      = (const float*)d_in[0];
    const float* x_b      = (const float*)d_in[1];
    const float* enc_a_w  = (const float*)d_in[2];
    const float* enc_a_b  = (const float*)d_in[3];
    const float* enc_a_rw = (const float*)d_in[4];
    const float* enc_a_rb = (const float*)d_in[5];
    const float* enc_b_w  = (const float*)d_in[6];
    const float* enc_b_b  = (const float*)d_in[7];
    const float* enc_b_rw = (const float*)d_in[8];
    const float* enc_b_rb = (const float*)d_in[9];
    const float* dec_a_rw = (const float*)d_in[10];
    const float* dec_a_rb = (const float*)d_in[11];
    const float* dec_a_w  = (const float*)d_in[12];
    const float* dec_a_b  = (const float*)d_in[13];
    const float* dec_b_rw = (const float*)d_in[14];
    const float* dec_b_rb = (const float*)d_in[15];
    const float* dec_b_w  = (const float*)d_in[16];
    const float* dec_b_b  = (const float*)d_in[17];
    const float* codebook = (const float*)d_in[18];

    float* out = (float*)d_out;

    float *ze, *buf0, *buf1, *z2, *e2, *dist;
    int* idx;
    cudaGetSymbolAddress((void**)&ze,   g_ze);
    cudaGetSymbolAddress((void**)&buf0, g_buf0);
    cudaGetSymbolAddress((void**)&buf1, g_buf1);
    cudaGetSymbolAddress((void**)&z2,   g_z2);
    cudaGetSymbolAddress((void**)&e2,   g_e2);
    cudaGetSymbolAddress((void**)&idx,  g_idx);
    cudaGetSymbolAddress((void**)&dist, g_dist);

    const size_t OFF_ZA = 0;
    const size_t OFF_LA = 2ull * B_ * D_;
    const size_t OFF_RA = OFF_LA + 2ull * B_;
    const size_t OFF_RB = OFF_RA + (size_t)B_ * 4096;
    const size_t OFF_XA = OFF_RB + (size_t)B_ * 2048;
    const size_t OFF_XB = OFF_XA + (size_t)B_ * 4096;

    const dim3 blk(256);
    const int BIG = 1 << 30;
    float* zeB = ze + (size_t)B_ * D_;

    e2_k<<<KCODES / 8, blk>>>(codebook, e2);

    // --- Encoders: fp32 SIMT (round-1 numerics, zero-flip proven) ---
    const dim3 gEnc(4, 128);
    gemm_k<1><<<gEnc, blk>>>(x_a, enc_a_w, enc_a_b, nullptr, buf0, B_, 256, 4096);
    gemm_k<2><<<gEnc, blk>>>(buf0, enc_a_rw,         enc_a_rb,       buf0, buf1, B_, 256, 256);
    gemm_k<2><<<gEnc, blk>>>(buf1, enc_a_rw + 65536, enc_a_rb + 256, buf1, ze,   B_, 256, 256);

    gemm_k<1><<<gEnc, blk>>>(x_b, enc_b_w, enc_b_b, nullptr, buf0, B_, 256, 2048);
    gemm_k<2><<<gEnc, blk>>>(buf0, enc_b_rw,         enc_b_rb,       buf0, buf1, B_, 256, 256);
    gemm_k<2><<<gEnc, blk>>>(buf1, enc_b_rw + 65536, enc_b_rb + 256, buf1, zeB,  B_, 256, 256);

    // --- VQ: tf32 approx scores -> exact fp32 candidate refine ---
    z2_k<<<2 * B_ / 8, blk>>>(ze, z2);
    gemm_tc<1, 3><<<dim3(KCODES / 64, 2 * B_ / 128), blk>>>(
        ze, codebook, e2, z2, dist, dist, BIG, 2 * B_, KCODES, 256);
    argmin_refine_k<<<2 * B_, blk>>>(dist, ze, codebook, z2, e2, idx);
    vq_apply_k<<<2 * B_, blk>>>(ze, codebook, idx, out + OFF_ZA, out + OFF_LA);

    // --- Decoders: batched over [z_a; z_b] (M=16384) ---
    gemm_tc<3, 2><<<dim3(4, 128), blk>>>(out, dec_a_rw, dec_a_rb, out,
                                         buf0, buf0, BIG, 2 * B_, 256, 256);
    gemm_tc<3, 2><<<dim3(4, 128), blk>>>(buf0, dec_a_rw + 65536, dec_a_rb + 256, buf0,
                                         buf1, buf1, BIG, 2 * B_, 256, 256);
    gemm_tc<1, 0><<<dim3(64, 128), blk>>>(buf1, dec_a_w, dec_a_b, nullptr,
                                          out + OFF_RA, out + OFF_XA, B_,
                                          2 * B_, 4096, 256);

    gemm_tc<3, 2><<<dim3(4, 128), blk>>>(out, dec_b_rw, dec_b_rb, out,
                                         buf0, buf0, BIG, 2 * B_, 256, 256);
    gemm_tc<3, 2><<<dim3(4, 128), blk>>>(buf0, dec_b_rw + 65536, dec_b_rb + 256, buf0,
                                         buf1, buf1, BIG, 2 * B_, 256, 256);
    gemm_tc<1, 0><<<dim3(32, 128), blk>>>(buf1, dec_b_w, dec_b_b, nullptr,
                                          out + OFF_XB, out + OFF_RB, B_,
                                          2 * B_, 2048, 256);
}

// round 8
// speedup vs baseline: 1.8249x; 1.0644x over previous
#include <cuda_runtime.h>
#include <stdint.h>

#define B_ 8192
#define D_ 256
#define KCODES 8192
#define NCHUNK (KCODES / 32)     // 256 chunk keys per row
#define MARGIN 2e-4f

typedef unsigned long long ull;

// Scratch (device globals; no allocation allowed)
__device__ float g_ze[2 * B_ * D_];       // [zeA; zeB]
__device__ float g_buf0[2 * B_ * D_];
__device__ float g_buf1[2 * B_ * D_];
__device__ float g_z2[2 * B_];
__device__ float g_e2[KCODES];
__device__ int   g_idx[2 * B_];
__device__ ull   g_chunk[(size_t)2 * B_ * NCHUNK];   // 32 MB chunk-min keys

// ---------------------------------------------------------------------------
// fp32 SIMT GEMM, re-tiled for FMA intensity but BIT-IDENTICAL accumulation:
// per output (m,n): acc = fma(a_k, b_k, acc) for k ascending — same chain as
// the round-1/7 kernel, so ze is bit-identical and argmin indices are frozen.
// Tile 128x64, BK=16, 256 threads, 8x4 micro-tile.
// EPI 1: relu(.+bias); 2: Res + relu(.+bias)
// ---------------------------------------------------------------------------
template <int EPI>
__global__ void __launch_bounds__(256) gemm2_k(
    const float* __restrict__ A, const float* __restrict__ Bm,
    const float* __restrict__ bias, const float* __restrict__ Res,
    float* __restrict__ C, int M, int N, int K)
{
    __shared__ float As[16][132];   // [k][m], padded
    __shared__ float Bs[16][64];    // [k][n]

    const int t  = threadIdx.x;
    const int ty = t >> 4;          // 0..15 -> 8 rows each
    const int tx = t & 15;          // 0..15 -> 4 cols each
    const int m0 = blockIdx.y * 128;
    const int n0 = blockIdx.x * 64;

    const int brow = t >> 4, bseg = t & 15;

    float acc[8][4];
#pragma unroll
    for (int i = 0; i < 8; i++)
#pragma unroll
        for (int j = 0; j < 4; j++) acc[i][j] = 0.f;

    for (int kb = 0; kb < K; kb += 16) {
        // stage A tile 128x16: 512 float4 / 256 threads = 2 each, transposed
#pragma unroll
        for (int i = 0; i < 2; i++) {
            int f = t + i * 256;
            int row = f >> 2, seg = f & 3;
            float4 v = *(const float4*)&A[(size_t)(m0 + row) * K + kb + seg * 4];
            As[seg * 4 + 0][row] = v.x;
            As[seg * 4 + 1][row] = v.y;
            As[seg * 4 + 2][row] = v.z;
            As[seg * 4 + 3][row] = v.w;
        }
        // stage B tile 16x64: 256 float4, 1 each
        {
            float4 v = *(const float4*)&Bm[(size_t)(kb + brow) * N + n0 + bseg * 4];
            *(float4*)&Bs[brow][bseg * 4] = v;
        }
        __syncthreads();
#pragma unroll
        for (int kk = 0; kk < 16; kk++) {
            float4 a0 = *(const float4*)&As[kk][ty * 8];
            float4 a1 = *(const float4*)&As[kk][ty * 8 + 4];
            float4 b4 = *(const float4*)&Bs[kk][tx * 4];
            float a[8] = {a0.x, a0.y, a0.z, a0.w, a1.x, a1.y, a1.z, a1.w};
            float b[4] = {b4.x, b4.y, b4.z, b4.w};
#pragma unroll
            for (int i = 0; i < 8; i++)
#pragma unroll
                for (int j = 0; j < 4; j++) acc[i][j] += a[i] * b[j];
        }
        __syncthreads();
    }

    float4 bb = *(const float4*)&bias[n0 + tx * 4];
    float bcol[4] = {bb.x, bb.y, bb.z, bb.w};
#pragma unroll
    for (int i = 0; i < 8; i++) {
        int m = m0 + ty * 8 + i;
        float v[4];
#pragma unroll
        for (int j = 0; j < 4; j++) {
            v[j] = acc[i][j] + bcol[j];
            if (EPI >= 1) v[j] = fmaxf(v[j], 0.f);
        }
        if (EPI == 2) {
            float4 r = *(const float4*)&Res[(size_t)m * N + n0 + tx * 4];
            v[0] += r.x; v[1] += r.y; v[2] += r.z; v[3] += r.w;
        }
        float4 o = {v[0], v[1], v[2], v[3]};
        *(float4*)&C[(size_t)m * N + n0 + tx * 4] = o;
    }
}

// ---------------------------------------------------------------------------
// tf32 helpers
// ---------------------------------------------------------------------------
__device__ __forceinline__ uint32_t f2tf32(float x) {
    uint32_t r;
    asm("cvt.rna.tf32.f32 %0, %1;" : "=r"(r) : "f"(x));
    return r;
}

__device__ __forceinline__ void mma_tf32(float* d, const uint32_t* a, const uint32_t* b) {
    asm volatile(
        "mma.sync.aligned.m16n8k8.row.col.f32.tf32.tf32.f32 "
        "{%0,%1,%2,%3}, {%4,%5,%6,%7}, {%8,%9}, {%0,%1,%2,%3};\n"
        : "+f"(d[0]), "+f"(d[1]), "+f"(d[2]), "+f"(d[3])
        : "r"(a[0]), "r"(a[1]), "r"(a[2]), "r"(a[3]), "r"(b[0]), "r"(b[1]));
}

// ---------------------------------------------------------------------------
// Tensor-core GEMM (tf32). PASSES=3: fp32-class; PASSES=1: plain tf32.
// EPI 0: bias; 2: Res + relu(.+bias)
// EPI 3: VQ scores s = fl(fl(z2[m]+e2[n]) - 2*acc), reduced to per-(row,
//        32-code-chunk) min keys written to C0 (cast to ull*). bias=e2, Res=z2.
//        Bw is the codebook [N rows x K dims] ROW-MAJOR, gathered transposed.
// Tile 128x64, BK=16, 8 warps. Rows >= rowSplit go to C1 at (m - rowSplit).
// ---------------------------------------------------------------------------
template <int PASSES, int EPI>
__global__ void __launch_bounds__(256) gemm_tc(
    const float* __restrict__ A, const float* __restrict__ Bw,
    const float* __restrict__ bias, const float* __restrict__ Res,
    float* __restrict__ C0, float* __restrict__ C1, int rowSplit,
    int M, int N, int K)
{
    __shared__ float AsH[16][132];
    __shared__ float BsH[16][68];
    __shared__ float AsL[PASSES == 3 ? 16 : 1][132];
    __shared__ float BsL[PASSES == 3 ? 16 : 1][68];

    const int t = threadIdx.x;
    const int lane = t & 31;
    const int warp = t >> 5;
    const int warpM = warp & 3;
    const int warpN = warp >> 2;
    const int m0 = blockIdx.y * 128;
    const int n0 = blockIdx.x * 64;

    float acc[2][4][4];
#pragma unroll
    for (int mt = 0; mt < 2; mt++)
#pragma unroll
        for (int nt = 0; nt < 4; nt++)
#pragma unroll
            for (int c = 0; c < 4; c++) acc[mt][nt][c] = 0.f;

    const int aRow = t >> 2, aSeg = t & 3;
    const int bRow = t >> 4, bSeg = t & 15;
    const int eCode = t >> 2, eSeg = t & 3;   // EPI==3 transposed B loader

    for (int kb = 0; kb < K; kb += 16) {
#pragma unroll
        for (int h = 0; h < 2; h++) {
            int row = aRow + h * 64;
            float4 v = *(const float4*)&A[(size_t)(m0 + row) * K + kb + aSeg * 4];
            float x[4] = {v.x, v.y, v.z, v.w};
#pragma unroll
            for (int j = 0; j < 4; j++) {
                uint32_t hb = f2tf32(x[j]);
                AsH[aSeg * 4 + j][row] = __uint_as_float(hb);
                if constexpr (PASSES == 3) {
                    float lo = x[j] - __uint_as_float(hb);
                    AsL[aSeg * 4 + j][row] = __uint_as_float(f2tf32(lo));
                }
            }
        }
        if constexpr (EPI == 3) {
            float4 v = *(const float4*)&Bw[(size_t)(n0 + eCode) * K + kb + eSeg * 4];
            float x[4] = {v.x, v.y, v.z, v.w};
#pragma unroll
            for (int j = 0; j < 4; j++)
                BsH[eSeg * 4 + j][eCode] = __uint_as_float(f2tf32(x[j]));
        } else {
            float4 v = *(const float4*)&Bw[(size_t)(kb + bRow) * N + n0 + bSeg * 4];
            float x[4] = {v.x, v.y, v.z, v.w};
#pragma unroll
            for (int j = 0; j < 4; j++) {
                uint32_t hb = f2tf32(x[j]);
                BsH[bRow][bSeg * 4 + j] = __uint_as_float(hb);
                if constexpr (PASSES == 3) {
                    float lo = x[j] - __uint_as_float(hb);
                    BsL[bRow][bSeg * 4 + j] = __uint_as_float(f2tf32(lo));
                }
            }
        }
        __syncthreads();

#pragma unroll
        for (int ks = 0; ks < 2; ks++) {
            uint32_t aH[2][4], aL[2][4], bH[4][2], bL[4][2];
            const int ar = warpM * 32 + (lane >> 2);
            const int ac = ks * 8 + (lane & 3);
#pragma unroll
            for (int mt = 0; mt < 2; mt++) {
                aH[mt][0] = __float_as_uint(AsH[ac][ar + mt * 16]);
                aH[mt][1] = __float_as_uint(AsH[ac][ar + mt * 16 + 8]);
                aH[mt][2] = __float_as_uint(AsH[ac + 4][ar + mt * 16]);
                aH[mt][3] = __float_as_uint(AsH[ac + 4][ar + mt * 16 + 8]);
                if constexpr (PASSES == 3) {
                    aL[mt][0] = __float_as_uint(AsL[ac][ar + mt * 16]);
                    aL[mt][1] = __float_as_uint(AsL[ac][ar + mt * 16 + 8]);
                    aL[mt][2] = __float_as_uint(AsL[ac + 4][ar + mt * 16]);
                    aL[mt][3] = __float_as_uint(AsL[ac + 4][ar + mt * 16 + 8]);
                }
            }
            const int bk = ks * 8 + (lane & 3);
#pragma unroll
            for (int nt = 0; nt < 4; nt++) {
                int nn = warpN * 32 + nt * 8 + (lane >> 2);
                bH[nt][0] = __float_as_uint(BsH[bk][nn]);
                bH[nt][1] = __float_as_uint(BsH[bk + 4][nn]);
                if constexpr (PASSES == 3) {
                    bL[nt][0] = __float_as_uint(BsL[bk][nn]);
                    bL[nt][1] = __float_as_uint(BsL[bk + 4][nn]);
                }
            }
#pragma unroll
            for (int mt = 0; mt < 2; mt++)
#pragma unroll
                for (int nt = 0; nt < 4; nt++) {
                    mma_tf32(acc[mt][nt], aH[mt], bH[nt]);
                    if constexpr (PASSES == 3) {
                        mma_tf32(acc[mt][nt], aH[mt], bL[nt]);
                        mma_tf32(acc[mt][nt], aL[mt], bH[nt]);
                    }
                }
        }
        __syncthreads();
    }

    // Epilogue
    if constexpr (EPI == 3) {
        // per-(row, 32-code chunk) min keys
        ull* chunkOut = (ull*)C0;
        ull best[2][2] = {{~0ull, ~0ull}, {~0ull, ~0ull}};
#pragma unroll
        for (int mt = 0; mt < 2; mt++)
#pragma unroll
            for (int h = 0; h < 2; h++) {
                int m = m0 + warpM * 32 + mt * 16 + (lane >> 2) + h * 8;
                float z2m = Res[m];
#pragma unroll
                for (int nt = 0; nt < 4; nt++) {
                    int n = n0 + warpN * 32 + nt * 8 + 2 * (lane & 3);
                    float2 e2v = *(const float2*)&bias[n];
                    float sx = __fadd_rn(__fadd_rn(z2m, e2v.x), -2.f * acc[mt][nt][h * 2 + 0]);
                    float sy = __fadd_rn(__fadd_rn(z2m, e2v.y), -2.f * acc[mt][nt][h * 2 + 1]);
                    ull kx = ((ull)__float_as_uint(sx) << 32) | (unsigned)n;
                    ull ky = ((ull)__float_as_uint(sy) << 32) | (unsigned)(n + 1);
                    if (kx < best[mt][h]) best[mt][h] = kx;
                    if (ky < best[mt][h]) best[mt][h] = ky;
                }
            }
        const int chunk = blockIdx.x * 2 + warpN;
#pragma unroll
        for (int mt = 0; mt < 2; mt++)
#pragma unroll
            for (int h = 0; h < 2; h++) {
                ull k = best[mt][h];
                ull o = __shfl_xor_sync(0xFFFFFFFFu, k, 1); if (o < k) k = o;
                o = __shfl_xor_sync(0xFFFFFFFFu, k, 2); if (o < k) k = o;
                if ((lane & 3) == 0) {
                    int m = m0 + warpM * 32 + mt * 16 + (lane >> 2) + h * 8;
                    chunkOut[(size_t)m * NCHUNK + chunk] = k;
                }
            }
    } else {
#pragma unroll
        for (int mt = 0; mt < 2; mt++)
#pragma unroll
            for (int nt = 0; nt < 4; nt++) {
                int n = n0 + warpN * 32 + nt * 8 + 2 * (lane & 3);
                float2 bb = *(const float2*)&bias[n];
#pragma unroll
                for (int h = 0; h < 2; h++) {
                    int m = m0 + warpM * 32 + mt * 16 + (lane >> 2) + h * 8;
                    float vx = acc[mt][nt][h * 2 + 0] + bb.x;
                    float vy = acc[mt][nt][h * 2 + 1] + bb.y;
                    if constexpr (EPI >= 1) { vx = fmaxf(vx, 0.f); vy = fmaxf(vy, 0.f); }
                    if constexpr (EPI == 2) {
                        float2 r = *(const float2*)&Res[(size_t)m * N + n];
                        vx += r.x; vy += r.y;
                    }
                    float* Cp; size_t mm;
                    if (m < rowSplit) { Cp = C0; mm = (size_t)m; }
                    else              { Cp = C1; mm = (size_t)(m - rowSplit); }
                    float2 o = {vx, vy};
                    *(float2*)&Cp[mm * (size_t)N + n] = o;
                }
            }
    }
}

// ---------------------------------------------------------------------------
// Refine from chunk mins: block per row. Find approx min over 256 chunk keys,
// select chunks within MARGIN, rescore all 32 codes in each selected chunk
// with EXACT fp32 (same reduction order + first-index tie-break as R7).
// ---------------------------------------------------------------------------
#define MAXCHUNK 64

__global__ void __launch_bounds__(256) refine2_k(
    const ull* __restrict__ chunkmin, const float* __restrict__ Zall,
    const float* __restrict__ E, const float* __restrict__ z2,
    const float* __restrict__ e2, int* __restrict__ idxOut)
{
    __shared__ float zrow[256];
    __shared__ ull   wmin[8];
    __shared__ int   chunks[MAXCHUNK];
    __shared__ int   cnt;
    __shared__ float sthresh;
    __shared__ ull   wbest[8];

    const int m = blockIdx.x;
    const int t = threadIdx.x;
    const int warp = t >> 5, lane = t & 31;

    zrow[t] = Zall[(size_t)m * 256 + t];
    if (t == 0) cnt = 0;
    const ull ck = chunkmin[(size_t)m * NCHUNK + t];

    // block min of chunk keys
    ull k = ck;
#pragma unroll
    for (int off = 16; off; off >>= 1) {
        ull o = __shfl_xor_sync(0xFFFFFFFFu, k, off);
        if (o < k) k = o;
    }
    if (lane == 0) wmin[warp] = k;
    __syncthreads();
    if (t < 8) {
        ull v = wmin[t];
#pragma unroll
        for (int off = 4; off; off >>= 1) {
            ull o = __shfl_xor_sync(0xFFu, v, off);
            if (o < v) v = o;
        }
        if (t == 0) sthresh = __uint_as_float((unsigned)(v >> 32)) + MARGIN;
    }
    __syncthreads();

    // collect chunks within margin
    if (__uint_as_float((unsigned)(ck >> 32)) <= sthresh) {
        int p = atomicAdd(&cnt, 1);
        if (p < MAXCHUNK) chunks[p] = t;
    }
    __syncthreads();

    // exact rescoring: warp-per-code over nc*32 codes
    const int nc = cnt < MAXCHUNK ? cnt : MAXCHUNK;
    const float z2m = z2[m];
    ull best = ~0ull;
    for (int g = warp; g < nc * 32; g += 8) {
        int c = chunks[g >> 5] * 32 + (g & 31);
        const float* er = E + (size_t)c * 256;
        float dot = 0.f;
#pragma unroll
        for (int d = lane; d < 256; d += 32) dot += zrow[d] * er[d];
#pragma unroll
        for (int off = 16; off; off >>= 1)
            dot += __shfl_xor_sync(0xFFFFFFFFu, dot, off);
        if (lane == 0) {
            float s = __fadd_rn(__fadd_rn(z2m, e2[c]), -2.f * dot);
            ull key = ((ull)__float_as_uint(s) << 32) | (unsigned)c;
            if (key < best) best = key;
        }
    }
    if (lane == 0) wbest[warp] = best;
    __syncthreads();
    if (t < 8) {
        ull v = wbest[t];
#pragma unroll
        for (int off = 4; off; off >>= 1) {
            ull o = __shfl_xor_sync(0xFFu, v, off);
            if (o < v) v = o;
        }
        if (t == 0) idxOut[m] = (int)(v & 0xFFFFFFFFull);
    }
}

// ---------------------------------------------------------------------------
// Small kernels
// ---------------------------------------------------------------------------
__global__ void __launch_bounds__(256) e2_k(const float* __restrict__ E,
                                            float* __restrict__ e2)
{
    int w = threadIdx.x >> 5, lane = threadIdx.x & 31;
    int code = blockIdx.x * 8 + w;
    float s = 0.f;
#pragma unroll
    for (int d = lane; d < 256; d += 32) {
        float v = E[(size_t)code * 256 + d];
        s += v * v;
    }
#pragma unroll
    for (int off = 16; off; off >>= 1) s += __shfl_xor_sync(0xFFFFFFFFu, s, off);
    if (lane == 0) e2[code] = s;
}

__global__ void __launch_bounds__(256) z2_k(const float* __restrict__ Z,
                                            float* __restrict__ z2)
{
    int w = threadIdx.x >> 5, lane = threadIdx.x & 31;
    int row = blockIdx.x * 8 + w;
    const float* zr = Z + (size_t)row * 256;
    float s = 0.f;
#pragma unroll
    for (int d = lane; d < 256; d += 32) { float v = zr[d]; s += v * v; }
#pragma unroll
    for (int off = 16; off; off >>= 1) s += __shfl_xor_sync(0xFFFFFFFFu, s, off);
    if (lane == 0) z2[row] = s;
}

__global__ void __launch_bounds__(256) vq_apply_k(
    const float* __restrict__ Zall, const float* __restrict__ E,
    const int* __restrict__ idx, float* __restrict__ zOut,
    float* __restrict__ loss)
{
    __shared__ float red[8];
    int m = blockIdx.x, d = threadIdx.x;
    int k = idx[m];
    float z = Zall[(size_t)m * 256 + d];
    float q = E[(size_t)k * 256 + d];
    zOut[(size_t)m * 256 + d] = __fadd_rn(z, __fsub_rn(q, z));
    float diff = z - q;
    float ss = diff * diff;
#pragma unroll
    for (int off = 16; off; off >>= 1) ss += __shfl_xor_sync(0xFFFFFFFFu, ss, off);
    if ((d & 31) == 0) red[d >> 5] = ss;
    __syncthreads();
    if (d < 8) {
        float v = red[d];
#pragma unroll
        for (int off = 4; off; off >>= 1) v += __shfl_xor_sync(0xFFu, v, off);
        if (d == 0) loss[m] = v + 0.25f * v;
    }
}

// ---------------------------------------------------------------------------
// Host orchestration
// ---------------------------------------------------------------------------
extern "C" void kernel_launch(void* const* d_in, const int* in_sizes, int n_in,
                              void* d_out, int out_size)
{
    const float* x_a      = (const float*)d_in[0];
    const float* x_b      = (const float*)d_in[1];
    const float* enc_a_w  = (const float*)d_in[2];
    const float* enc_a_b  = (const float*)d_in[3];
    const float* enc_a_rw = (const float*)d_in[4];
    const float* enc_a_rb = (const float*)d_in[5];
    const float* enc_b_w  = (const float*)d_in[6];
    const float* enc_b_b  = (const float*)d_in[7];
    const float* enc_b_rw = (const float*)d_in[8];
    const float* enc_b_rb = (const float*)d_in[9];
    const float* dec_a_rw = (const float*)d_in[10];
    const float* dec_a_rb = (const float*)d_in[11];
    const float* dec_a_w  = (const float*)d_in[12];
    const float* dec_a_b  = (const float*)d_in[13];
    const float* dec_b_rw = (const float*)d_in[14];
    const float* dec_b_rb = (const float*)d_in[15];
    const float* dec_b_w  = (const float*)d_in[16];
    const float* dec_b_b  = (const float*)d_in[17];
    const float* codebook = (const float*)d_in[18];

    float* out = (float*)d_out;

    float *ze, *buf0, *buf1, *z2, *e2;
    int* idx;
    ull* chunk;
    cudaGetSymbolAddress((void**)&ze,    g_ze);
    cudaGetSymbolAddress((void**)&buf0,  g_buf0);
    cudaGetSymbolAddress((void**)&buf1,  g_buf1);
    cudaGetSymbolAddress((void**)&z2,    g_z2);
    cudaGetSymbolAddress((void**)&e2,    g_e2);
    cudaGetSymbolAddress((void**)&idx,   g_idx);
    cudaGetSymbolAddress((void**)&chunk, g_chunk);

    const size_t OFF_ZA = 0;
    const size_t OFF_LA = 2ull * B_ * D_;
    const size_t OFF_RA = OFF_LA + 2ull * B_;
    const size_t OFF_RB = OFF_RA + (size_t)B_ * 4096;
    const size_t OFF_XA = OFF_RB + (size_t)B_ * 2048;
    const size_t OFF_XB = OFF_XA + (size_t)B_ * 4096;

    const dim3 blk(256);
    const int BIG = 1 << 30;
    float* zeB = ze + (size_t)B_ * D_;

    e2_k<<<KCODES / 8, blk>>>(codebook, e2);

    // --- Encoders: fp32, bit-identical accumulation, re-tiled for speed ---
    const dim3 gEnc(4, 64);   // N/64 x M/128
    gemm2_k<1><<<gEnc, blk>>>(x_a, enc_a_w, enc_a_b, nullptr, buf0, B_, 256, 4096);
    gemm2_k<2><<<gEnc, blk>>>(buf0, enc_a_rw,         enc_a_rb,       buf0, buf1, B_, 256, 256);
    gemm2_k<2><<<gEnc, blk>>>(buf1, enc_a_rw + 65536, enc_a_rb + 256, buf1, ze,   B_, 256, 256);

    gemm2_k<1><<<gEnc, blk>>>(x_b, enc_b_w, enc_b_b, nullptr, buf0, B_, 256, 2048);
    gemm2_k<2><<<gEnc, blk>>>(buf0, enc_b_rw,         enc_b_rb,       buf0, buf1, B_, 256, 256);
    gemm2_k<2><<<gEnc, blk>>>(buf1, enc_b_rw + 65536, enc_b_rb + 256, buf1, zeB,  B_, 256, 256);

    // --- VQ: tf32 approx scores -> chunk-min keys -> exact fp32 refine ---
    z2_k<<<2 * B_ / 8, blk>>>(ze, z2);
    gemm_tc<1, 3><<<dim3(KCODES / 64, 2 * B_ / 128), blk>>>(
        ze, codebook, e2, z2, (float*)chunk, nullptr, BIG, 2 * B_, KCODES, 256);
    refine2_k<<<2 * B_, blk>>>(chunk, ze, codebook, z2, e2, idx);
    vq_apply_k<<<2 * B_, blk>>>(ze, codebook, idx, out + OFF_ZA, out + OFF_LA);

    // --- Decoders: batched over [z_a; z_b] (M=16384), unchanged numerics ---
    gemm_tc<3, 2><<<dim3(4, 128), blk>>>(out, dec_a_rw, dec_a_rb, out,
                                         buf0, buf0, BIG, 2 * B_, 256, 256);
    gemm_tc<3, 2><<<dim3(4, 128), blk>>>(buf0, dec_a_rw + 65536, dec_a_rb + 256, buf0,
                                         buf1, buf1, BIG, 2 * B_, 256, 256);
    gemm_tc<1, 0><<<dim3(64, 128), blk>>>(buf1, dec_a_w, dec_a_b, nullptr,
                                          out + OFF_RA, out + OFF_XA, B_,
                                          2 * B_, 4096, 256);

    gemm_tc<3, 2><<<dim3(4, 128), blk>>>(out, dec_b_rw, dec_b_rb, out,
                                         buf0, buf0, BIG, 2 * B_, 256, 256);
    gemm_tc<3, 2><<<dim3(4, 128), blk>>>(buf0, dec_b_rw + 65536, dec_b_rb + 256, buf0,
                                         buf1, buf1, BIG, 2 * B_, 256, 256);
    gemm_tc<1, 0><<<dim3(32, 128), blk>>>(buf1, dec_b_w, dec_b_b, nullptr,
                                          out + OFF_XB, out + OFF_RB, B_,
                                          2 * B_, 2048, 256);
}

// round 9
// speedup vs baseline: 1.9512x; 1.0692x over previous
#include <cuda_runtime.h>
#include <stdint.h>

#define B_ 8192
#define D_ 256
#define KCODES 8192
#define NCHUNK (KCODES / 32)     // 256 chunk keys per row
#define MARGIN 2e-4f

typedef unsigned long long ull;

// Scratch (device globals; no allocation allowed)
__device__ float g_ze[2 * B_ * D_];       // [zeA; zeB]
__device__ float g_buf0[2 * B_ * D_];
__device__ float g_buf1[2 * B_ * D_];
__device__ float g_z2[2 * B_];
__device__ float g_e2[KCODES];
__device__ int   g_idx[2 * B_];
__device__ ull   g_chunk[(size_t)2 * B_ * NCHUNK];   // 32 MB chunk-min keys

// ---------------------------------------------------------------------------
// fp32 SIMT GEMM, 128x128 tile, 8x8 micro-tile, double-buffered smem.
// BIT-IDENTICAL accumulation vs rounds 1/7/8: per output (m,n),
// acc = fma(a_k, b_k, acc), k strictly ascending, same epilogue exprs.
// EPI 1: relu(.+bias); 2: Res + relu(.+bias)
// ---------------------------------------------------------------------------
template <int EPI>
__global__ void __launch_bounds__(256) gemm3_k(
    const float* __restrict__ A, const float* __restrict__ Bm,
    const float* __restrict__ bias, const float* __restrict__ Res,
    float* __restrict__ C, int M, int N, int K)
{
    __shared__ float As[2][16][132];   // [k][m], padded
    __shared__ float Bs[2][16][128];   // [k][n]

    const int t  = threadIdx.x;
    const int ty = t >> 4;             // 0..15 -> 8 rows
    const int tx = t & 15;             // 0..15 -> 8 cols
    const int m0 = blockIdx.y * 128;
    const int n0 = blockIdx.x * 128;

    // loader mappings: A tile 128x16 = 512 float4 (2/thread), transposed store
    //                  B tile 16x128 = 512 float4 (2/thread)
    const int aRow0 = t >> 1;              // rows 0..127 (t + 0*256 -> f>>2 with f=t.. wait)
    // f0 = t, f1 = t + 256;  row = f >> 2, seg = f & 3
    const int ar0 = t >> 2,        as0 = t & 3;
    const int ar1 = (t + 256) >> 2, as1 = (t + 256) & 3;
    const int br0 = t >> 5,        bs0 = t & 31;
    const int br1 = (t + 256) >> 5, bs1 = (t + 256) & 31;
    (void)aRow0;

    float acc[8][8];
#pragma unroll
    for (int i = 0; i < 8; i++)
#pragma unroll
        for (int j = 0; j < 8; j++) acc[i][j] = 0.f;

    // preload tile kb=0 into buffer 0
    {
        float4 a0 = *(const float4*)&A[(size_t)(m0 + ar0) * K + as0 * 4];
        float4 a1 = *(const float4*)&A[(size_t)(m0 + ar1) * K + as1 * 4];
        float4 b0 = *(const float4*)&Bm[(size_t)br0 * N + n0 + bs0 * 4];
        float4 b1 = *(const float4*)&Bm[(size_t)br1 * N + n0 + bs1 * 4];
        As[0][as0 * 4 + 0][ar0] = a0.x; As[0][as0 * 4 + 1][ar0] = a0.y;
        As[0][as0 * 4 + 2][ar0] = a0.z; As[0][as0 * 4 + 3][ar0] = a0.w;
        As[0][as1 * 4 + 0][ar1] = a1.x; As[0][as1 * 4 + 1][ar1] = a1.y;
        As[0][as1 * 4 + 2][ar1] = a1.z; As[0][as1 * 4 + 3][ar1] = a1.w;
        *(float4*)&Bs[0][br0][bs0 * 4] = b0;
        *(float4*)&Bs[0][br1][bs1 * 4] = b1;
    }
    __syncthreads();

    int p = 0;
    for (int kb = 16; kb < K; kb += 16) {
        // prefetch next tile into registers
        float4 a0 = *(const float4*)&A[(size_t)(m0 + ar0) * K + kb + as0 * 4];
        float4 a1 = *(const float4*)&A[(size_t)(m0 + ar1) * K + kb + as1 * 4];
        float4 b0 = *(const float4*)&Bm[(size_t)(kb + br0) * N + n0 + bs0 * 4];
        float4 b1 = *(const float4*)&Bm[(size_t)(kb + br1) * N + n0 + bs1 * 4];

        // compute on buffer p
#pragma unroll
        for (int kk = 0; kk < 16; kk++) {
            float4 x0 = *(const float4*)&As[p][kk][ty * 8];
            float4 x1 = *(const float4*)&As[p][kk][ty * 8 + 4];
            float4 y0 = *(const float4*)&Bs[p][kk][tx * 8];
            float4 y1 = *(const float4*)&Bs[p][kk][tx * 8 + 4];
            float a[8] = {x0.x, x0.y, x0.z, x0.w, x1.x, x1.y, x1.z, x1.w};
            float b[8] = {y0.x, y0.y, y0.z, y0.w, y1.x, y1.y, y1.z, y1.w};
#pragma unroll
            for (int i = 0; i < 8; i++)
#pragma unroll
                for (int j = 0; j < 8; j++) acc[i][j] += a[i] * b[j];
        }

        // store prefetched into buffer p^1
        int q = p ^ 1;
        As[q][as0 * 4 + 0][ar0] = a0.x; As[q][as0 * 4 + 1][ar0] = a0.y;
        As[q][as0 * 4 + 2][ar0] = a0.z; As[q][as0 * 4 + 3][ar0] = a0.w;
        As[q][as1 * 4 + 0][ar1] = a1.x; As[q][as1 * 4 + 1][ar1] = a1.y;
        As[q][as1 * 4 + 2][ar1] = a1.z; As[q][as1 * 4 + 3][ar1] = a1.w;
        *(float4*)&Bs[q][br0][bs0 * 4] = b0;
        *(float4*)&Bs[q][br1][bs1 * 4] = b1;
        __syncthreads();
        p = q;
    }

    // final tile
#pragma unroll
    for (int kk = 0; kk < 16; kk++) {
        float4 x0 = *(const float4*)&As[p][kk][ty * 8];
        float4 x1 = *(const float4*)&As[p][kk][ty * 8 + 4];
        float4 y0 = *(const float4*)&Bs[p][kk][tx * 8];
        float4 y1 = *(const float4*)&Bs[p][kk][tx * 8 + 4];
        float a[8] = {x0.x, x0.y, x0.z, x0.w, x1.x, x1.y, x1.z, x1.w};
        float b[8] = {y0.x, y0.y, y0.z, y0.w, y1.x, y1.y, y1.z, y1.w};
#pragma unroll
        for (int i = 0; i < 8; i++)
#pragma unroll
            for (int j = 0; j < 8; j++) acc[i][j] += a[i] * b[j];
    }

    // epilogue (same expressions as rounds 1/7/8)
    float4 bb0 = *(const float4*)&bias[n0 + tx * 8];
    float4 bb1 = *(const float4*)&bias[n0 + tx * 8 + 4];
    float bcol[8] = {bb0.x, bb0.y, bb0.z, bb0.w, bb1.x, bb1.y, bb1.z, bb1.w};
#pragma unroll
    for (int i = 0; i < 8; i++) {
        int m = m0 + ty * 8 + i;
        float v[8];
#pragma unroll
        for (int j = 0; j < 8; j++) {
            v[j] = acc[i][j] + bcol[j];
            if (EPI >= 1) v[j] = fmaxf(v[j], 0.f);
        }
        if (EPI == 2) {
            float4 r0 = *(const float4*)&Res[(size_t)m * N + n0 + tx * 8];
            float4 r1 = *(const float4*)&Res[(size_t)m * N + n0 + tx * 8 + 4];
            v[0] += r0.x; v[1] += r0.y; v[2] += r0.z; v[3] += r0.w;
            v[4] += r1.x; v[5] += r1.y; v[6] += r1.z; v[7] += r1.w;
        }
        float4 o0 = {v[0], v[1], v[2], v[3]};
        float4 o1 = {v[4], v[5], v[6], v[7]};
        *(float4*)&C[(size_t)m * N + n0 + tx * 8] = o0;
        *(float4*)&C[(size_t)m * N + n0 + tx * 8 + 4] = o1;
    }
}

// ---------------------------------------------------------------------------
// tf32 helpers
// ---------------------------------------------------------------------------
__device__ __forceinline__ uint32_t f2tf32(float x) {
    uint32_t r;
    asm("cvt.rna.tf32.f32 %0, %1;" : "=r"(r) : "f"(x));
    return r;
}

__device__ __forceinline__ void mma_tf32(float* d, const uint32_t* a, const uint32_t* b) {
    asm volatile(
        "mma.sync.aligned.m16n8k8.row.col.f32.tf32.tf32.f32 "
        "{%0,%1,%2,%3}, {%4,%5,%6,%7}, {%8,%9}, {%0,%1,%2,%3};\n"
        : "+f"(d[0]), "+f"(d[1]), "+f"(d[2]), "+f"(d[3])
        : "r"(a[0]), "r"(a[1]), "r"(a[2]), "r"(a[3]), "r"(b[0]), "r"(b[1]));
}

// ---------------------------------------------------------------------------
// Tensor-core GEMM (tf32). PASSES=3: fp32-class; PASSES=1: plain tf32.
// EPI 0: bias; 2: Res + relu(.+bias)
// EPI 3: VQ scores -> per-(row, 32-code-chunk) min keys into C0 (ull*).
//        bias=e2, Res=z2; Bw = codebook [N x K] row-major, gathered transposed.
// Tile 128x64, BK=16, 8 warps. Rows >= rowSplit go to C1 at (m - rowSplit).
// ---------------------------------------------------------------------------
template <int PASSES, int EPI>
__global__ void __launch_bounds__(256) gemm_tc(
    const float* __restrict__ A, const float* __restrict__ Bw,
    const float* __restrict__ bias, const float* __restrict__ Res,
    float* __restrict__ C0, float* __restrict__ C1, int rowSplit,
    int M, int N, int K)
{
    __shared__ float AsH[16][132];
    __shared__ float BsH[16][68];
    __shared__ float AsL[PASSES == 3 ? 16 : 1][132];
    __shared__ float BsL[PASSES == 3 ? 16 : 1][68];

    const int t = threadIdx.x;
    const int lane = t & 31;
    const int warp = t >> 5;
    const int warpM = warp & 3;
    const int warpN = warp >> 2;
    const int m0 = blockIdx.y * 128;
    const int n0 = blockIdx.x * 64;

    float acc[2][4][4];
#pragma unroll
    for (int mt = 0; mt < 2; mt++)
#pragma unroll
        for (int nt = 0; nt < 4; nt++)
#pragma unroll
            for (int c = 0; c < 4; c++) acc[mt][nt][c] = 0.f;

    const int aRow = t >> 2, aSeg = t & 3;
    const int bRow = t >> 4, bSeg = t & 15;
    const int eCode = t >> 2, eSeg = t & 3;   // EPI==3 transposed B loader

    for (int kb = 0; kb < K; kb += 16) {
#pragma unroll
        for (int h = 0; h < 2; h++) {
            int row = aRow + h * 64;
            float4 v = *(const float4*)&A[(size_t)(m0 + row) * K + kb + aSeg * 4];
            float x[4] = {v.x, v.y, v.z, v.w};
#pragma unroll
            for (int j = 0; j < 4; j++) {
                uint32_t hb = f2tf32(x[j]);
                AsH[aSeg * 4 + j][row] = __uint_as_float(hb);
                if constexpr (PASSES == 3) {
                    float lo = x[j] - __uint_as_float(hb);
                    AsL[aSeg * 4 + j][row] = __uint_as_float(f2tf32(lo));
                }
            }
        }
        if constexpr (EPI == 3) {
            float4 v = *(const float4*)&Bw[(size_t)(n0 + eCode) * K + kb + eSeg * 4];
            float x[4] = {v.x, v.y, v.z, v.w};
#pragma unroll
            for (int j = 0; j < 4; j++)
                BsH[eSeg * 4 + j][eCode] = __uint_as_float(f2tf32(x[j]));
        } else {
            float4 v = *(const float4*)&Bw[(size_t)(kb + bRow) * N + n0 + bSeg * 4];
            float x[4] = {v.x, v.y, v.z, v.w};
#pragma unroll
            for (int j = 0; j < 4; j++) {
                uint32_t hb = f2tf32(x[j]);
                BsH[bRow][bSeg * 4 + j] = __uint_as_float(hb);
                if constexpr (PASSES == 3) {
                    float lo = x[j] - __uint_as_float(hb);
                    BsL[bRow][bSeg * 4 + j] = __uint_as_float(f2tf32(lo));
                }
            }
        }
        __syncthreads();

#pragma unroll
        for (int ks = 0; ks < 2; ks++) {
            uint32_t aH[2][4], aL[2][4], bH[4][2], bL[4][2];
            const int ar = warpM * 32 + (lane >> 2);
            const int ac = ks * 8 + (lane & 3);
#pragma unroll
            for (int mt = 0; mt < 2; mt++) {
                aH[mt][0] = __float_as_uint(AsH[ac][ar + mt * 16]);
                aH[mt][1] = __float_as_uint(AsH[ac][ar + mt * 16 + 8]);
                aH[mt][2] = __float_as_uint(AsH[ac + 4][ar + mt * 16]);
                aH[mt][3] = __float_as_uint(AsH[ac + 4][ar + mt * 16 + 8]);
                if constexpr (PASSES == 3) {
                    aL[mt][0] = __float_as_uint(AsL[ac][ar + mt * 16]);
                    aL[mt][1] = __float_as_uint(AsL[ac][ar + mt * 16 + 8]);
                    aL[mt][2] = __float_as_uint(AsL[ac + 4][ar + mt * 16]);
                    aL[mt][3] = __float_as_uint(AsL[ac + 4][ar + mt * 16 + 8]);
                }
            }
            const int bk = ks * 8 + (lane & 3);
#pragma unroll
            for (int nt = 0; nt < 4; nt++) {
                int nn = warpN * 32 + nt * 8 + (lane >> 2);
                bH[nt][0] = __float_as_uint(BsH[bk][nn]);
                bH[nt][1] = __float_as_uint(BsH[bk + 4][nn]);
                if constexpr (PASSES == 3) {
                    bL[nt][0] = __float_as_uint(BsL[bk][nn]);
                    bL[nt][1] = __float_as_uint(BsL[bk + 4][nn]);
                }
            }
#pragma unroll
            for (int mt = 0; mt < 2; mt++)
#pragma unroll
                for (int nt = 0; nt < 4; nt++) {
                    mma_tf32(acc[mt][nt], aH[mt], bH[nt]);
                    if constexpr (PASSES == 3) {
                        mma_tf32(acc[mt][nt], aH[mt], bL[nt]);
                        mma_tf32(acc[mt][nt], aL[mt], bH[nt]);
                    }
                }
        }
        __syncthreads();
    }

    // Epilogue
    if constexpr (EPI == 3) {
        ull* chunkOut = (ull*)C0;
        ull best[2][2] = {{~0ull, ~0ull}, {~0ull, ~0ull}};
#pragma unroll
        for (int mt = 0; mt < 2; mt++)
#pragma unroll
            for (int h = 0; h < 2; h++) {
                int m = m0 + warpM * 32 + mt * 16 + (lane >> 2) + h * 8;
                float z2m = Res[m];
#pragma unroll
                for (int nt = 0; nt < 4; nt++) {
                    int n = n0 + warpN * 32 + nt * 8 + 2 * (lane & 3);
                    float2 e2v = *(const float2*)&bias[n];
                    float sx = __fadd_rn(__fadd_rn(z2m, e2v.x), -2.f * acc[mt][nt][h * 2 + 0]);
                    float sy = __fadd_rn(__fadd_rn(z2m, e2v.y), -2.f * acc[mt][nt][h * 2 + 1]);
                    ull kx = ((ull)__float_as_uint(sx) << 32) | (unsigned)n;
                    ull ky = ((ull)__float_as_uint(sy) << 32) | (unsigned)(n + 1);
                    if (kx < best[mt][h]) best[mt][h] = kx;
                    if (ky < best[mt][h]) best[mt][h] = ky;
                }
            }
        const int chunk = blockIdx.x * 2 + warpN;
#pragma unroll
        for (int mt = 0; mt < 2; mt++)
#pragma unroll
            for (int h = 0; h < 2; h++) {
                ull k = best[mt][h];
                ull o = __shfl_xor_sync(0xFFFFFFFFu, k, 1); if (o < k) k = o;
                o = __shfl_xor_sync(0xFFFFFFFFu, k, 2); if (o < k) k = o;
                if ((lane & 3) == 0) {
                    int m = m0 + warpM * 32 + mt * 16 + (lane >> 2) + h * 8;
                    chunkOut[(size_t)m * NCHUNK + chunk] = k;
                }
            }
    } else {
#pragma unroll
        for (int mt = 0; mt < 2; mt++)
#pragma unroll
            for (int nt = 0; nt < 4; nt++) {
                int n = n0 + warpN * 32 + nt * 8 + 2 * (lane & 3);
                float2 bb = *(const float2*)&bias[n];
#pragma unroll
                for (int h = 0; h < 2; h++) {
                    int m = m0 + warpM * 32 + mt * 16 + (lane >> 2) + h * 8;
                    float vx = acc[mt][nt][h * 2 + 0] + bb.x;
                    float vy = acc[mt][nt][h * 2 + 1] + bb.y;
                    if constexpr (EPI >= 1) { vx = fmaxf(vx, 0.f); vy = fmaxf(vy, 0.f); }
                    if constexpr (EPI == 2) {
                        float2 r = *(const float2*)&Res[(size_t)m * N + n];
                        vx += r.x; vy += r.y;
                    }
                    float* Cp; size_t mm;
                    if (m < rowSplit) { Cp = C0; mm = (size_t)m; }
                    else              { Cp = C1; mm = (size_t)(m - rowSplit); }
                    float2 o = {vx, vy};
                    *(float2*)&Cp[mm * (size_t)N + n] = o;
                }
            }
    }
}

// ---------------------------------------------------------------------------
// Refine from chunk mins (exact fp32 rescoring, first-index tie-break)
// ---------------------------------------------------------------------------
#define MAXCHUNK 64

__global__ void __launch_bounds__(256) refine2_k(
    const ull* __restrict__ chunkmin, const float* __restrict__ Zall,
    const float* __restrict__ E, const float* __restrict__ z2,
    const float* __restrict__ e2, int* __restrict__ idxOut)
{
    __shared__ float zrow[256];
    __shared__ ull   wmin[8];
    __shared__ int   chunks[MAXCHUNK];
    __shared__ int   cnt;
    __shared__ float sthresh;
    __shared__ ull   wbest[8];

    const int m = blockIdx.x;
    const int t = threadIdx.x;
    const int warp = t >> 5, lane = t & 31;

    zrow[t] = Zall[(size_t)m * 256 + t];
    if (t == 0) cnt = 0;
    const ull ck = chunkmin[(size_t)m * NCHUNK + t];

    ull k = ck;
#pragma unroll
    for (int off = 16; off; off >>= 1) {
        ull o = __shfl_xor_sync(0xFFFFFFFFu, k, off);
        if (o < k) k = o;
    }
    if (lane == 0) wmin[warp] = k;
    __syncthreads();
    if (t < 8) {
        ull v = wmin[t];
#pragma unroll
        for (int off = 4; off; off >>= 1) {
            ull o = __shfl_xor_sync(0xFFu, v, off);
            if (o < v) v = o;
        }
        if (t == 0) sthresh = __uint_as_float((unsigned)(v >> 32)) + MARGIN;
    }
    __syncthreads();

    if (__uint_as_float((unsigned)(ck >> 32)) <= sthresh) {
        int p = atomicAdd(&cnt, 1);
        if (p < MAXCHUNK) chunks[p] = t;
    }
    __syncthreads();

    const int nc = cnt < MAXCHUNK ? cnt : MAXCHUNK;
    const float z2m = z2[m];
    ull best = ~0ull;
    for (int g = warp; g < nc * 32; g += 8) {
        int c = chunks[g >> 5] * 32 + (g & 31);
        const float* er = E + (size_t)c * 256;
        float dot = 0.f;
#pragma unroll
        for (int d = lane; d < 256; d += 32) dot += zrow[d] * er[d];
#pragma unroll
        for (int off = 16; off; off >>= 1)
            dot += __shfl_xor_sync(0xFFFFFFFFu, dot, off);
        if (lane == 0) {
            float s = __fadd_rn(__fadd_rn(z2m, e2[c]), -2.f * dot);
            ull key = ((ull)__float_as_uint(s) << 32) | (unsigned)c;
            if (key < best) best = key;
        }
    }
    if (lane == 0) wbest[warp] = best;
    __syncthreads();
    if (t < 8) {
        ull v = wbest[t];
#pragma unroll
        for (int off = 4; off; off >>= 1) {
            ull o = __shfl_xor_sync(0xFFu, v, off);
            if (o < v) v = o;
        }
        if (t == 0) idxOut[m] = (int)(v & 0xFFFFFFFFull);
    }
}

// ---------------------------------------------------------------------------
// Small kernels
// ---------------------------------------------------------------------------
__global__ void __launch_bounds__(256) e2_k(const float* __restrict__ E,
                                            float* __restrict__ e2)
{
    int w = threadIdx.x >> 5, lane = threadIdx.x & 31;
    int code = blockIdx.x * 8 + w;
    float s = 0.f;
#pragma unroll
    for (int d = lane; d < 256; d += 32) {
        float v = E[(size_t)code * 256 + d];
        s += v * v;
    }
#pragma unroll
    for (int off = 16; off; off >>= 1) s += __shfl_xor_sync(0xFFFFFFFFu, s, off);
    if (lane == 0) e2[code] = s;
}

__global__ void __launch_bounds__(256) z2_k(const float* __restrict__ Z,
                                            float* __restrict__ z2)
{
    int w = threadIdx.x >> 5, lane = threadIdx.x & 31;
    int row = blockIdx.x * 8 + w;
    const float* zr = Z + (size_t)row * 256;
    float s = 0.f;
#pragma unroll
    for (int d = lane; d < 256; d += 32) { float v = zr[d]; s += v * v; }
#pragma unroll
    for (int off = 16; off; off >>= 1) s += __shfl_xor_sync(0xFFFFFFFFu, s, off);
    if (lane == 0) z2[row] = s;
}

__global__ void __launch_bounds__(256) vq_apply_k(
    const float* __restrict__ Zall, const float* __restrict__ E,
    const int* __restrict__ idx, float* __restrict__ zOut,
    float* __restrict__ loss)
{
    __shared__ float red[8];
    int m = blockIdx.x, d = threadIdx.x;
    int k = idx[m];
    float z = Zall[(size_t)m * 256 + d];
    float q = E[(size_t)k * 256 + d];
    zOut[(size_t)m * 256 + d] = __fadd_rn(z, __fsub_rn(q, z));
    float diff = z - q;
    float ss = diff * diff;
#pragma unroll
    for (int off = 16; off; off >>= 1) ss += __shfl_xor_sync(0xFFFFFFFFu, ss, off);
    if ((d & 31) == 0) red[d >> 5] = ss;
    __syncthreads();
    if (d < 8) {
        float v = red[d];
#pragma unroll
        for (int off = 4; off; off >>= 1) v += __shfl_xor_sync(0xFFu, v, off);
        if (d == 0) loss[m] = v + 0.25f * v;
    }
}

// ---------------------------------------------------------------------------
// Host orchestration
// ---------------------------------------------------------------------------
extern "C" void kernel_launch(void* const* d_in, const int* in_sizes, int n_in,
                              void* d_out, int out_size)
{
    const float* x_a      = (const float*)d_in[0];
    const float* x_b      = (const float*)d_in[1];
    const float* enc_a_w  = (const float*)d_in[2];
    const float* enc_a_b  = (const float*)d_in[3];
    const float* enc_a_rw = (const float*)d_in[4];
    const float* enc_a_rb = (const float*)d_in[5];
    const float* enc_b_w  = (const float*)d_in[6];
    const float* enc_b_b  = (const float*)d_in[7];
    const float* enc_b_rw = (const float*)d_in[8];
    const float* enc_b_rb = (const float*)d_in[9];
    const float* dec_a_rw = (const float*)d_in[10];
    const float* dec_a_rb = (const float*)d_in[11];
    const float* dec_a_w  = (const float*)d_in[12];
    const float* dec_a_b  = (const float*)d_in[13];
    const float* dec_b_rw = (const float*)d_in[14];
    const float* dec_b_rb = (const float*)d_in[15];
    const float* dec_b_w  = (const float*)d_in[16];
    const float* dec_b_b  = (const float*)d_in[17];
    const float* codebook = (const float*)d_in[18];

    float* out = (float*)d_out;

    float *ze, *buf0, *buf1, *z2, *e2;
    int* idx;
    ull* chunk;
    cudaGetSymbolAddress((void**)&ze,    g_ze);
    cudaGetSymbolAddress((void**)&buf0,  g_buf0);
    cudaGetSymbolAddress((void**)&buf1,  g_buf1);
    cudaGetSymbolAddress((void**)&z2,    g_z2);
    cudaGetSymbolAddress((void**)&e2,    g_e2);
    cudaGetSymbolAddress((void**)&idx,   g_idx);
    cudaGetSymbolAddress((void**)&chunk, g_chunk);

    const size_t OFF_ZA = 0;
    const size_t OFF_LA = 2ull * B_ * D_;
    const size_t OFF_RA = OFF_LA + 2ull * B_;
    const size_t OFF_RB = OFF_RA + (size_t)B_ * 4096;
    const size_t OFF_XA = OFF_RB + (size_t)B_ * 2048;
    const size_t OFF_XB = OFF_XA + (size_t)B_ * 4096;

    const dim3 blk(256);
    const int BIG = 1 << 30;
    float* zeB = ze + (size_t)B_ * D_;

    e2_k<<<KCODES / 8, blk>>>(codebook, e2);

    // --- Encoders: fp32, bit-identical chain, 128x128 double-buffered ---
    const dim3 gEnc(2, 64);   // N/128 x M/128
    gemm3_k<1><<<gEnc, blk>>>(x_a, enc_a_w, enc_a_b, nullptr, buf0, B_, 256, 4096);
    gemm3_k<2><<<gEnc, blk>>>(buf0, enc_a_rw,         enc_a_rb,       buf0, buf1, B_, 256, 256);
    gemm3_k<2><<<gEnc, blk>>>(buf1, enc_a_rw + 65536, enc_a_rb + 256, buf1, ze,   B_, 256, 256);

    gemm3_k<1><<<gEnc, blk>>>(x_b, enc_b_w, enc_b_b, nullptr, buf0, B_, 256, 2048);
    gemm3_k<2><<<gEnc, blk>>>(buf0, enc_b_rw,         enc_b_rb,       buf0, buf1, B_, 256, 256);
    gemm3_k<2><<<gEnc, blk>>>(buf1, enc_b_rw + 65536, enc_b_rb + 256, buf1, zeB,  B_, 256, 256);

    // --- VQ: tf32 approx scores -> chunk-min keys -> exact fp32 refine ---
    z2_k<<<2 * B_ / 8, blk>>>(ze, z2);
    gemm_tc<1, 3><<<dim3(KCODES / 64, 2 * B_ / 128), blk>>>(
        ze, codebook, e2, z2, (float*)chunk, nullptr, BIG, 2 * B_, KCODES, 256);
    refine2_k<<<2 * B_, blk>>>(chunk, ze, codebook, z2, e2, idx);
    vq_apply_k<<<2 * B_, blk>>>(ze, codebook, idx, out + OFF_ZA, out + OFF_LA);

    // --- Decoders: batched [z_a; z_b] (M=16384), 1-pass tf32 throughout ---
    gemm_tc<1, 2><<<dim3(4, 128), blk>>>(out, dec_a_rw, dec_a_rb, out,
                                         buf0, buf0, BIG, 2 * B_, 256, 256);
    gemm_tc<1, 2><<<dim3(4, 128), blk>>>(buf0, dec_a_rw + 65536, dec_a_rb + 256, buf0,
                                         buf1, buf1, BIG, 2 * B_, 256, 256);
    gemm_tc<1, 0><<<dim3(64, 128), blk>>>(buf1, dec_a_w, dec_a_b, nullptr,
                                          out + OFF_RA, out + OFF_XA, B_,
                                          2 * B_, 4096, 256);

    gemm_tc<1, 2><<<dim3(4, 128), blk>>>(out, dec_b_rw, dec_b_rb, out,
                                         buf0, buf0, BIG, 2 * B_, 256, 256);
    gemm_tc<1, 2><<<dim3(4, 128), blk>>>(buf0, dec_b_rw + 65536, dec_b_rb + 256, buf0,
                                         buf1, buf1, BIG, 2 * B_, 256, 256);
    gemm_tc<1, 0><<<dim3(32, 128), blk>>>(buf1, dec_b_w, dec_b_b, nullptr,
                                          out + OFF_XB, out + OFF_RB, B_,
                                          2 * B_, 2048, 256);
}

// round 11
// speedup vs baseline: 1.9699x; 1.0096x over previous
#include <cuda_runtime.h>
#include <stdint.h>

#define B_ 8192
#define D_ 256
#define KCODES 8192
#define NCHUNK (KCODES / 32)     // 256 chunk keys per row
#define MARGIN 2e-4f

typedef unsigned long long ull;

// Scratch (device globals; no allocation allowed)
__device__ float g_ze[2 * B_ * D_];       // [zeA; zeB]
__device__ float g_buf0[2 * B_ * D_];
__device__ float g_buf1[2 * B_ * D_];
__device__ float g_z2[2 * B_];
__device__ float g_e2[KCODES];
__device__ int   g_idx[2 * B_];
__device__ ull   g_chunk[(size_t)2 * B_ * NCHUNK];   // 32 MB chunk-min keys

// ---------------------------------------------------------------------------
// f32x2 packed helpers (two independent .rn fp32 ops per instruction; per-lane
// rounding identical to scalar FFMA -> bit-identical accumulation chains)
// ---------------------------------------------------------------------------
__device__ __forceinline__ ull pack2(float x, float y) {
    ull r;
    asm("mov.b64 %0, {%1, %2};" : "=l"(r) : "f"(x), "f"(y));
    return r;
}
__device__ __forceinline__ void fma2(ull& d, ull a, ull b) {
    asm("fma.rn.f32x2 %0, %1, %2, %0;" : "+l"(d) : "l"(a), "l"(b));
}
__device__ __forceinline__ void unpack2(float& lo, float& hi, ull v) {
    asm("mov.b64 {%0, %1}, %2;" : "=f"(lo), "=f"(hi) : "l"(v));
}

// ---------------------------------------------------------------------------
// fp32 SIMT GEMM, 128x128 tile, 8x8 micro-tile, double-buffered smem,
// FFMA2 (f32x2) inner product. BIT-IDENTICAL per-output accumulation vs
// rounds 1/7/8/9: acc = fma(a_k, b_k, acc), k strictly ascending, same
// epilogue expressions. EPI 1: relu(.+bias); 2: Res + relu(.+bias)
// ---------------------------------------------------------------------------
template <int EPI>
__global__ void __launch_bounds__(256) gemm3_k(
    const float* __restrict__ A, const float* __restrict__ Bm,
    const float* __restrict__ bias, const float* __restrict__ Res,
    float* __restrict__ C, int M, int N, int K)
{
    __shared__ __align__(16) float As[2][16][132];   // [k][m], padded
    __shared__ __align__(16) float Bs[2][16][128];   // [k][n]

    const int t  = threadIdx.x;
    const int ty = t >> 4;             // 0..15 -> 8 rows
    const int tx = t & 15;             // 0..15 -> 8 cols
    const int m0 = blockIdx.y * 128;
    const int n0 = blockIdx.x * 128;

    const int ar0 = t >> 2,         as0 = t & 3;
    const int ar1 = (t + 256) >> 2, as1 = (t + 256) & 3;
    const int br0 = t >> 5,         bs0 = t & 31;
    const int br1 = (t + 256) >> 5, bs1 = (t + 256) & 31;

    // packed accumulators: acc2[i][j] = cols (2j, 2j+1) of row i
    ull acc2[8][4];
#pragma unroll
    for (int i = 0; i < 8; i++)
#pragma unroll
        for (int j = 0; j < 4; j++) acc2[i][j] = 0ull;

    // preload tile kb=0 into buffer 0
    {
        float4 a0 = *(const float4*)&A[(size_t)(m0 + ar0) * K + as0 * 4];
        float4 a1 = *(const float4*)&A[(size_t)(m0 + ar1) * K + as1 * 4];
        float4 b0 = *(const float4*)&Bm[(size_t)br0 * N + n0 + bs0 * 4];
        float4 b1 = *(const float4*)&Bm[(size_t)br1 * N + n0 + bs1 * 4];
        As[0][as0 * 4 + 0][ar0] = a0.x; As[0][as0 * 4 + 1][ar0] = a0.y;
        As[0][as0 * 4 + 2][ar0] = a0.z; As[0][as0 * 4 + 3][ar0] = a0.w;
        As[0][as1 * 4 + 0][ar1] = a1.x; As[0][as1 * 4 + 1][ar1] = a1.y;
        As[0][as1 * 4 + 2][ar1] = a1.z; As[0][as1 * 4 + 3][ar1] = a1.w;
        *(float4*)&Bs[0][br0][bs0 * 4] = b0;
        *(float4*)&Bs[0][br1][bs1 * 4] = b1;
    }
    __syncthreads();

    int p = 0;
    for (int kb = 16; kb < K; kb += 16) {
        float4 a0 = *(const float4*)&A[(size_t)(m0 + ar0) * K + kb + as0 * 4];
        float4 a1 = *(const float4*)&A[(size_t)(m0 + ar1) * K + kb + as1 * 4];
        float4 b0 = *(const float4*)&Bm[(size_t)(kb + br0) * N + n0 + bs0 * 4];
        float4 b1 = *(const float4*)&Bm[(size_t)(kb + br1) * N + n0 + bs1 * 4];

#pragma unroll
        for (int kk = 0; kk < 16; kk++) {
            float4 x0 = *(const float4*)&As[p][kk][ty * 8];
            float4 x1 = *(const float4*)&As[p][kk][ty * 8 + 4];
            const ull* brow = (const ull*)&Bs[p][kk][tx * 8];
            ull b2[4] = {brow[0], brow[1], brow[2], brow[3]};
            float a[8] = {x0.x, x0.y, x0.z, x0.w, x1.x, x1.y, x1.z, x1.w};
#pragma unroll
            for (int i = 0; i < 8; i++) {
                ull aa = pack2(a[i], a[i]);
#pragma unroll
                for (int j = 0; j < 4; j++) fma2(acc2[i][j], aa, b2[j]);
            }
        }

        int q = p ^ 1;
        As[q][as0 * 4 + 0][ar0] = a0.x; As[q][as0 * 4 + 1][ar0] = a0.y;
        As[q][as0 * 4 + 2][ar0] = a0.z; As[q][as0 * 4 + 3][ar0] = a0.w;
        As[q][as1 * 4 + 0][ar1] = a1.x; As[q][as1 * 4 + 1][ar1] = a1.y;
        As[q][as1 * 4 + 2][ar1] = a1.z; As[q][as1 * 4 + 3][ar1] = a1.w;
        *(float4*)&Bs[q][br0][bs0 * 4] = b0;
        *(float4*)&Bs[q][br1][bs1 * 4] = b1;
        __syncthreads();
        p = q;
    }

    // final tile
#pragma unroll
    for (int kk = 0; kk < 16; kk++) {
        float4 x0 = *(const float4*)&As[p][kk][ty * 8];
        float4 x1 = *(const float4*)&As[p][kk][ty * 8 + 4];
        const ull* brow = (const ull*)&Bs[p][kk][tx * 8];
        ull b2[4] = {brow[0], brow[1], brow[2], brow[3]};
        float a[8] = {x0.x, x0.y, x0.z, x0.w, x1.x, x1.y, x1.z, x1.w};
#pragma unroll
        for (int i = 0; i < 8; i++) {
            ull aa = pack2(a[i], a[i]);
#pragma unroll
            for (int j = 0; j < 4; j++) fma2(acc2[i][j], aa, b2[j]);
        }
    }

    // epilogue (same expressions as rounds 1/7/8/9)
    float4 bb0 = *(const float4*)&bias[n0 + tx * 8];
    float4 bb1 = *(const float4*)&bias[n0 + tx * 8 + 4];
    float bcol[8] = {bb0.x, bb0.y, bb0.z, bb0.w, bb1.x, bb1.y, bb1.z, bb1.w};
#pragma unroll
    for (int i = 0; i < 8; i++) {
        int m = m0 + ty * 8 + i;
        float v[8];
#pragma unroll
        for (int j = 0; j < 4; j++) unpack2(v[2 * j], v[2 * j + 1], acc2[i][j]);
#pragma unroll
        for (int j = 0; j < 8; j++) {
            v[j] = v[j] + bcol[j];
            if (EPI >= 1) v[j] = fmaxf(v[j], 0.f);
        }
        if (EPI == 2) {
            float4 r0 = *(const float4*)&Res[(size_t)m * N + n0 + tx * 8];
            float4 r1 = *(const float4*)&Res[(size_t)m * N + n0 + tx * 8 + 4];
            v[0] += r0.x; v[1] += r0.y; v[2] += r0.z; v[3] += r0.w;
            v[4] += r1.x; v[5] += r1.y; v[6] += r1.z; v[7] += r1.w;
        }
        float4 o0 = {v[0], v[1], v[2], v[3]};
        float4 o1 = {v[4], v[5], v[6], v[7]};
        *(float4*)&C[(size_t)m * N + n0 + tx * 8] = o0;
        *(float4*)&C[(size_t)m * N + n0 + tx * 8 + 4] = o1;
    }
}

// ---------------------------------------------------------------------------
// tf32 helpers
// ---------------------------------------------------------------------------
__device__ __forceinline__ uint32_t f2tf32(float x) {
    uint32_t r;
    asm("cvt.rna.tf32.f32 %0, %1;" : "=r"(r) : "f"(x));
    return r;
}

__device__ __forceinline__ void mma_tf32(float* d, const uint32_t* a, const uint32_t* b) {
    asm volatile(
        "mma.sync.aligned.m16n8k8.row.col.f32.tf32.tf32.f32 "
        "{%0,%1,%2,%3}, {%4,%5,%6,%7}, {%8,%9}, {%0,%1,%2,%3};\n"
        : "+f"(d[0]), "+f"(d[1]), "+f"(d[2]), "+f"(d[3])
        : "r"(a[0]), "r"(a[1]), "r"(a[2]), "r"(a[3]), "r"(b[0]), "r"(b[1]));
}

// ---------------------------------------------------------------------------
// Tensor-core GEMM (tf32). PASSES=3: fp32-class; PASSES=1: plain tf32.
// EPI 0: bias; 2: Res + relu(.+bias)
// EPI 3: VQ scores -> per-(row, 32-code-chunk) min keys into C0 (ull*).
//        bias=e2, Res=z2; Bw = codebook [N x K] row-major, gathered transposed.
// Tile 128x64, BK=16, 8 warps. Rows >= rowSplit go to C1 at (m - rowSplit).
// ---------------------------------------------------------------------------
template <int PASSES, int EPI>
__global__ void __launch_bounds__(256) gemm_tc(
    const float* __restrict__ A, const float* __restrict__ Bw,
    const float* __restrict__ bias, const float* __restrict__ Res,
    float* __restrict__ C0, float* __restrict__ C1, int rowSplit,
    int M, int N, int K)
{
    __shared__ float AsH[16][132];
    __shared__ float BsH[16][68];
    __shared__ float AsL[PASSES == 3 ? 16 : 1][132];
    __shared__ float BsL[PASSES == 3 ? 16 : 1][68];

    const int t = threadIdx.x;
    const int lane = t & 31;
    const int warp = t >> 5;
    const int warpM = warp & 3;
    const int warpN = warp >> 2;
    const int m0 = blockIdx.y * 128;
    const int n0 = blockIdx.x * 64;

    float acc[2][4][4];
#pragma unroll
    for (int mt = 0; mt < 2; mt++)
#pragma unroll
        for (int nt = 0; nt < 4; nt++)
#pragma unroll
            for (int c = 0; c < 4; c++) acc[mt][nt][c] = 0.f;

    const int aRow = t >> 2, aSeg = t & 3;
    const int bRow = t >> 4, bSeg = t & 15;
    const int eCode = t >> 2, eSeg = t & 3;   // EPI==3 transposed B loader

    for (int kb = 0; kb < K; kb += 16) {
#pragma unroll
        for (int h = 0; h < 2; h++) {
            int row = aRow + h * 64;
            float4 v = *(const float4*)&A[(size_t)(m0 + row) * K + kb + aSeg * 4];
            float x[4] = {v.x, v.y, v.z, v.w};
#pragma unroll
            for (int j = 0; j < 4; j++) {
                uint32_t hb = f2tf32(x[j]);
                AsH[aSeg * 4 + j][row] = __uint_as_float(hb);
                if constexpr (PASSES == 3) {
                    float lo = x[j] - __uint_as_float(hb);
                    AsL[aSeg * 4 + j][row] = __uint_as_float(f2tf32(lo));
                }
            }
        }
        if constexpr (EPI == 3) {
            float4 v = *(const float4*)&Bw[(size_t)(n0 + eCode) * K + kb + eSeg * 4];
            float x[4] = {v.x, v.y, v.z, v.w};
#pragma unroll
            for (int j = 0; j < 4; j++)
                BsH[eSeg * 4 + j][eCode] = __uint_as_float(f2tf32(x[j]));
        } else {
            float4 v = *(const float4*)&Bw[(size_t)(kb + bRow) * N + n0 + bSeg * 4];
            float x[4] = {v.x, v.y, v.z, v.w};
#pragma unroll
            for (int j = 0; j < 4; j++) {
                uint32_t hb = f2tf32(x[j]);
                BsH[bRow][bSeg * 4 + j] = __uint_as_float(hb);
                if constexpr (PASSES == 3) {
                    float lo = x[j] - __uint_as_float(hb);
                    BsL[bRow][bSeg * 4 + j] = __uint_as_float(f2tf32(lo));
                }
            }
        }
        __syncthreads();

#pragma unroll
        for (int ks = 0; ks < 2; ks++) {
            uint32_t aH[2][4], aL[2][4], bH[4][2], bL[4][2];
            const int ar = warpM * 32 + (lane >> 2);
            const int ac = ks * 8 + (lane & 3);
#pragma unroll
            for (int mt = 0; mt < 2; mt++) {
                aH[mt][0] = __float_as_uint(AsH[ac][ar + mt * 16]);
                aH[mt][1] = __float_as_uint(AsH[ac][ar + mt * 16 + 8]);
                aH[mt][2] = __float_as_uint(AsH[ac + 4][ar + mt * 16]);
                aH[mt][3] = __float_as_uint(AsH[ac + 4][ar + mt * 16 + 8]);
                if constexpr (PASSES == 3) {
                    aL[mt][0] = __float_as_uint(AsL[ac][ar + mt * 16]);
                    aL[mt][1] = __float_as_uint(AsL[ac][ar + mt * 16 + 8]);
                    aL[mt][2] = __float_as_uint(AsL[ac + 4][ar + mt * 16]);
                    aL[mt][3] = __float_as_uint(AsL[ac + 4][ar + mt * 16 + 8]);
                }
            }
            const int bk = ks * 8 + (lane & 3);
#pragma unroll
            for (int nt = 0; nt < 4; nt++) {
                int nn = warpN * 32 + nt * 8 + (lane >> 2);
                bH[nt][0] = __float_as_uint(BsH[bk][nn]);
                bH[nt][1] = __float_as_uint(BsH[bk + 4][nn]);
                if constexpr (PASSES == 3) {
                    bL[nt][0] = __float_as_uint(BsL[bk][nn]);
                    bL[nt][1] = __float_as_uint(BsL[bk + 4][nn]);
                }
            }
#pragma unroll
            for (int mt = 0; mt < 2; mt++)
#pragma unroll
                for (int nt = 0; nt < 4; nt++) {
                    mma_tf32(acc[mt][nt], aH[mt], bH[nt]);
                    if constexpr (PASSES == 3) {
                        mma_tf32(acc[mt][nt], aH[mt], bL[nt]);
                        mma_tf32(acc[mt][nt], aL[mt], bH[nt]);
                    }
                }
        }
        __syncthreads();
    }

    // Epilogue
    if constexpr (EPI == 3) {
        ull* chunkOut = (ull*)C0;
        ull best[2][2] = {{~0ull, ~0ull}, {~0ull, ~0ull}};
#pragma unroll
        for (int mt = 0; mt < 2; mt++)
#pragma unroll
            for (int h = 0; h < 2; h++) {
                int m = m0 + warpM * 32 + mt * 16 + (lane >> 2) + h * 8;
                float z2m = Res[m];
#pragma unroll
                for (int nt = 0; nt < 4; nt++) {
                    int n = n0 + warpN * 32 + nt * 8 + 2 * (lane & 3);
                    float2 e2v = *(const float2*)&bias[n];
                    float sx = __fadd_rn(__fadd_rn(z2m, e2v.x), -2.f * acc[mt][nt][h * 2 + 0]);
                    float sy = __fadd_rn(__fadd_rn(z2m, e2v.y), -2.f * acc[mt][nt][h * 2 + 1]);
                    ull kx = ((ull)__float_as_uint(sx) << 32) | (unsigned)n;
                    ull ky = ((ull)__float_as_uint(sy) << 32) | (unsigned)(n + 1);
                    if (kx < best[mt][h]) best[mt][h] = kx;
                    if (ky < best[mt][h]) best[mt][h] = ky;
                }
            }
        const int chunk = blockIdx.x * 2 + warpN;
#pragma unroll
        for (int mt = 0; mt < 2; mt++)
#pragma unroll
            for (int h = 0; h < 2; h++) {
                ull k = best[mt][h];
                ull o = __shfl_xor_sync(0xFFFFFFFFu, k, 1); if (o < k) k = o;
                o = __shfl_xor_sync(0xFFFFFFFFu, k, 2); if (o < k) k = o;
                if ((lane & 3) == 0) {
                    int m = m0 + warpM * 32 + mt * 16 + (lane >> 2) + h * 8;
                    chunkOut[(size_t)m * NCHUNK + chunk] = k;
                }
            }
    } else {
#pragma unroll
        for (int mt = 0; mt < 2; mt++)
#pragma unroll
            for (int nt = 0; nt < 4; nt++) {
                int n = n0 + warpN * 32 + nt * 8 + 2 * (lane & 3);
                float2 bb = *(const float2*)&bias[n];
#pragma unroll
                for (int h = 0; h < 2; h++) {
                    int m = m0 + warpM * 32 + mt * 16 + (lane >> 2) + h * 8;
                    float vx = acc[mt][nt][h * 2 + 0] + bb.x;
                    float vy = acc[mt][nt][h * 2 + 1] + bb.y;
                    if constexpr (EPI >= 1) { vx = fmaxf(vx, 0.f); vy = fmaxf(vy, 0.f); }
                    if constexpr (EPI == 2) {
                        float2 r = *(const float2*)&Res[(size_t)m * N + n];
                        vx += r.x; vy += r.y;
                    }
                    float* Cp; size_t mm;
                    if (m < rowSplit) { Cp = C0; mm = (size_t)m; }
                    else              { Cp = C1; mm = (size_t)(m - rowSplit); }
                    float2 o = {vx, vy};
                    *(float2*)&Cp[mm * (size_t)N + n] = o;
                }
            }
    }
}

// ---------------------------------------------------------------------------
// Refine from chunk mins (exact fp32 rescoring, first-index tie-break)
// ---------------------------------------------------------------------------
#define MAXCHUNK 64

__global__ void __launch_bounds__(256) refine2_k(
    const ull* __restrict__ chunkmin, const float* __restrict__ Zall,
    const float* __restrict__ E, const float* __restrict__ z2,
    const float* __restrict__ e2, int* __restrict__ idxOut)
{
    __shared__ float zrow[256];
    __shared__ ull   wmin[8];
    __shared__ int   chunks[MAXCHUNK];
    __shared__ int   cnt;
    __shared__ float sthresh;
    __shared__ ull   wbest[8];

    const int m = blockIdx.x;
    const int t = threadIdx.x;
    const int warp = t >> 5, lane = t & 31;

    zrow[t] = Zall[(size_t)m * 256 + t];
    if (t == 0) cnt = 0;
    const ull ck = chunkmin[(size_t)m * NCHUNK + t];

    ull k = ck;
#pragma unroll
    for (int off = 16; off; off >>= 1) {
        ull o = __shfl_xor_sync(0xFFFFFFFFu, k, off);
        if (o < k) k = o;
    }
    if (lane == 0) wmin[warp] = k;
    __syncthreads();
    if (t < 8) {
        ull v = wmin[t];
#pragma unroll
        for (int off = 4; off; off >>= 1) {
            ull o = __shfl_xor_sync(0xFFu, v, off);
            if (o < v) v = o;
        }
        if (t == 0) sthresh = __uint_as_float((unsigned)(v >> 32)) + MARGIN;
    }
    __syncthreads();

    if (__uint_as_float((unsigned)(ck >> 32)) <= sthresh) {
        int p = atomicAdd(&cnt, 1);
        if (p < MAXCHUNK) chunks[p] = t;
    }
    __syncthreads();

    const int nc = cnt < MAXCHUNK ? cnt : MAXCHUNK;
    const float z2m = z2[m];
    ull best = ~0ull;
    for (int g = warp; g < nc * 32; g += 8) {
        int c = chunks[g >> 5] * 32 + (g & 31);
        const float* er = E + (size_t)c * 256;
        float dot = 0.f;
#pragma unroll
        for (int d = lane; d < 256; d += 32) dot += zrow[d] * er[d];
#pragma unroll
        for (int off = 16; off; off >>= 1)
            dot += __shfl_xor_sync(0xFFFFFFFFu, dot, off);
        if (lane == 0) {
            float s = __fadd_rn(__fadd_rn(z2m, e2[c]), -2.f * dot);
            ull key = ((ull)__float_as_uint(s) << 32) | (unsigned)c;
            if (key < best) best = key;
        }
    }
    if (lane == 0) wbest[warp] = best;
    __syncthreads();
    if (t < 8) {
        ull v = wbest[t];
#pragma unroll
        for (int off = 4; off; off >>= 1) {
            ull o = __shfl_xor_sync(0xFFu, v, off);
            if (o < v) v = o;
        }
        if (t == 0) idxOut[m] = (int)(v & 0xFFFFFFFFull);
    }
}

// ---------------------------------------------------------------------------
// Small kernels
// ---------------------------------------------------------------------------
__global__ void __launch_bounds__(256) e2_k(const float* __restrict__ E,
                                            float* __restrict__ e2)
{
    int w = threadIdx.x >> 5, lane = threadIdx.x & 31;
    int code = blockIdx.x * 8 + w;
    float s = 0.f;
#pragma unroll
    for (int d = lane; d < 256; d += 32) {
        float v = E[(size_t)code * 256 + d];
        s += v * v;
    }
#pragma unroll
    for (int off = 16; off; off >>= 1) s += __shfl_xor_sync(0xFFFFFFFFu, s, off);
    if (lane == 0) e2[code] = s;
}

__global__ void __launch_bounds__(256) z2_k(const float* __restrict__ Z,
                                            float* __restrict__ z2)
{
    int w = threadIdx.x >> 5, lane = threadIdx.x & 31;
    int row = blockIdx.x * 8 + w;
    const float* zr = Z + (size_t)row * 256;
    float s = 0.f;
#pragma unroll
    for (int d = lane; d < 256; d += 32) { float v = zr[d]; s += v * v; }
#pragma unroll
    for (int off = 16; off; off >>= 1) s += __shfl_xor_sync(0xFFFFFFFFu, s, off);
    if (lane == 0) z2[row] = s;
}

__global__ void __launch_bounds__(256) vq_apply_k(
    const float* __restrict__ Zall, const float* __restrict__ E,
    const int* __restrict__ idx, float* __restrict__ zOut,
    float* __restrict__ loss)
{
    __shared__ float red[8];
    int m = blockIdx.x, d = threadIdx.x;
    int k = idx[m];
    float z = Zall[(size_t)m * 256 + d];
    float q = E[(size_t)k * 256 + d];
    zOut[(size_t)m * 256 + d] = __fadd_rn(z, __fsub_rn(q, z));
    float diff = z - q;
    float ss = diff * diff;
#pragma unroll
    for (int off = 16; off; off >>= 1) ss += __shfl_xor_sync(0xFFFFFFFFu, ss, off);
    if ((d & 31) == 0) red[d >> 5] = ss;
    __syncthreads();
    if (d < 8) {
        float v = red[d];
#pragma unroll
        for (int off = 4; off; off >>= 1) v += __shfl_xor_sync(0xFFu, v, off);
        if (d == 0) loss[m] = v + 0.25f * v;
    }
}

// ---------------------------------------------------------------------------
// Host orchestration
// ---------------------------------------------------------------------------
extern "C" void kernel_launch(void* const* d_in, const int* in_sizes, int n_in,
                              void* d_out, int out_size)
{
    const float* x_a      = (const float*)d_in[0];
    const float* x_b      = (const float*)d_in[1];
    const float* enc_a_w  = (const float*)d_in[2];
    const float* enc_a_b  = (const float*)d_in[3];
    const float* enc_a_rw = (const float*)d_in[4];
    const float* enc_a_rb = (const float*)d_in[5];
    const float* enc_b_w  = (const float*)d_in[6];
    const float* enc_b_b  = (const float*)d_in[7];
    const float* enc_b_rw = (const float*)d_in[8];
    const float* enc_b_rb = (const float*)d_in[9];
    const float* dec_a_rw = (const float*)d_in[10];
    const float* dec_a_rb = (const float*)d_in[11];
    const float* dec_a_w  = (const float*)d_in[12];
    const float* dec_a_b  = (const float*)d_in[13];
    const float* dec_b_rw = (const float*)d_in[14];
    const float* dec_b_rb = (const float*)d_in[15];
    const float* dec_b_w  = (const float*)d_in[16];
    const float* dec_b_b  = (const float*)d_in[17];
    const float* codebook = (const float*)d_in[18];

    float* out = (float*)d_out;

    float *ze, *buf0, *buf1, *z2, *e2;
    int* idx;
    ull* chunk;
    cudaGetSymbolAddress((void**)&ze,    g_ze);
    cudaGetSymbolAddress((void**)&buf0,  g_buf0);
    cudaGetSymbolAddress((void**)&buf1,  g_buf1);
    cudaGetSymbolAddress((void**)&z2,    g_z2);
    cudaGetSymbolAddress((void**)&e2,    g_e2);
    cudaGetSymbolAddress((void**)&idx,   g_idx);
    cudaGetSymbolAddress((void**)&chunk, g_chunk);

    const size_t OFF_ZA = 0;
    const size_t OFF_LA = 2ull * B_ * D_;
    const size_t OFF_RA = OFF_LA + 2ull * B_;
    const size_t OFF_RB = OFF_RA + (size_t)B_ * 4096;
    const size_t OFF_XA = OFF_RB + (size_t)B_ * 2048;
    const size_t OFF_XB = OFF_XA + (size_t)B_ * 4096;

    const dim3 blk(256);
    const int BIG = 1 << 30;
    float* zeB = ze + (size_t)B_ * D_;

    e2_k<<<KCODES / 8, blk>>>(codebook, e2);

    // --- Encoders: fp32 FFMA2, bit-identical chain, 128x128 double-buffered ---
    const dim3 gEnc(2, 64);   // N/128 x M/128
    gemm3_k<1><<<gEnc, blk>>>(x_a, enc_a_w, enc_a_b, nullptr, buf0, B_, 256, 4096);
    gemm3_k<2><<<gEnc, blk>>>(buf0, enc_a_rw,         enc_a_rb,       buf0, buf1, B_, 256, 256);
    gemm3_k<2><<<gEnc, blk>>>(buf1, enc_a_rw + 65536, enc_a_rb + 256, buf1, ze,   B_, 256, 256);

    gemm3_k<1><<<gEnc, blk>>>(x_b, enc_b_w, enc_b_b, nullptr, buf0, B_, 256, 2048);
    gemm3_k<2><<<gEnc, blk>>>(buf0, enc_b_rw,         enc_b_rb,       buf0, buf1, B_, 256, 256);
    gemm3_k<2><<<gEnc, blk>>>(buf1, enc_b_rw + 65536, enc_b_rb + 256, buf1, zeB,  B_, 256, 256);

    // --- VQ: tf32 approx scores -> chunk-min keys -> exact fp32 refine ---
    z2_k<<<2 * B_ / 8, blk>>>(ze, z2);
    gemm_tc<1, 3><<<dim3(KCODES / 64, 2 * B_ / 128), blk>>>(
        ze, codebook, e2, z2, (float*)chunk, nullptr, BIG, 2 * B_, KCODES, 256);
    refine2_k<<<2 * B_, blk>>>(chunk, ze, codebook, z2, e2, idx);
    vq_apply_k<<<2 * B_, blk>>>(ze, codebook, idx, out + OFF_ZA, out + OFF_LA);

    // --- Decoders: batched [z_a; z_b] (M=16384), 1-pass tf32 throughout ---
    gemm_tc<1, 2><<<dim3(4, 128), blk>>>(out, dec_a_rw, dec_a_rb, out,
                                         buf0, buf0, BIG, 2 * B_, 256, 256);
    gemm_tc<1, 2><<<dim3(4, 128), blk>>>(buf0, dec_a_rw + 65536, dec_a_rb + 256, buf0,
                                         buf1, buf1, BIG, 2 * B_, 256, 256);
    gemm_tc<1, 0><<<dim3(64, 128), blk>>>(buf1, dec_a_w, dec_a_b, nullptr,
                                          out + OFF_RA, out + OFF_XA, B_,
                                          2 * B_, 4096, 256);

    gemm_tc<1, 2><<<dim3(4, 128), blk>>>(out, dec_b_rw, dec_b_rb, out,
                                         buf0, buf0, BIG, 2 * B_, 256, 256);
    gemm_tc<1, 2><<<dim3(4, 128), blk>>>(buf0, dec_b_rw + 65536, dec_b_rb + 256, buf0,
                                         buf1, buf1, BIG, 2 * B_, 256, 256);
    gemm_tc<1, 0><<<dim3(32, 128), blk>>>(buf1, dec_b_w, dec_b_b, nullptr,
                                          out + OFF_XB, out + OFF_RB, B_,
                                          2 * B_, 2048, 256);
}

// round 12
// speedup vs baseline: 2.3361x; 1.1859x over previous
#include <cuda_runtime.h>
#include <stdint.h>

#define B_ 8192
#define D_ 256
#define KCODES 8192
#define NCHUNK (KCODES / 32)     // 256 chunk keys per row
#define MARGIN 4e-4f

typedef unsigned long long ull;

// Scratch (device globals; no allocation allowed)
__device__ float g_ze[2 * B_ * D_];       // [zeA; zeB]
__device__ float g_buf0[2 * B_ * D_];
__device__ float g_buf1[2 * B_ * D_];
__device__ float g_z2[2 * B_];
__device__ float g_e2[KCODES];
__device__ int   g_idx[2 * B_];
__device__ ull   g_chunk[(size_t)2 * B_ * NCHUNK];   // 32 MB chunk-min keys

// ---------------------------------------------------------------------------
// Merged dual-problem fp32 SIMT GEMM (R8's proven bit-identical gemm2_k body:
// per output (m,n) acc = fma(a_k,b_k,acc), k ascending, same epilogue).
// Tile 128x64, BK=16, 8x4 micro-tile, 66 regs -> 3 CTAs/SM for smooth packing.
// blockIdx.z selects problem {0,1}. EPI 1: relu(.+bias); 2: Res + relu(.+bias)
// ---------------------------------------------------------------------------
template <int EPI>
__global__ void __launch_bounds__(256) gemm2m_k(
    const float* __restrict__ A0, const float* __restrict__ A1,
    const float* __restrict__ W0, const float* __restrict__ W1,
    const float* __restrict__ bias0, const float* __restrict__ bias1,
    const float* __restrict__ Res0, const float* __restrict__ Res1,
    float* __restrict__ C0, float* __restrict__ C1,
    int M, int N, int K0, int K1)
{
    const float* A    = blockIdx.z ? A1 : A0;
    const float* Bm   = blockIdx.z ? W1 : W0;
    const float* bias = blockIdx.z ? bias1 : bias0;
    const float* Res  = blockIdx.z ? Res1 : Res0;
    float* C          = blockIdx.z ? C1 : C0;
    const int K       = blockIdx.z ? K1 : K0;

    __shared__ float As[16][132];   // [k][m], padded
    __shared__ float Bs[16][64];    // [k][n]

    const int t  = threadIdx.x;
    const int ty = t >> 4;          // 0..15 -> 8 rows each
    const int tx = t & 15;          // 0..15 -> 4 cols each
    const int m0 = blockIdx.y * 128;
    const int n0 = blockIdx.x * 64;

    const int brow = t >> 4, bseg = t & 15;

    float acc[8][4];
#pragma unroll
    for (int i = 0; i < 8; i++)
#pragma unroll
        for (int j = 0; j < 4; j++) acc[i][j] = 0.f;

    for (int kb = 0; kb < K; kb += 16) {
        // stage A tile 128x16: 512 float4 / 256 threads = 2 each, transposed
#pragma unroll
        for (int i = 0; i < 2; i++) {
            int f = t + i * 256;
            int row = f >> 2, seg = f & 3;
            float4 v = *(const float4*)&A[(size_t)(m0 + row) * K + kb + seg * 4];
            As[seg * 4 + 0][row] = v.x;
            As[seg * 4 + 1][row] = v.y;
            As[seg * 4 + 2][row] = v.z;
            As[seg * 4 + 3][row] = v.w;
        }
        // stage B tile 16x64
        {
            float4 v = *(const float4*)&Bm[(size_t)(kb + brow) * N + n0 + bseg * 4];
            *(float4*)&Bs[brow][bseg * 4] = v;
        }
        __syncthreads();
#pragma unroll
        for (int kk = 0; kk < 16; kk++) {
            float4 a0 = *(const float4*)&As[kk][ty * 8];
            float4 a1 = *(const float4*)&As[kk][ty * 8 + 4];
            float4 b4 = *(const float4*)&Bs[kk][tx * 4];
            float a[8] = {a0.x, a0.y, a0.z, a0.w, a1.x, a1.y, a1.z, a1.w};
            float b[4] = {b4.x, b4.y, b4.z, b4.w};
#pragma unroll
            for (int i = 0; i < 8; i++)
#pragma unroll
                for (int j = 0; j < 4; j++) acc[i][j] += a[i] * b[j];
        }
        __syncthreads();
    }

    float4 bb = *(const float4*)&bias[n0 + tx * 4];
    float bcol[4] = {bb.x, bb.y, bb.z, bb.w};
#pragma unroll
    for (int i = 0; i < 8; i++) {
        int m = m0 + ty * 8 + i;
        float v[4];
#pragma unroll
        for (int j = 0; j < 4; j++) {
            v[j] = acc[i][j] + bcol[j];
            if (EPI >= 1) v[j] = fmaxf(v[j], 0.f);
        }
        if (EPI == 2) {
            float4 r = *(const float4*)&Res[(size_t)m * N + n0 + tx * 4];
            v[0] += r.x; v[1] += r.y; v[2] += r.z; v[3] += r.w;
        }
        float4 o = {v[0], v[1], v[2], v[3]};
        *(float4*)&C[(size_t)m * N + n0 + tx * 4] = o;
    }
}

// ---------------------------------------------------------------------------
// bf16 / tf32 helpers
// ---------------------------------------------------------------------------
__device__ __forceinline__ uint32_t packbf(float lo, float hi) {
    uint32_t r;
    asm("cvt.rn.bf16x2.f32 %0, %1, %2;" : "=r"(r) : "f"(hi), "f"(lo));
    return r;
}

__device__ __forceinline__ void mma_bf16(float* d, const uint32_t* a, const uint32_t* b) {
    asm volatile(
        "mma.sync.aligned.m16n8k16.row.col.f32.bf16.bf16.f32 "
        "{%0,%1,%2,%3}, {%4,%5,%6,%7}, {%8,%9}, {%0,%1,%2,%3};\n"
        : "+f"(d[0]), "+f"(d[1]), "+f"(d[2]), "+f"(d[3])
        : "r"(a[0]), "r"(a[1]), "r"(a[2]), "r"(a[3]), "r"(b[0]), "r"(b[1]));
}

__device__ __forceinline__ uint32_t f2tf32(float x) {
    uint32_t r;
    asm("cvt.rna.tf32.f32 %0, %1;" : "=r"(r) : "f"(x));
    return r;
}

__device__ __forceinline__ void mma_tf32(float* d, const uint32_t* a, const uint32_t* b) {
    asm volatile(
        "mma.sync.aligned.m16n8k8.row.col.f32.tf32.tf32.f32 "
        "{%0,%1,%2,%3}, {%4,%5,%6,%7}, {%8,%9}, {%0,%1,%2,%3};\n"
        : "+f"(d[0]), "+f"(d[1]), "+f"(d[2]), "+f"(d[3])
        : "r"(a[0]), "r"(a[1]), "r"(a[2]), "r"(a[3]), "r"(b[0]), "r"(b[1]));
}

// ---------------------------------------------------------------------------
// bf16 VQ score GEMM: dot(Z, E^T) via m16n8k16, score s = z2[m]+e2[n]-2*dot,
// reduced to per-(row, 32-code-chunk) min keys. Candidate-nomination only —
// exact fp32 rescoring follows in refine2_k, so bf16 error (~2.6e-5 RMS)
// only needs to stay << MARGIN (4e-4).
// Tile 128 rows x 64 codes, BK=16 (one k16 mma step per K-tile).
// ---------------------------------------------------------------------------
__global__ void __launch_bounds__(256) vq_bf16_k(
    const float* __restrict__ Z, const float* __restrict__ E,
    const float* __restrict__ e2, const float* __restrict__ z2,
    ull* __restrict__ chunkOut)
{
    __shared__ uint32_t Apk[8][136];   // k-pair x m (pad: conflict-free frag reads)
    __shared__ uint32_t Bpk[8][72];    // k-pair x n

    const int t = threadIdx.x;
    const int lane = t & 31;
    const int warp = t >> 5;
    const int warpM = warp & 3;
    const int warpN = warp >> 2;
    const int m0 = blockIdx.y * 128;
    const int n0 = blockIdx.x * 64;

    float acc[2][4][4];
#pragma unroll
    for (int mt = 0; mt < 2; mt++)
#pragma unroll
        for (int nt = 0; nt < 4; nt++)
#pragma unroll
            for (int c = 0; c < 4; c++) acc[mt][nt][c] = 0.f;

    const int aRow = t >> 2, aSeg = t & 3;   // also E loader: 64 codes x 4 segs

    for (int kb = 0; kb < 256; kb += 16) {
        // stage Z tile 128x16 as bf16 k-pairs
#pragma unroll
        for (int h = 0; h < 2; h++) {
            int row = aRow + h * 64;
            float4 v = *(const float4*)&Z[(size_t)(m0 + row) * 256 + kb + aSeg * 4];
            Apk[aSeg * 2 + 0][row] = packbf(v.x, v.y);
            Apk[aSeg * 2 + 1][row] = packbf(v.z, v.w);
        }
        // stage E tile 64 codes x 16 dims (row-major codebook, transposed gather)
        {
            float4 v = *(const float4*)&E[(size_t)(n0 + aRow) * 256 + kb + aSeg * 4];
            Bpk[aSeg * 2 + 0][aRow] = packbf(v.x, v.y);
            Bpk[aSeg * 2 + 1][aRow] = packbf(v.z, v.w);
        }
        __syncthreads();

        uint32_t a[2][4], b[4][2];
        const int ar = warpM * 32 + (lane >> 2);
        const int kq = lane & 3;
#pragma unroll
        for (int mt = 0; mt < 2; mt++) {
            a[mt][0] = Apk[kq][ar + mt * 16];
            a[mt][1] = Apk[kq][ar + mt * 16 + 8];
            a[mt][2] = Apk[4 + kq][ar + mt * 16];
            a[mt][3] = Apk[4 + kq][ar + mt * 16 + 8];
        }
#pragma unroll
        for (int nt = 0; nt < 4; nt++) {
            int nn = warpN * 32 + nt * 8 + (lane >> 2);
            b[nt][0] = Bpk[kq][nn];
            b[nt][1] = Bpk[4 + kq][nn];
        }
#pragma unroll
        for (int mt = 0; mt < 2; mt++)
#pragma unroll
            for (int nt = 0; nt < 4; nt++)
                mma_bf16(acc[mt][nt], a[mt], b[nt]);
        __syncthreads();
    }

    // chunk-min epilogue (scores + packed keys; first-index via ascending n)
    ull best[2][2] = {{~0ull, ~0ull}, {~0ull, ~0ull}};
#pragma unroll
    for (int mt = 0; mt < 2; mt++)
#pragma unroll
        for (int h = 0; h < 2; h++) {
            int m = m0 + warpM * 32 + mt * 16 + (lane >> 2) + h * 8;
            float z2m = z2[m];
#pragma unroll
            for (int nt = 0; nt < 4; nt++) {
                int n = n0 + warpN * 32 + nt * 8 + 2 * (lane & 3);
                float2 e2v = *(const float2*)&e2[n];
                float sx = __fadd_rn(__fadd_rn(z2m, e2v.x), -2.f * acc[mt][nt][h * 2 + 0]);
                float sy = __fadd_rn(__fadd_rn(z2m, e2v.y), -2.f * acc[mt][nt][h * 2 + 1]);
                ull kx = ((ull)__float_as_uint(sx) << 32) | (unsigned)n;
                ull ky = ((ull)__float_as_uint(sy) << 32) | (unsigned)(n + 1);
                if (kx < best[mt][h]) best[mt][h] = kx;
                if (ky < best[mt][h]) best[mt][h] = ky;
            }
        }
    const int chunk = blockIdx.x * 2 + warpN;
#pragma unroll
    for (int mt = 0; mt < 2; mt++)
#pragma unroll
        for (int h = 0; h < 2; h++) {
            ull k = best[mt][h];
            ull o = __shfl_xor_sync(0xFFFFFFFFu, k, 1); if (o < k) k = o;
            o = __shfl_xor_sync(0xFFFFFFFFu, k, 2); if (o < k) k = o;
            if ((lane & 3) == 0) {
                int m = m0 + warpM * 32 + mt * 16 + (lane >> 2) + h * 8;
                chunkOut[(size_t)m * NCHUNK + chunk] = k;
            }
        }
}

// ---------------------------------------------------------------------------
// Tensor-core GEMM (tf32, 1-pass) for decoders (frozen numerics since R9).
// EPI 0: bias; 2: Res + relu(.+bias). Tile 128x64, BK=16, 8 warps.
// Rows >= rowSplit go to C1 at (m - rowSplit).
// ---------------------------------------------------------------------------
template <int EPI>
__global__ void __launch_bounds__(256) gemm_tc(
    const float* __restrict__ A, const float* __restrict__ Bw,
    const float* __restrict__ bias, const float* __restrict__ Res,
    float* __restrict__ C0, float* __restrict__ C1, int rowSplit,
    int M, int N, int K)
{
    __shared__ float AsH[16][132];
    __shared__ float BsH[16][68];

    const int t = threadIdx.x;
    const int lane = t & 31;
    const int warp = t >> 5;
    const int warpM = warp & 3;
    const int warpN = warp >> 2;
    const int m0 = blockIdx.y * 128;
    const int n0 = blockIdx.x * 64;

    float acc[2][4][4];
#pragma unroll
    for (int mt = 0; mt < 2; mt++)
#pragma unroll
        for (int nt = 0; nt < 4; nt++)
#pragma unroll
            for (int c = 0; c < 4; c++) acc[mt][nt][c] = 0.f;

    const int aRow = t >> 2, aSeg = t & 3;
    const int bRow = t >> 4, bSeg = t & 15;

    for (int kb = 0; kb < K; kb += 16) {
#pragma unroll
        for (int h = 0; h < 2; h++) {
            int row = aRow + h * 64;
            float4 v = *(const float4*)&A[(size_t)(m0 + row) * K + kb + aSeg * 4];
            float x[4] = {v.x, v.y, v.z, v.w};
#pragma unroll
            for (int j = 0; j < 4; j++)
                AsH[aSeg * 4 + j][row] = __uint_as_float(f2tf32(x[j]));
        }
        {
            float4 v = *(const float4*)&Bw[(size_t)(kb + bRow) * N + n0 + bSeg * 4];
            float x[4] = {v.x, v.y, v.z, v.w};
#pragma unroll
            for (int j = 0; j < 4; j++)
                BsH[bRow][bSeg * 4 + j] = __uint_as_float(f2tf32(x[j]));
        }
        __syncthreads();

#pragma unroll
        for (int ks = 0; ks < 2; ks++) {
            uint32_t a[2][4], b[4][2];
            const int ar = warpM * 32 + (lane >> 2);
            const int ac = ks * 8 + (lane & 3);
#pragma unroll
            for (int mt = 0; mt < 2; mt++) {
                a[mt][0] = __float_as_uint(AsH[ac][ar + mt * 16]);
                a[mt][1] = __float_as_uint(AsH[ac][ar + mt * 16 + 8]);
                a[mt][2] = __float_as_uint(AsH[ac + 4][ar + mt * 16]);
                a[mt][3] = __float_as_uint(AsH[ac + 4][ar + mt * 16 + 8]);
            }
            const int bk = ks * 8 + (lane & 3);
#pragma unroll
            for (int nt = 0; nt < 4; nt++) {
                int nn = warpN * 32 + nt * 8 + (lane >> 2);
                b[nt][0] = __float_as_uint(BsH[bk][nn]);
                b[nt][1] = __float_as_uint(BsH[bk + 4][nn]);
            }
#pragma unroll
            for (int mt = 0; mt < 2; mt++)
#pragma unroll
                for (int nt = 0; nt < 4; nt++)
                    mma_tf32(acc[mt][nt], a[mt], b[nt]);
        }
        __syncthreads();
    }

#pragma unroll
    for (int mt = 0; mt < 2; mt++)
#pragma unroll
        for (int nt = 0; nt < 4; nt++) {
            int n = n0 + warpN * 32 + nt * 8 + 2 * (lane & 3);
            float2 bb = *(const float2*)&bias[n];
#pragma unroll
            for (int h = 0; h < 2; h++) {
                int m = m0 + warpM * 32 + mt * 16 + (lane >> 2) + h * 8;
                float vx = acc[mt][nt][h * 2 + 0] + bb.x;
                float vy = acc[mt][nt][h * 2 + 1] + bb.y;
                if constexpr (EPI >= 1) { vx = fmaxf(vx, 0.f); vy = fmaxf(vy, 0.f); }
                if constexpr (EPI == 2) {
                    float2 r = *(const float2*)&Res[(size_t)m * N + n];
                    vx += r.x; vy += r.y;
                }
                float* Cp; size_t mm;
                if (m < rowSplit) { Cp = C0; mm = (size_t)m; }
                else              { Cp = C1; mm = (size_t)(m - rowSplit); }
                float2 o = {vx, vy};
                *(float2*)&Cp[mm * (size_t)N + n] = o;
            }
        }
}

// ---------------------------------------------------------------------------
// Refine from chunk mins (exact fp32 rescoring, first-index tie-break)
// ---------------------------------------------------------------------------
#define MAXCHUNK 64

__global__ void __launch_bounds__(256) refine2_k(
    const ull* __restrict__ chunkmin, const float* __restrict__ Zall,
    const float* __restrict__ E, const float* __restrict__ z2,
    const float* __restrict__ e2, int* __restrict__ idxOut)
{
    __shared__ float zrow[256];
    __shared__ ull   wmin[8];
    __shared__ int   chunks[MAXCHUNK];
    __shared__ int   cnt;
    __shared__ float sthresh;
    __shared__ ull   wbest[8];

    const int m = blockIdx.x;
    const int t = threadIdx.x;
    const int warp = t >> 5, lane = t & 31;

    zrow[t] = Zall[(size_t)m * 256 + t];
    if (t == 0) cnt = 0;
    const ull ck = chunkmin[(size_t)m * NCHUNK + t];

    ull k = ck;
#pragma unroll
    for (int off = 16; off; off >>= 1) {
        ull o = __shfl_xor_sync(0xFFFFFFFFu, k, off);
        if (o < k) k = o;
    }
    if (lane == 0) wmin[warp] = k;
    __syncthreads();
    if (t < 8) {
        ull v = wmin[t];
#pragma unroll
        for (int off = 4; off; off >>= 1) {
            ull o = __shfl_xor_sync(0xFFu, v, off);
            if (o < v) v = o;
        }
        if (t == 0) sthresh = __uint_as_float((unsigned)(v >> 32)) + MARGIN;
    }
    __syncthreads();

    if (__uint_as_float((unsigned)(ck >> 32)) <= sthresh) {
        int p = atomicAdd(&cnt, 1);
        if (p < MAXCHUNK) chunks[p] = t;
    }
    __syncthreads();

    const int nc = cnt < MAXCHUNK ? cnt : MAXCHUNK;
    const float z2m = z2[m];
    ull best = ~0ull;
    for (int g = warp; g < nc * 32; g += 8) {
        int c = chunks[g >> 5] * 32 + (g & 31);
        const float* er = E + (size_t)c * 256;
        float dot = 0.f;
#pragma unroll
        for (int d = lane; d < 256; d += 32) dot += zrow[d] * er[d];
#pragma unroll
        for (int off = 16; off; off >>= 1)
            dot += __shfl_xor_sync(0xFFFFFFFFu, dot, off);
        if (lane == 0) {
            float s = __fadd_rn(__fadd_rn(z2m, e2[c]), -2.f * dot);
            ull key = ((ull)__float_as_uint(s) << 32) | (unsigned)c;
            if (key < best) best = key;
        }
    }
    if (lane == 0) wbest[warp] = best;
    __syncthreads();
    if (t < 8) {
        ull v = wbest[t];
#pragma unroll
        for (int off = 4; off; off >>= 1) {
            ull o = __shfl_xor_sync(0xFFu, v, off);
            if (o < v) v = o;
        }
        if (t == 0) idxOut[m] = (int)(v & 0xFFFFFFFFull);
    }
}

// ---------------------------------------------------------------------------
// Small kernels
// ---------------------------------------------------------------------------
__global__ void __launch_bounds__(256) e2_k(const float* __restrict__ E,
                                            float* __restrict__ e2)
{
    int w = threadIdx.x >> 5, lane = threadIdx.x & 31;
    int code = blockIdx.x * 8 + w;
    float s = 0.f;
#pragma unroll
    for (int d = lane; d < 256; d += 32) {
        float v = E[(size_t)code * 256 + d];
        s += v * v;
    }
#pragma unroll
    for (int off = 16; off; off >>= 1) s += __shfl_xor_sync(0xFFFFFFFFu, s, off);
    if (lane == 0) e2[code] = s;
}

__global__ void __launch_bounds__(256) z2_k(const float* __restrict__ Z,
                                            float* __restrict__ z2)
{
    int w = threadIdx.x >> 5, lane = threadIdx.x & 31;
    int row = blockIdx.x * 8 + w;
    const float* zr = Z + (size_t)row * 256;
    float s = 0.f;
#pragma unroll
    for (int d = lane; d < 256; d += 32) { float v = zr[d]; s += v * v; }
#pragma unroll
    for (int off = 16; off; off >>= 1) s += __shfl_xor_sync(0xFFFFFFFFu, s, off);
    if (lane == 0) z2[row] = s;
}

__global__ void __launch_bounds__(256) vq_apply_k(
    const float* __restrict__ Zall, const float* __restrict__ E,
    const int* __restrict__ idx, float* __restrict__ zOut,
    float* __restrict__ loss)
{
    __shared__ float red[8];
    int m = blockIdx.x, d = threadIdx.x;
    int k = idx[m];
    float z = Zall[(size_t)m * 256 + d];
    float q = E[(size_t)k * 256 + d];
    zOut[(size_t)m * 256 + d] = __fadd_rn(z, __fsub_rn(q, z));
    float diff = z - q;
    float ss = diff * diff;
#pragma unroll
    for (int off = 16; off; off >>= 1) ss += __shfl_xor_sync(0xFFFFFFFFu, ss, off);
    if ((d & 31) == 0) red[d >> 5] = ss;
    __syncthreads();
    if (d < 8) {
        float v = red[d];
#pragma unroll
        for (int off = 4; off; off >>= 1) v += __shfl_xor_sync(0xFFu, v, off);
        if (d == 0) loss[m] = v + 0.25f * v;
    }
}

// ---------------------------------------------------------------------------
// Host orchestration
// ---------------------------------------------------------------------------
extern "C" void kernel_launch(void* const* d_in, const int* in_sizes, int n_in,
                              void* d_out, int out_size)
{
    const float* x_a      = (const float*)d_in[0];
    const float* x_b      = (const float*)d_in[1];
    const float* enc_a_w  = (const float*)d_in[2];
    const float* enc_a_b  = (const float*)d_in[3];
    const float* enc_a_rw = (const float*)d_in[4];
    const float* enc_a_rb = (const float*)d_in[5];
    const float* enc_b_w  = (const float*)d_in[6];
    const float* enc_b_b  = (const float*)d_in[7];
    const float* enc_b_rw = (const float*)d_in[8];
    const float* enc_b_rb = (const float*)d_in[9];
    const float* dec_a_rw = (const float*)d_in[10];
    const float* dec_a_rb = (const float*)d_in[11];
    const float* dec_a_w  = (const float*)d_in[12];
    const float* dec_a_b  = (const float*)d_in[13];
    const float* dec_b_rw = (const float*)d_in[14];
    const float* dec_b_rb = (const float*)d_in[15];
    const float* dec_b_w  = (const float*)d_in[16];
    const float* dec_b_b  = (const float*)d_in[17];
    const float* codebook = (const float*)d_in[18];

    float* out = (float*)d_out;

    float *ze, *buf0, *buf1, *z2, *e2;
    int* idx;
    ull* chunk;
    cudaGetSymbolAddress((void**)&ze,    g_ze);
    cudaGetSymbolAddress((void**)&buf0,  g_buf0);
    cudaGetSymbolAddress((void**)&buf1,  g_buf1);
    cudaGetSymbolAddress((void**)&z2,    g_z2);
    cudaGetSymbolAddress((void**)&e2,    g_e2);
    cudaGetSymbolAddress((void**)&idx,   g_idx);
    cudaGetSymbolAddress((void**)&chunk, g_chunk);

    const size_t BD = (size_t)B_ * D_;
    const size_t OFF_ZA = 0;
    const size_t OFF_LA = 2ull * B_ * D_;
    const size_t OFF_RA = OFF_LA + 2ull * B_;
    const size_t OFF_RB = OFF_RA + (size_t)B_ * 4096;
    const size_t OFF_XA = OFF_RB + (size_t)B_ * 2048;
    const size_t OFF_XB = OFF_XA + (size_t)B_ * 4096;

    const dim3 blk(256);
    const int BIG = 1 << 30;
    float* zeB = ze + BD;

    e2_k<<<KCODES / 8, blk>>>(codebook, e2);

    // --- Encoders: fp32 bit-identical chain, A+B merged per stage ---
    // projections (K=4096 / 2048), tile 128x64, 512 blocks total
    gemm2m_k<1><<<dim3(4, 64, 2), blk>>>(
        x_a, x_b, enc_a_w, enc_b_w, enc_a_b, enc_b_b,
        nullptr, nullptr, buf0, buf0 + BD, B_, 256, 4096, 2048);
    // residual block 1 (merged)
    gemm2m_k<2><<<dim3(4, 64, 2), blk>>>(
        buf0, buf0 + BD, enc_a_rw, enc_b_rw, enc_a_rb, enc_b_rb,
        buf0, buf0 + BD, buf1, buf1 + BD, B_, 256, 256, 256);
    // residual block 2 (merged)
    gemm2m_k<2><<<dim3(4, 64, 2), blk>>>(
        buf1, buf1 + BD, enc_a_rw + 65536, enc_b_rw + 65536,
        enc_a_rb + 256, enc_b_rb + 256,
        buf1, buf1 + BD, ze, zeB, B_, 256, 256, 256);

    // --- VQ: bf16 approx scores -> chunk-min keys -> exact fp32 refine ---
    z2_k<<<2 * B_ / 8, blk>>>(ze, z2);
    vq_bf16_k<<<dim3(KCODES / 64, 2 * B_ / 128), blk>>>(ze, codebook, e2, z2, chunk);
    refine2_k<<<2 * B_, blk>>>(chunk, ze, codebook, z2, e2, idx);
    vq_apply_k<<<2 * B_, blk>>>(ze, codebook, idx, out + OFF_ZA, out + OFF_LA);

    // --- Decoders: batched [z_a; z_b] (M=16384), 1-pass tf32 (frozen) ---
    gemm_tc<2><<<dim3(4, 128), blk>>>(out, dec_a_rw, dec_a_rb, out,
                                      buf0, buf0, BIG, 2 * B_, 256, 256);
    gemm_tc<2><<<dim3(4, 128), blk>>>(buf0, dec_a_rw + 65536, dec_a_rb + 256, buf0,
                                      buf1, buf1, BIG, 2 * B_, 256, 256);
    gemm_tc<0><<<dim3(64, 128), blk>>>(buf1, dec_a_w, dec_a_b, nullptr,
                                       out + OFF_RA, out + OFF_XA, B_,
                                       2 * B_, 4096, 256);

    gemm_tc<2><<<dim3(4, 128), blk>>>(out, dec_b_rw, dec_b_rb, out,
                                      buf0, buf0, BIG, 2 * B_, 256, 256);
    gemm_tc<2><<<dim3(4, 128), blk>>>(buf0, dec_b_rw + 65536, dec_b_rb + 256, buf0,
                                      buf1, buf1, BIG, 2 * B_, 256, 256);
    gemm_tc<0><<<dim3(32, 128), blk>>>(buf1, dec_b_w, dec_b_b, nullptr,
                                       out + OFF_XB, out + OFF_RB, B_,
                                       2 * B_, 2048, 256);
}

// round 13
// speedup vs baseline: 2.5755x; 1.1024x over previous
#include <cuda_runtime.h>
#include <stdint.h>

#define B_ 8192
#define D_ 256
#define KCODES 8192
#define NCHUNK (KCODES / 32)     // 256 chunk keys per row
#define MARGIN 4e-4f

typedef unsigned long long ull;

// Scratch (device globals; no allocation allowed)
__device__ float g_ze[2 * B_ * D_];       // [zeA; zeB]
__device__ float g_buf0[2 * B_ * D_];
__device__ float g_buf1[2 * B_ * D_];
__device__ float g_buf2[2 * B_ * D_];
__device__ float g_buf3[2 * B_ * D_];
__device__ float g_z2[2 * B_];
__device__ float g_e2[KCODES];
__device__ int   g_idx[2 * B_];
__device__ ull   g_chunk[(size_t)2 * B_ * NCHUNK];   // 32 MB chunk-min keys

// ---------------------------------------------------------------------------
// Merged dual-problem fp32 SIMT GEMM (bit-identical accumulation chain).
// Tile 128x64, BK=16, 8x4 micro-tile. blockIdx.z selects problem {0,1}.
// EPI 1: relu(.+bias); 2: Res + relu(.+bias)
// ---------------------------------------------------------------------------
template <int EPI>
__global__ void __launch_bounds__(256) gemm2m_k(
    const float* __restrict__ A0, const float* __restrict__ A1,
    const float* __restrict__ W0, const float* __restrict__ W1,
    const float* __restrict__ bias0, const float* __restrict__ bias1,
    const float* __restrict__ Res0, const float* __restrict__ Res1,
    float* __restrict__ C0, float* __restrict__ C1,
    int M, int N, int K0, int K1)
{
    const float* A    = blockIdx.z ? A1 : A0;
    const float* Bm   = blockIdx.z ? W1 : W0;
    const float* bias = blockIdx.z ? bias1 : bias0;
    const float* Res  = blockIdx.z ? Res1 : Res0;
    float* C          = blockIdx.z ? C1 : C0;
    const int K       = blockIdx.z ? K1 : K0;

    __shared__ float As[16][132];
    __shared__ float Bs[16][64];

    const int t  = threadIdx.x;
    const int ty = t >> 4;
    const int tx = t & 15;
    const int m0 = blockIdx.y * 128;
    const int n0 = blockIdx.x * 64;

    const int brow = t >> 4, bseg = t & 15;

    float acc[8][4];
#pragma unroll
    for (int i = 0; i < 8; i++)
#pragma unroll
        for (int j = 0; j < 4; j++) acc[i][j] = 0.f;

    for (int kb = 0; kb < K; kb += 16) {
#pragma unroll
        for (int i = 0; i < 2; i++) {
            int f = t + i * 256;
            int row = f >> 2, seg = f & 3;
            float4 v = *(const float4*)&A[(size_t)(m0 + row) * K + kb + seg * 4];
            As[seg * 4 + 0][row] = v.x;
            As[seg * 4 + 1][row] = v.y;
            As[seg * 4 + 2][row] = v.z;
            As[seg * 4 + 3][row] = v.w;
        }
        {
            float4 v = *(const float4*)&Bm[(size_t)(kb + brow) * N + n0 + bseg * 4];
            *(float4*)&Bs[brow][bseg * 4] = v;
        }
        __syncthreads();
#pragma unroll
        for (int kk = 0; kk < 16; kk++) {
            float4 a0 = *(const float4*)&As[kk][ty * 8];
            float4 a1 = *(const float4*)&As[kk][ty * 8 + 4];
            float4 b4 = *(const float4*)&Bs[kk][tx * 4];
            float a[8] = {a0.x, a0.y, a0.z, a0.w, a1.x, a1.y, a1.z, a1.w};
            float b[4] = {b4.x, b4.y, b4.z, b4.w};
#pragma unroll
            for (int i = 0; i < 8; i++)
#pragma unroll
                for (int j = 0; j < 4; j++) acc[i][j] += a[i] * b[j];
        }
        __syncthreads();
    }

    float4 bb = *(const float4*)&bias[n0 + tx * 4];
    float bcol[4] = {bb.x, bb.y, bb.z, bb.w};
#pragma unroll
    for (int i = 0; i < 8; i++) {
        int m = m0 + ty * 8 + i;
        float v[4];
#pragma unroll
        for (int j = 0; j < 4; j++) {
            v[j] = acc[i][j] + bcol[j];
            if (EPI >= 1) v[j] = fmaxf(v[j], 0.f);
        }
        if (EPI == 2) {
            float4 r = *(const float4*)&Res[(size_t)m * N + n0 + tx * 4];
            v[0] += r.x; v[1] += r.y; v[2] += r.z; v[3] += r.w;
        }
        float4 o = {v[0], v[1], v[2], v[3]};
        *(float4*)&C[(size_t)m * N + n0 + tx * 4] = o;
    }
}

// ---------------------------------------------------------------------------
// bf16 / tf32 helpers
// ---------------------------------------------------------------------------
__device__ __forceinline__ uint32_t packbf(float lo, float hi) {
    uint32_t r;
    asm("cvt.rn.bf16x2.f32 %0, %1, %2;" : "=r"(r) : "f"(hi), "f"(lo));
    return r;
}

__device__ __forceinline__ void mma_bf16(float* d, const uint32_t* a, const uint32_t* b) {
    asm volatile(
        "mma.sync.aligned.m16n8k16.row.col.f32.bf16.bf16.f32 "
        "{%0,%1,%2,%3}, {%4,%5,%6,%7}, {%8,%9}, {%0,%1,%2,%3};\n"
        : "+f"(d[0]), "+f"(d[1]), "+f"(d[2]), "+f"(d[3])
        : "r"(a[0]), "r"(a[1]), "r"(a[2]), "r"(a[3]), "r"(b[0]), "r"(b[1]));
}

__device__ __forceinline__ uint32_t f2tf32(float x) {
    uint32_t r;
    asm("cvt.rna.tf32.f32 %0, %1;" : "=r"(r) : "f"(x));
    return r;
}

__device__ __forceinline__ void mma_tf32(float* d, const uint32_t* a, const uint32_t* b) {
    asm volatile(
        "mma.sync.aligned.m16n8k8.row.col.f32.tf32.tf32.f32 "
        "{%0,%1,%2,%3}, {%4,%5,%6,%7}, {%8,%9}, {%0,%1,%2,%3};\n"
        : "+f"(d[0]), "+f"(d[1]), "+f"(d[2]), "+f"(d[3])
        : "r"(a[0]), "r"(a[1]), "r"(a[2]), "r"(a[3]), "r"(b[0]), "r"(b[1]));
}

// ---------------------------------------------------------------------------
// bf16 VQ score GEMM (candidate nomination; exact rescoring follows)
// ---------------------------------------------------------------------------
__global__ void __launch_bounds__(256) vq_bf16_k(
    const float* __restrict__ Z, const float* __restrict__ E,
    const float* __restrict__ e2, const float* __restrict__ z2,
    ull* __restrict__ chunkOut)
{
    __shared__ uint32_t Apk[8][136];
    __shared__ uint32_t Bpk[8][72];

    const int t = threadIdx.x;
    const int lane = t & 31;
    const int warp = t >> 5;
    const int warpM = warp & 3;
    const int warpN = warp >> 2;
    const int m0 = blockIdx.y * 128;
    const int n0 = blockIdx.x * 64;

    float acc[2][4][4];
#pragma unroll
    for (int mt = 0; mt < 2; mt++)
#pragma unroll
        for (int nt = 0; nt < 4; nt++)
#pragma unroll
            for (int c = 0; c < 4; c++) acc[mt][nt][c] = 0.f;

    const int aRow = t >> 2, aSeg = t & 3;

    for (int kb = 0; kb < 256; kb += 16) {
#pragma unroll
        for (int h = 0; h < 2; h++) {
            int row = aRow + h * 64;
            float4 v = *(const float4*)&Z[(size_t)(m0 + row) * 256 + kb + aSeg * 4];
            Apk[aSeg * 2 + 0][row] = packbf(v.x, v.y);
            Apk[aSeg * 2 + 1][row] = packbf(v.z, v.w);
        }
        {
            float4 v = *(const float4*)&E[(size_t)(n0 + aRow) * 256 + kb + aSeg * 4];
            Bpk[aSeg * 2 + 0][aRow] = packbf(v.x, v.y);
            Bpk[aSeg * 2 + 1][aRow] = packbf(v.z, v.w);
        }
        __syncthreads();

        uint32_t a[2][4], b[4][2];
        const int ar = warpM * 32 + (lane >> 2);
        const int kq = lane & 3;
#pragma unroll
        for (int mt = 0; mt < 2; mt++) {
            a[mt][0] = Apk[kq][ar + mt * 16];
            a[mt][1] = Apk[kq][ar + mt * 16 + 8];
            a[mt][2] = Apk[4 + kq][ar + mt * 16];
            a[mt][3] = Apk[4 + kq][ar + mt * 16 + 8];
        }
#pragma unroll
        for (int nt = 0; nt < 4; nt++) {
            int nn = warpN * 32 + nt * 8 + (lane >> 2);
            b[nt][0] = Bpk[kq][nn];
            b[nt][1] = Bpk[4 + kq][nn];
        }
#pragma unroll
        for (int mt = 0; mt < 2; mt++)
#pragma unroll
            for (int nt = 0; nt < 4; nt++)
                mma_bf16(acc[mt][nt], a[mt], b[nt]);
        __syncthreads();
    }

    ull best[2][2] = {{~0ull, ~0ull}, {~0ull, ~0ull}};
#pragma unroll
    for (int mt = 0; mt < 2; mt++)
#pragma unroll
        for (int h = 0; h < 2; h++) {
            int m = m0 + warpM * 32 + mt * 16 + (lane >> 2) + h * 8;
            float z2m = z2[m];
#pragma unroll
            for (int nt = 0; nt < 4; nt++) {
                int n = n0 + warpN * 32 + nt * 8 + 2 * (lane & 3);
                float2 e2v = *(const float2*)&e2[n];
                float sx = __fadd_rn(__fadd_rn(z2m, e2v.x), -2.f * acc[mt][nt][h * 2 + 0]);
                float sy = __fadd_rn(__fadd_rn(z2m, e2v.y), -2.f * acc[mt][nt][h * 2 + 1]);
                ull kx = ((ull)__float_as_uint(sx) << 32) | (unsigned)n;
                ull ky = ((ull)__float_as_uint(sy) << 32) | (unsigned)(n + 1);
                if (kx < best[mt][h]) best[mt][h] = kx;
                if (ky < best[mt][h]) best[mt][h] = ky;
            }
        }
    const int chunk = blockIdx.x * 2 + warpN;
#pragma unroll
    for (int mt = 0; mt < 2; mt++)
#pragma unroll
        for (int h = 0; h < 2; h++) {
            ull k = best[mt][h];
            ull o = __shfl_xor_sync(0xFFFFFFFFu, k, 1); if (o < k) k = o;
            o = __shfl_xor_sync(0xFFFFFFFFu, k, 2); if (o < k) k = o;
            if ((lane & 3) == 0) {
                int m = m0 + warpM * 32 + mt * 16 + (lane >> 2) + h * 8;
                chunkOut[(size_t)m * NCHUNK + chunk] = k;
            }
        }
}

// ---------------------------------------------------------------------------
// Merged dual-problem tf32 resblock GEMM (decoder res blocks; both problems
// read the same A/Res). Tile 128x64, BK=16, blockIdx.z selects weights/output.
// C = Res + relu(A @ W + bias)
// ---------------------------------------------------------------------------
__global__ void __launch_bounds__(256) gemm_tcm(
    const float* __restrict__ A, const float* __restrict__ W0,
    const float* __restrict__ W1, const float* __restrict__ bias0,
    const float* __restrict__ bias1, const float* __restrict__ Res,
    float* __restrict__ C0, float* __restrict__ C1,
    const float* __restrict__ A1in, const float* __restrict__ Res1in,
    int M, int N, int K)
{
    const float* Ap   = blockIdx.z ? (A1in ? A1in : A) : A;
    const float* Bw   = blockIdx.z ? W1 : W0;
    const float* bias = blockIdx.z ? bias1 : bias0;
    const float* Res_ = blockIdx.z ? (Res1in ? Res1in : Res) : Res;
    float* C          = blockIdx.z ? C1 : C0;

    __shared__ float AsH[16][132];
    __shared__ float BsH[16][68];

    const int t = threadIdx.x;
    const int lane = t & 31;
    const int warp = t >> 5;
    const int warpM = warp & 3;
    const int warpN = warp >> 2;
    const int m0 = blockIdx.y * 128;
    const int n0 = blockIdx.x * 64;

    float acc[2][4][4];
#pragma unroll
    for (int mt = 0; mt < 2; mt++)
#pragma unroll
        for (int nt = 0; nt < 4; nt++)
#pragma unroll
            for (int c = 0; c < 4; c++) acc[mt][nt][c] = 0.f;

    const int aRow = t >> 2, aSeg = t & 3;
    const int bRow = t >> 4, bSeg = t & 15;

    for (int kb = 0; kb < K; kb += 16) {
#pragma unroll
        for (int h = 0; h < 2; h++) {
            int row = aRow + h * 64;
            float4 v = *(const float4*)&Ap[(size_t)(m0 + row) * K + kb + aSeg * 4];
            AsH[aSeg * 4 + 0][row] = __uint_as_float(f2tf32(v.x));
            AsH[aSeg * 4 + 1][row] = __uint_as_float(f2tf32(v.y));
            AsH[aSeg * 4 + 2][row] = __uint_as_float(f2tf32(v.z));
            AsH[aSeg * 4 + 3][row] = __uint_as_float(f2tf32(v.w));
        }
        {
            float4 v = *(const float4*)&Bw[(size_t)(kb + bRow) * N + n0 + bSeg * 4];
            BsH[bRow][bSeg * 4 + 0] = __uint_as_float(f2tf32(v.x));
            BsH[bRow][bSeg * 4 + 1] = __uint_as_float(f2tf32(v.y));
            BsH[bRow][bSeg * 4 + 2] = __uint_as_float(f2tf32(v.z));
            BsH[bRow][bSeg * 4 + 3] = __uint_as_float(f2tf32(v.w));
        }
        __syncthreads();

#pragma unroll
        for (int ks = 0; ks < 2; ks++) {
            uint32_t a[2][4], b[4][2];
            const int ar = warpM * 32 + (lane >> 2);
            const int ac = ks * 8 + (lane & 3);
#pragma unroll
            for (int mt = 0; mt < 2; mt++) {
                a[mt][0] = __float_as_uint(AsH[ac][ar + mt * 16]);
                a[mt][1] = __float_as_uint(AsH[ac][ar + mt * 16 + 8]);
                a[mt][2] = __float_as_uint(AsH[ac + 4][ar + mt * 16]);
                a[mt][3] = __float_as_uint(AsH[ac + 4][ar + mt * 16 + 8]);
            }
            const int bk = ks * 8 + (lane & 3);
#pragma unroll
            for (int nt = 0; nt < 4; nt++) {
                int nn = warpN * 32 + nt * 8 + (lane >> 2);
                b[nt][0] = __float_as_uint(BsH[bk][nn]);
                b[nt][1] = __float_as_uint(BsH[bk + 4][nn]);
            }
#pragma unroll
            for (int mt = 0; mt < 2; mt++)
#pragma unroll
                for (int nt = 0; nt < 4; nt++)
                    mma_tf32(acc[mt][nt], a[mt], b[nt]);
        }
        __syncthreads();
    }

#pragma unroll
    for (int mt = 0; mt < 2; mt++)
#pragma unroll
        for (int nt = 0; nt < 4; nt++) {
            int n = n0 + warpN * 32 + nt * 8 + 2 * (lane & 3);
            float2 bb = *(const float2*)&bias[n];
#pragma unroll
            for (int h = 0; h < 2; h++) {
                int m = m0 + warpM * 32 + mt * 16 + (lane >> 2) + h * 8;
                float vx = fmaxf(acc[mt][nt][h * 2 + 0] + bb.x, 0.f);
                float vy = fmaxf(acc[mt][nt][h * 2 + 1] + bb.y, 0.f);
                float2 r = *(const float2*)&Res_[(size_t)m * N + n];
                vx += r.x; vy += r.y;
                float2 o = {vx, vy};
                *(float2*)&C[(size_t)m * N + n] = o;
            }
        }
}

// ---------------------------------------------------------------------------
// tf32 GEMM, 128x128 tile, double-buffered smem + register prefetch.
// Used for the decoder final projections (bias only). 8 warps = 2(M) x 4(N),
// warp tile 64x32 = 4x4 m16n8k8 tiles. Rows >= rowSplit -> C1 at m-rowSplit.
// ---------------------------------------------------------------------------
__global__ void __launch_bounds__(256) gemm_tc2(
    const float* __restrict__ A, const float* __restrict__ Bw,
    const float* __restrict__ bias,
    float* __restrict__ C0, float* __restrict__ C1, int rowSplit,
    int M, int N, int K)
{
    __shared__ float As[2][16][132];
    __shared__ float Bs[2][16][132];

    const int t = threadIdx.x;
    const int lane = t & 31;
    const int warp = t >> 5;
    const int warpM = warp & 1;      // 2 along M
    const int warpN = warp >> 1;     // 4 along N
    const int m0 = blockIdx.y * 128;
    const int n0 = blockIdx.x * 128;

    const int ar0 = t >> 2,         as0 = t & 3;
    const int ar1 = (t + 256) >> 2, as1 = (t + 256) & 3;
    const int br0 = t >> 5,         bs0 = t & 31;
    const int br1 = (t + 256) >> 5, bs1 = (t + 256) & 31;

    float acc[4][4][4];
#pragma unroll
    for (int mt = 0; mt < 4; mt++)
#pragma unroll
        for (int nt = 0; nt < 4; nt++)
#pragma unroll
            for (int c = 0; c < 4; c++) acc[mt][nt][c] = 0.f;

    // preload kb=0 into buffer 0 (convert to tf32 at store)
    {
        float4 a0 = *(const float4*)&A[(size_t)(m0 + ar0) * K + as0 * 4];
        float4 a1 = *(const float4*)&A[(size_t)(m0 + ar1) * K + as1 * 4];
        float4 b0 = *(const float4*)&Bw[(size_t)br0 * N + n0 + bs0 * 4];
        float4 b1 = *(const float4*)&Bw[(size_t)br1 * N + n0 + bs1 * 4];
        As[0][as0 * 4 + 0][ar0] = __uint_as_float(f2tf32(a0.x));
        As[0][as0 * 4 + 1][ar0] = __uint_as_float(f2tf32(a0.y));
        As[0][as0 * 4 + 2][ar0] = __uint_as_float(f2tf32(a0.z));
        As[0][as0 * 4 + 3][ar0] = __uint_as_float(f2tf32(a0.w));
        As[0][as1 * 4 + 0][ar1] = __uint_as_float(f2tf32(a1.x));
        As[0][as1 * 4 + 1][ar1] = __uint_as_float(f2tf32(a1.y));
        As[0][as1 * 4 + 2][ar1] = __uint_as_float(f2tf32(a1.z));
        As[0][as1 * 4 + 3][ar1] = __uint_as_float(f2tf32(a1.w));
        Bs[0][br0][bs0 * 4 + 0] = __uint_as_float(f2tf32(b0.x));
        Bs[0][br0][bs0 * 4 + 1] = __uint_as_float(f2tf32(b0.y));
        Bs[0][br0][bs0 * 4 + 2] = __uint_as_float(f2tf32(b0.z));
        Bs[0][br0][bs0 * 4 + 3] = __uint_as_float(f2tf32(b0.w));
        Bs[0][br1][bs1 * 4 + 0] = __uint_as_float(f2tf32(b1.x));
        Bs[0][br1][bs1 * 4 + 1] = __uint_as_float(f2tf32(b1.y));
        Bs[0][br1][bs1 * 4 + 2] = __uint_as_float(f2tf32(b1.z));
        Bs[0][br1][bs1 * 4 + 3] = __uint_as_float(f2tf32(b1.w));
    }
    __syncthreads();

    int p = 0;
    for (int kb = 16; kb <= K; kb += 16) {
        float4 a0, a1, b0, b1;
        const bool more = (kb < K);
        if (more) {
            a0 = *(const float4*)&A[(size_t)(m0 + ar0) * K + kb + as0 * 4];
            a1 = *(const float4*)&A[(size_t)(m0 + ar1) * K + kb + as1 * 4];
            b0 = *(const float4*)&Bw[(size_t)(kb + br0) * N + n0 + bs0 * 4];
            b1 = *(const float4*)&Bw[(size_t)(kb + br1) * N + n0 + bs1 * 4];
        }

#pragma unroll
        for (int ks = 0; ks < 2; ks++) {
            uint32_t a[4][4], b[4][2];
            const int ar = warpM * 64 + (lane >> 2);
            const int ac = ks * 8 + (lane & 3);
#pragma unroll
            for (int mt = 0; mt < 4; mt++) {
                a[mt][0] = __float_as_uint(As[p][ac][ar + mt * 16]);
                a[mt][1] = __float_as_uint(As[p][ac][ar + mt * 16 + 8]);
                a[mt][2] = __float_as_uint(As[p][ac + 4][ar + mt * 16]);
                a[mt][3] = __float_as_uint(As[p][ac + 4][ar + mt * 16 + 8]);
            }
            const int bk = ks * 8 + (lane & 3);
#pragma unroll
            for (int nt = 0; nt < 4; nt++) {
                int nn = warpN * 32 + nt * 8 + (lane >> 2);
                b[nt][0] = __float_as_uint(Bs[p][bk][nn]);
                b[nt][1] = __float_as_uint(Bs[p][bk + 4][nn]);
            }
#pragma unroll
            for (int mt = 0; mt < 4; mt++)
#pragma unroll
                for (int nt = 0; nt < 4; nt++)
                    mma_tf32(acc[mt][nt], a[mt], b[nt]);
        }

        if (more) {
            int q = p ^ 1;
            As[q][as0 * 4 + 0][ar0] = __uint_as_float(f2tf32(a0.x));
            As[q][as0 * 4 + 1][ar0] = __uint_as_float(f2tf32(a0.y));
            As[q][as0 * 4 + 2][ar0] = __uint_as_float(f2tf32(a0.z));
            As[q][as0 * 4 + 3][ar0] = __uint_as_float(f2tf32(a0.w));
            As[q][as1 * 4 + 0][ar1] = __uint_as_float(f2tf32(a1.x));
            As[q][as1 * 4 + 1][ar1] = __uint_as_float(f2tf32(a1.y));
            As[q][as1 * 4 + 2][ar1] = __uint_as_float(f2tf32(a1.z));
            As[q][as1 * 4 + 3][ar1] = __uint_as_float(f2tf32(a1.w));
            Bs[q][br0][bs0 * 4 + 0] = __uint_as_float(f2tf32(b0.x));
            Bs[q][br0][bs0 * 4 + 1] = __uint_as_float(f2tf32(b0.y));
            Bs[q][br0][bs0 * 4 + 2] = __uint_as_float(f2tf32(b0.z));
            Bs[q][br0][bs0 * 4 + 3] = __uint_as_float(f2tf32(b0.w));
            Bs[q][br1][bs1 * 4 + 0] = __uint_as_float(f2tf32(b1.x));
            Bs[q][br1][bs1 * 4 + 1] = __uint_as_float(f2tf32(b1.y));
            Bs[q][br1][bs1 * 4 + 2] = __uint_as_float(f2tf32(b1.z));
            Bs[q][br1][bs1 * 4 + 3] = __uint_as_float(f2tf32(b1.w));
            __syncthreads();
            p = q;
        }
    }

    // epilogue: bias only, split output
#pragma unroll
    for (int mt = 0; mt < 4; mt++)
#pragma unroll
        for (int nt = 0; nt < 4; nt++) {
            int n = n0 + warpN * 32 + nt * 8 + 2 * (lane & 3);
            float2 bb = *(const float2*)&bias[n];
#pragma unroll
            for (int h = 0; h < 2; h++) {
                int m = m0 + warpM * 64 + mt * 16 + (lane >> 2) + h * 8;
                float vx = acc[mt][nt][h * 2 + 0] + bb.x;
                float vy = acc[mt][nt][h * 2 + 1] + bb.y;
                float* Cp; size_t mm;
                if (m < rowSplit) { Cp = C0; mm = (size_t)m; }
                else              { Cp = C1; mm = (size_t)(m - rowSplit); }
                float2 o = {vx, vy};
                *(float2*)&Cp[mm * (size_t)N + n] = o;
            }
        }
}

// ---------------------------------------------------------------------------
// Refine from chunk mins (exact fp32 rescoring, first-index tie-break)
// ---------------------------------------------------------------------------
#define MAXCHUNK 64

__global__ void __launch_bounds__(256) refine2_k(
    const ull* __restrict__ chunkmin, const float* __restrict__ Zall,
    const float* __restrict__ E, const float* __restrict__ z2,
    const float* __restrict__ e2, int* __restrict__ idxOut)
{
    __shared__ float zrow[256];
    __shared__ ull   wmin[8];
    __shared__ int   chunks[MAXCHUNK];
    __shared__ int   cnt;
    __shared__ float sthresh;
    __shared__ ull   wbest[8];

    const int m = blockIdx.x;
    const int t = threadIdx.x;
    const int warp = t >> 5, lane = t & 31;

    zrow[t] = Zall[(size_t)m * 256 + t];
    if (t == 0) cnt = 0;
    const ull ck = chunkmin[(size_t)m * NCHUNK + t];

    ull k = ck;
#pragma unroll
    for (int off = 16; off; off >>= 1) {
        ull o = __shfl_xor_sync(0xFFFFFFFFu, k, off);
        if (o < k) k = o;
    }
    if (lane == 0) wmin[warp] = k;
    __syncthreads();
    if (t < 8) {
        ull v = wmin[t];
#pragma unroll
        for (int off = 4; off; off >>= 1) {
            ull o = __shfl_xor_sync(0xFFu, v, off);
            if (o < v) v = o;
        }
        if (t == 0) sthresh = __uint_as_float((unsigned)(v >> 32)) + MARGIN;
    }
    __syncthreads();

    if (__uint_as_float((unsigned)(ck >> 32)) <= sthresh) {
        int p = atomicAdd(&cnt, 1);
        if (p < MAXCHUNK) chunks[p] = t;
    }
    __syncthreads();

    const int nc = cnt < MAXCHUNK ? cnt : MAXCHUNK;
    const float z2m = z2[m];
    ull best = ~0ull;
    for (int g = warp; g < nc * 32; g += 8) {
        int c = chunks[g >> 5] * 32 + (g & 31);
        const float* er = E + (size_t)c * 256;
        float dot = 0.f;
#pragma unroll
        for (int d = lane; d < 256; d += 32) dot += zrow[d] * er[d];
#pragma unroll
        for (int off = 16; off; off >>= 1)
            dot += __shfl_xor_sync(0xFFFFFFFFu, dot, off);
        if (lane == 0) {
            float s = __fadd_rn(__fadd_rn(z2m, e2[c]), -2.f * dot);
            ull key = ((ull)__float_as_uint(s) << 32) | (unsigned)c;
            if (key < best) best = key;
        }
    }
    if (lane == 0) wbest[warp] = best;
    __syncthreads();
    if (t < 8) {
        ull v = wbest[t];
#pragma unroll
        for (int off = 4; off; off >>= 1) {
            ull o = __shfl_xor_sync(0xFFu, v, off);
            if (o < v) v = o;
        }
        if (t == 0) idxOut[m] = (int)(v & 0xFFFFFFFFull);
    }
}

// ---------------------------------------------------------------------------
// Small kernels
// ---------------------------------------------------------------------------
__global__ void __launch_bounds__(256) e2_k(const float* __restrict__ E,
                                            float* __restrict__ e2)
{
    int w = threadIdx.x >> 5, lane = threadIdx.x & 31;
    int code = blockIdx.x * 8 + w;
    float s = 0.f;
#pragma unroll
    for (int d = lane; d < 256; d += 32) {
        float v = E[(size_t)code * 256 + d];
        s += v * v;
    }
#pragma unroll
    for (int off = 16; off; off >>= 1) s += __shfl_xor_sync(0xFFFFFFFFu, s, off);
    if (lane == 0) e2[code] = s;
}

__global__ void __launch_bounds__(256) z2_k(const float* __restrict__ Z,
                                            float* __restrict__ z2)
{
    int w = threadIdx.x >> 5, lane = threadIdx.x & 31;
    int row = blockIdx.x * 8 + w;
    const float* zr = Z + (size_t)row * 256;
    float s = 0.f;
#pragma unroll
    for (int d = lane; d < 256; d += 32) { float v = zr[d]; s += v * v; }
#pragma unroll
    for (int off = 16; off; off >>= 1) s += __shfl_xor_sync(0xFFFFFFFFu, s, off);
    if (lane == 0) z2[row] = s;
}

__global__ void __launch_bounds__(256) vq_apply_k(
    const float* __restrict__ Zall, const float* __restrict__ E,
    const int* __restrict__ idx, float* __restrict__ zOut,
    float* __restrict__ loss)
{
    __shared__ float red[8];
    int m = blockIdx.x, d = threadIdx.x;
    int k = idx[m];
    float z = Zall[(size_t)m * 256 + d];
    float q = E[(size_t)k * 256 + d];
    zOut[(size_t)m * 256 + d] = __fadd_rn(z, __fsub_rn(q, z));
    float diff = z - q;
    float ss = diff * diff;
#pragma unroll
    for (int off = 16; off; off >>= 1) ss += __shfl_xor_sync(0xFFFFFFFFu, ss, off);
    if ((d & 31) == 0) red[d >> 5] = ss;
    __syncthreads();
    if (d < 8) {
        float v = red[d];
#pragma unroll
        for (int off = 4; off; off >>= 1) v += __shfl_xor_sync(0xFFu, v, off);
        if (d == 0) loss[m] = v + 0.25f * v;
    }
}

// ---------------------------------------------------------------------------
// Host orchestration
// ---------------------------------------------------------------------------
extern "C" void kernel_launch(void* const* d_in, const int* in_sizes, int n_in,
                              void* d_out, int out_size)
{
    const float* x_a      = (const float*)d_in[0];
    const float* x_b      = (const float*)d_in[1];
    const float* enc_a_w  = (const float*)d_in[2];
    const float* enc_a_b  = (const float*)d_in[3];
    const float* enc_a_rw = (const float*)d_in[4];
    const float* enc_a_rb = (const float*)d_in[5];
    const float* enc_b_w  = (const float*)d_in[6];
    const float* enc_b_b  = (const float*)d_in[7];
    const float* enc_b_rw = (const float*)d_in[8];
    const float* enc_b_rb = (const float*)d_in[9];
    const float* dec_a_rw = (const float*)d_in[10];
    const float* dec_a_rb = (const float*)d_in[11];
    const float* dec_a_w  = (const float*)d_in[12];
    const float* dec_a_b  = (const float*)d_in[13];
    const float* dec_b_rw = (const float*)d_in[14];
    const float* dec_b_rb = (const float*)d_in[15];
    const float* dec_b_w  = (const float*)d_in[16];
    const float* dec_b_b  = (const float*)d_in[17];
    const float* codebook = (const float*)d_in[18];

    float* out = (float*)d_out;

    float *ze, *buf0, *buf1, *buf2, *buf3, *z2, *e2;
    int* idx;
    ull* chunk;
    cudaGetSymbolAddress((void**)&ze,    g_ze);
    cudaGetSymbolAddress((void**)&buf0,  g_buf0);
    cudaGetSymbolAddress((void**)&buf1,  g_buf1);
    cudaGetSymbolAddress((void**)&buf2,  g_buf2);
    cudaGetSymbolAddress((void**)&buf3,  g_buf3);
    cudaGetSymbolAddress((void**)&z2,    g_z2);
    cudaGetSymbolAddress((void**)&e2,    g_e2);
    cudaGetSymbolAddress((void**)&idx,   g_idx);
    cudaGetSymbolAddress((void**)&chunk, g_chunk);

    const size_t BD = (size_t)B_ * D_;
    const size_t OFF_ZA = 0;
    const size_t OFF_LA = 2ull * B_ * D_;
    const size_t OFF_RA = OFF_LA + 2ull * B_;
    const size_t OFF_RB = OFF_RA + (size_t)B_ * 4096;
    const size_t OFF_XA = OFF_RB + (size_t)B_ * 2048;
    const size_t OFF_XB = OFF_XA + (size_t)B_ * 4096;

    const dim3 blk(256);
    float* zeB = ze + BD;

    e2_k<<<KCODES / 8, blk>>>(codebook, e2);

    // --- Encoders: fp32 bit-identical chain, A+B merged per stage ---
    gemm2m_k<1><<<dim3(4, 64, 2), blk>>>(
        x_a, x_b, enc_a_w, enc_b_w, enc_a_b, enc_b_b,
        nullptr, nullptr, buf0, buf0 + BD, B_, 256, 4096, 2048);
    gemm2m_k<2><<<dim3(4, 64, 2), blk>>>(
        buf0, buf0 + BD, enc_a_rw, enc_b_rw, enc_a_rb, enc_b_rb,
        buf0, buf0 + BD, buf1, buf1 + BD, B_, 256, 256, 256);
    gemm2m_k<2><<<dim3(4, 64, 2), blk>>>(
        buf1, buf1 + BD, enc_a_rw + 65536, enc_b_rw + 65536,
        enc_a_rb + 256, enc_b_rb + 256,
        buf1, buf1 + BD, ze, zeB, B_, 256, 256, 256);

    // --- VQ: bf16 approx scores -> chunk-min keys -> exact fp32 refine ---
    z2_k<<<2 * B_ / 8, blk>>>(ze, z2);
    vq_bf16_k<<<dim3(KCODES / 64, 2 * B_ / 128), blk>>>(ze, codebook, e2, z2, chunk);
    refine2_k<<<2 * B_, blk>>>(chunk, ze, codebook, z2, e2, idx);
    vq_apply_k<<<2 * B_, blk>>>(ze, codebook, idx, out + OFF_ZA, out + OFF_LA);

    // --- Decoders: merged resblocks (dec_a/dec_b share input), then
    //     double-buffered 128x128 finals ---
    // res1: z=0 -> dec_a (out->buf0), z=1 -> dec_b (out->buf1)
    gemm_tcm<<<dim3(4, 128, 2), blk>>>(
        out, dec_a_rw, dec_b_rw, dec_a_rb, dec_b_rb, out,
        buf0, buf1, nullptr, nullptr, 2 * B_, 256, 256);
    // res2: z=0 -> dec_a (buf0->buf2), z=1 -> dec_b (buf1->buf3)
    gemm_tcm<<<dim3(4, 128, 2), blk>>>(
        buf0, dec_a_rw + 65536, dec_b_rw + 65536, dec_a_rb + 256, dec_b_rb + 256,
        buf0, buf2, buf3, buf1, buf1, 2 * B_, 256, 256);

    // final A: rows<8192 -> recon_a, rows>=8192 -> cross_recon_a
    gemm_tc2<<<dim3(32, 128), blk>>>(buf2, dec_a_w, dec_a_b,
                                     out + OFF_RA, out + OFF_XA, B_,
                                     2 * B_, 4096, 256);
    // final B: rows<8192 (z_a) -> cross_recon_b, rows>=8192 (z_b) -> recon_b
    gemm_tc2<<<dim3(16, 128), blk>>>(buf3, dec_b_w, dec_b_b,
                                     out + OFF_XB, out + OFF_RB, B_,
                                     2 * B_, 2048, 256);
}

// round 14
// speedup vs baseline: 2.5826x; 1.0028x over previous
#include <cuda_runtime.h>
#include <stdint.h>

#define B_ 8192
#define D_ 256
#define KCODES 8192
#define NCHUNK (KCODES / 32)     // 256 chunk keys per row
#define MARGIN 4e-4f

typedef unsigned long long ull;

// Scratch (device globals; no allocation allowed)
__device__ float g_ze[2 * B_ * D_];       // [zeA; zeB]
__device__ float g_buf0[2 * B_ * D_];
__device__ float g_buf1[2 * B_ * D_];
__device__ float g_buf2[2 * B_ * D_];
__device__ float g_buf3[2 * B_ * D_];
__device__ float g_z2[2 * B_];
__device__ float g_e2[KCODES];
__device__ ull   g_chunk[(size_t)2 * B_ * NCHUNK];   // 32 MB chunk-min keys

// ---------------------------------------------------------------------------
// Merged dual-problem fp32 SIMT GEMM (bit-identical accumulation chain).
// Tile 128x64, BK=16, 8x4 micro-tile. blockIdx.z selects problem {0,1}.
// EPI 1: relu(.+bias); 2: Res + relu(.+bias)
// ---------------------------------------------------------------------------
template <int EPI>
__global__ void __launch_bounds__(256) gemm2m_k(
    const float* __restrict__ A0, const float* __restrict__ A1,
    const float* __restrict__ W0, const float* __restrict__ W1,
    const float* __restrict__ bias0, const float* __restrict__ bias1,
    const float* __restrict__ Res0, const float* __restrict__ Res1,
    float* __restrict__ C0, float* __restrict__ C1,
    int M, int N, int K0, int K1)
{
    const float* A    = blockIdx.z ? A1 : A0;
    const float* Bm   = blockIdx.z ? W1 : W0;
    const float* bias = blockIdx.z ? bias1 : bias0;
    const float* Res  = blockIdx.z ? Res1 : Res0;
    float* C          = blockIdx.z ? C1 : C0;
    const int K       = blockIdx.z ? K1 : K0;

    __shared__ float As[16][132];
    __shared__ float Bs[16][64];

    const int t  = threadIdx.x;
    const int ty = t >> 4;
    const int tx = t & 15;
    const int m0 = blockIdx.y * 128;
    const int n0 = blockIdx.x * 64;

    const int brow = t >> 4, bseg = t & 15;

    float acc[8][4];
#pragma unroll
    for (int i = 0; i < 8; i++)
#pragma unroll
        for (int j = 0; j < 4; j++) acc[i][j] = 0.f;

    for (int kb = 0; kb < K; kb += 16) {
#pragma unroll
        for (int i = 0; i < 2; i++) {
            int f = t + i * 256;
            int row = f >> 2, seg = f & 3;
            float4 v = *(const float4*)&A[(size_t)(m0 + row) * K + kb + seg * 4];
            As[seg * 4 + 0][row] = v.x;
            As[seg * 4 + 1][row] = v.y;
            As[seg * 4 + 2][row] = v.z;
            As[seg * 4 + 3][row] = v.w;
        }
        {
            float4 v = *(const float4*)&Bm[(size_t)(kb + brow) * N + n0 + bseg * 4];
            *(float4*)&Bs[brow][bseg * 4] = v;
        }
        __syncthreads();
#pragma unroll
        for (int kk = 0; kk < 16; kk++) {
            float4 a0 = *(const float4*)&As[kk][ty * 8];
            float4 a1 = *(const float4*)&As[kk][ty * 8 + 4];
            float4 b4 = *(const float4*)&Bs[kk][tx * 4];
            float a[8] = {a0.x, a0.y, a0.z, a0.w, a1.x, a1.y, a1.z, a1.w};
            float b[4] = {b4.x, b4.y, b4.z, b4.w};
#pragma unroll
            for (int i = 0; i < 8; i++)
#pragma unroll
                for (int j = 0; j < 4; j++) acc[i][j] += a[i] * b[j];
        }
        __syncthreads();
    }

    float4 bb = *(const float4*)&bias[n0 + tx * 4];
    float bcol[4] = {bb.x, bb.y, bb.z, bb.w};
#pragma unroll
    for (int i = 0; i < 8; i++) {
        int m = m0 + ty * 8 + i;
        float v[4];
#pragma unroll
        for (int j = 0; j < 4; j++) {
            v[j] = acc[i][j] + bcol[j];
            if (EPI >= 1) v[j] = fmaxf(v[j], 0.f);
        }
        if (EPI == 2) {
            float4 r = *(const float4*)&Res[(size_t)m * N + n0 + tx * 4];
            v[0] += r.x; v[1] += r.y; v[2] += r.z; v[3] += r.w;
        }
        float4 o = {v[0], v[1], v[2], v[3]};
        *(float4*)&C[(size_t)m * N + n0 + tx * 4] = o;
    }
}

// ---------------------------------------------------------------------------
// bf16 / tf32 helpers
// ---------------------------------------------------------------------------
__device__ __forceinline__ uint32_t packbf(float lo, float hi) {
    uint32_t r;
    asm("cvt.rn.bf16x2.f32 %0, %1, %2;" : "=r"(r) : "f"(hi), "f"(lo));
    return r;
}

__device__ __forceinline__ void mma_bf16(float* d, const uint32_t* a, const uint32_t* b) {
    asm volatile(
        "mma.sync.aligned.m16n8k16.row.col.f32.bf16.bf16.f32 "
        "{%0,%1,%2,%3}, {%4,%5,%6,%7}, {%8,%9}, {%0,%1,%2,%3};\n"
        : "+f"(d[0]), "+f"(d[1]), "+f"(d[2]), "+f"(d[3])
        : "r"(a[0]), "r"(a[1]), "r"(a[2]), "r"(a[3]), "r"(b[0]), "r"(b[1]));
}

__device__ __forceinline__ uint32_t f2tf32(float x) {
    uint32_t r;
    asm("cvt.rna.tf32.f32 %0, %1;" : "=r"(r) : "f"(x));
    return r;
}

__device__ __forceinline__ void mma_tf32(float* d, const uint32_t* a, const uint32_t* b) {
    asm volatile(
        "mma.sync.aligned.m16n8k8.row.col.f32.tf32.tf32.f32 "
        "{%0,%1,%2,%3}, {%4,%5,%6,%7}, {%8,%9}, {%0,%1,%2,%3};\n"
        : "+f"(d[0]), "+f"(d[1]), "+f"(d[2]), "+f"(d[3])
        : "r"(a[0]), "r"(a[1]), "r"(a[2]), "r"(a[3]), "r"(b[0]), "r"(b[1]));
}

// ---------------------------------------------------------------------------
// bf16 VQ score GEMM, BK=32, double-buffered smem + register prefetch.
// Candidate nomination only (exact fp32 rescoring follows in refine).
// Tile 128 rows x 64 codes. Chunk-min epilogue identical to R12/R13.
// ---------------------------------------------------------------------------
__global__ void __launch_bounds__(256) vq_bf16_k(
    const float* __restrict__ Z, const float* __restrict__ E,
    const float* __restrict__ e2, const float* __restrict__ z2,
    ull* __restrict__ chunkOut)
{
    __shared__ uint32_t Apk[2][16][136];   // k-pair x m
    __shared__ uint32_t Bpk[2][16][72];    // k-pair x n

    const int t = threadIdx.x;
    const int lane = t & 31;
    const int warp = t >> 5;
    const int warpM = warp & 3;
    const int warpN = warp >> 2;
    const int m0 = blockIdx.y * 128;
    const int n0 = blockIdx.x * 64;

    float acc[2][4][4];
#pragma unroll
    for (int mt = 0; mt < 2; mt++)
#pragma unroll
        for (int nt = 0; nt < 4; nt++)
#pragma unroll
            for (int c = 0; c < 4; c++) acc[mt][nt][c] = 0.f;

    const int zr = t >> 3, zs = t & 7;   // Z loader: rows zr+32i, seg zs (i<4)
    const int er = t >> 3, es = t & 7;   // E loader: codes er+32i, seg es (i<2)

    // preload kb=0
    {
#pragma unroll
        for (int i = 0; i < 4; i++) {
            int row = zr + i * 32;
            float4 v = *(const float4*)&Z[(size_t)(m0 + row) * 256 + zs * 4];
            Apk[0][zs * 2 + 0][row] = packbf(v.x, v.y);
            Apk[0][zs * 2 + 1][row] = packbf(v.z, v.w);
        }
#pragma unroll
        for (int i = 0; i < 2; i++) {
            int code = er + i * 32;
            float4 v = *(const float4*)&E[(size_t)(n0 + code) * 256 + es * 4];
            Bpk[0][es * 2 + 0][code] = packbf(v.x, v.y);
            Bpk[0][es * 2 + 1][code] = packbf(v.z, v.w);
        }
    }
    __syncthreads();

    int p = 0;
    for (int kb = 32; kb <= 256; kb += 32) {
        float4 za[4], eb[2];
        const bool more = (kb < 256);
        if (more) {
#pragma unroll
            for (int i = 0; i < 4; i++)
                za[i] = *(const float4*)&Z[(size_t)(m0 + zr + i * 32) * 256 + kb + zs * 4];
#pragma unroll
            for (int i = 0; i < 2; i++)
                eb[i] = *(const float4*)&E[(size_t)(n0 + er + i * 32) * 256 + kb + es * 4];
        }

        // compute on buffer p: two k16 steps
#pragma unroll
        for (int ks = 0; ks < 2; ks++) {
            uint32_t a[2][4], b[4][2];
            const int ar = warpM * 32 + (lane >> 2);
            const int kq = ks * 8 + (lane & 3);
#pragma unroll
            for (int mt = 0; mt < 2; mt++) {
                a[mt][0] = Apk[p][kq][ar + mt * 16];
                a[mt][1] = Apk[p][kq][ar + mt * 16 + 8];
                a[mt][2] = Apk[p][kq + 4][ar + mt * 16];
                a[mt][3] = Apk[p][kq + 4][ar + mt * 16 + 8];
            }
#pragma unroll
            for (int nt = 0; nt < 4; nt++) {
                int nn = warpN * 32 + nt * 8 + (lane >> 2);
                b[nt][0] = Bpk[p][kq][nn];
                b[nt][1] = Bpk[p][kq + 4][nn];
            }
#pragma unroll
            for (int mt = 0; mt < 2; mt++)
#pragma unroll
                for (int nt = 0; nt < 4; nt++)
                    mma_bf16(acc[mt][nt], a[mt], b[nt]);
        }

        if (more) {
            int q = p ^ 1;
#pragma unroll
            for (int i = 0; i < 4; i++) {
                int row = zr + i * 32;
                Apk[q][zs * 2 + 0][row] = packbf(za[i].x, za[i].y);
                Apk[q][zs * 2 + 1][row] = packbf(za[i].z, za[i].w);
            }
#pragma unroll
            for (int i = 0; i < 2; i++) {
                int code = er + i * 32;
                Bpk[q][es * 2 + 0][code] = packbf(eb[i].x, eb[i].y);
                Bpk[q][es * 2 + 1][code] = packbf(eb[i].z, eb[i].w);
            }
            __syncthreads();
            p = q;
        }
    }

    // chunk-min epilogue (identical to R12/R13)
    ull best[2][2] = {{~0ull, ~0ull}, {~0ull, ~0ull}};
#pragma unroll
    for (int mt = 0; mt < 2; mt++)
#pragma unroll
        for (int h = 0; h < 2; h++) {
            int m = m0 + warpM * 32 + mt * 16 + (lane >> 2) + h * 8;
            float z2m = z2[m];
#pragma unroll
            for (int nt = 0; nt < 4; nt++) {
                int n = n0 + warpN * 32 + nt * 8 + 2 * (lane & 3);
                float2 e2v = *(const float2*)&e2[n];
                float sx = __fadd_rn(__fadd_rn(z2m, e2v.x), -2.f * acc[mt][nt][h * 2 + 0]);
                float sy = __fadd_rn(__fadd_rn(z2m, e2v.y), -2.f * acc[mt][nt][h * 2 + 1]);
                ull kx = ((ull)__float_as_uint(sx) << 32) | (unsigned)n;
                ull ky = ((ull)__float_as_uint(sy) << 32) | (unsigned)(n + 1);
                if (kx < best[mt][h]) best[mt][h] = kx;
                if (ky < best[mt][h]) best[mt][h] = ky;
            }
        }
    const int chunk = blockIdx.x * 2 + warpN;
#pragma unroll
    for (int mt = 0; mt < 2; mt++)
#pragma unroll
        for (int h = 0; h < 2; h++) {
            ull k = best[mt][h];
            ull o = __shfl_xor_sync(0xFFFFFFFFu, k, 1); if (o < k) k = o;
            o = __shfl_xor_sync(0xFFFFFFFFu, k, 2); if (o < k) k = o;
            if ((lane & 3) == 0) {
                int m = m0 + warpM * 32 + mt * 16 + (lane >> 2) + h * 8;
                chunkOut[(size_t)m * NCHUNK + chunk] = k;
            }
        }
}

// ---------------------------------------------------------------------------
// Merged dual-problem tf32 resblock GEMM (decoder res blocks).
// C = Res + relu(A @ W + bias). blockIdx.z selects weights/output.
// ---------------------------------------------------------------------------
__global__ void __launch_bounds__(256) gemm_tcm(
    const float* __restrict__ A, const float* __restrict__ W0,
    const float* __restrict__ W1, const float* __restrict__ bias0,
    const float* __restrict__ bias1, const float* __restrict__ Res,
    float* __restrict__ C0, float* __restrict__ C1,
    const float* __restrict__ A1in, const float* __restrict__ Res1in,
    int M, int N, int K)
{
    const float* Ap   = blockIdx.z ? (A1in ? A1in : A) : A;
    const float* Bw   = blockIdx.z ? W1 : W0;
    const float* bias = blockIdx.z ? bias1 : bias0;
    const float* Res_ = blockIdx.z ? (Res1in ? Res1in : Res) : Res;
    float* C          = blockIdx.z ? C1 : C0;

    __shared__ float AsH[16][132];
    __shared__ float BsH[16][68];

    const int t = threadIdx.x;
    const int lane = t & 31;
    const int warp = t >> 5;
    const int warpM = warp & 3;
    const int warpN = warp >> 2;
    const int m0 = blockIdx.y * 128;
    const int n0 = blockIdx.x * 64;

    float acc[2][4][4];
#pragma unroll
    for (int mt = 0; mt < 2; mt++)
#pragma unroll
        for (int nt = 0; nt < 4; nt++)
#pragma unroll
            for (int c = 0; c < 4; c++) acc[mt][nt][c] = 0.f;

    const int aRow = t >> 2, aSeg = t & 3;
    const int bRow = t >> 4, bSeg = t & 15;

    for (int kb = 0; kb < K; kb += 16) {
#pragma unroll
        for (int h = 0; h < 2; h++) {
            int row = aRow + h * 64;
            float4 v = *(const float4*)&Ap[(size_t)(m0 + row) * K + kb + aSeg * 4];
            AsH[aSeg * 4 + 0][row] = __uint_as_float(f2tf32(v.x));
            AsH[aSeg * 4 + 1][row] = __uint_as_float(f2tf32(v.y));
            AsH[aSeg * 4 + 2][row] = __uint_as_float(f2tf32(v.z));
            AsH[aSeg * 4 + 3][row] = __uint_as_float(f2tf32(v.w));
        }
        {
            float4 v = *(const float4*)&Bw[(size_t)(kb + bRow) * N + n0 + bSeg * 4];
            BsH[bRow][bSeg * 4 + 0] = __uint_as_float(f2tf32(v.x));
            BsH[bRow][bSeg * 4 + 1] = __uint_as_float(f2tf32(v.y));
            BsH[bRow][bSeg * 4 + 2] = __uint_as_float(f2tf32(v.z));
            BsH[bRow][bSeg * 4 + 3] = __uint_as_float(f2tf32(v.w));
        }
        __syncthreads();

#pragma unroll
        for (int ks = 0; ks < 2; ks++) {
            uint32_t a[2][4], b[4][2];
            const int ar = warpM * 32 + (lane >> 2);
            const int ac = ks * 8 + (lane & 3);
#pragma unroll
            for (int mt = 0; mt < 2; mt++) {
                a[mt][0] = __float_as_uint(AsH[ac][ar + mt * 16]);
                a[mt][1] = __float_as_uint(AsH[ac][ar + mt * 16 + 8]);
                a[mt][2] = __float_as_uint(AsH[ac + 4][ar + mt * 16]);
                a[mt][3] = __float_as_uint(AsH[ac + 4][ar + mt * 16 + 8]);
            }
            const int bk = ks * 8 + (lane & 3);
#pragma unroll
            for (int nt = 0; nt < 4; nt++) {
                int nn = warpN * 32 + nt * 8 + (lane >> 2);
                b[nt][0] = __float_as_uint(BsH[bk][nn]);
                b[nt][1] = __float_as_uint(BsH[bk + 4][nn]);
            }
#pragma unroll
            for (int mt = 0; mt < 2; mt++)
#pragma unroll
                for (int nt = 0; nt < 4; nt++)
                    mma_tf32(acc[mt][nt], a[mt], b[nt]);
        }
        __syncthreads();
    }

#pragma unroll
    for (int mt = 0; mt < 2; mt++)
#pragma unroll
        for (int nt = 0; nt < 4; nt++) {
            int n = n0 + warpN * 32 + nt * 8 + 2 * (lane & 3);
            float2 bb = *(const float2*)&bias[n];
#pragma unroll
            for (int h = 0; h < 2; h++) {
                int m = m0 + warpM * 32 + mt * 16 + (lane >> 2) + h * 8;
                float vx = fmaxf(acc[mt][nt][h * 2 + 0] + bb.x, 0.f);
                float vy = fmaxf(acc[mt][nt][h * 2 + 1] + bb.y, 0.f);
                float2 r = *(const float2*)&Res_[(size_t)m * N + n];
                vx += r.x; vy += r.y;
                float2 o = {vx, vy};
                *(float2*)&C[(size_t)m * N + n] = o;
            }
        }
}

// ---------------------------------------------------------------------------
// tf32 GEMM, 128x128 tile, double-buffered (decoder finals, bias only).
// Rows >= rowSplit -> C1 at m-rowSplit.
// ---------------------------------------------------------------------------
__global__ void __launch_bounds__(256) gemm_tc2(
    const float* __restrict__ A, const float* __restrict__ Bw,
    const float* __restrict__ bias,
    float* __restrict__ C0, float* __restrict__ C1, int rowSplit,
    int M, int N, int K)
{
    __shared__ float As[2][16][132];
    __shared__ float Bs[2][16][132];

    const int t = threadIdx.x;
    const int lane = t & 31;
    const int warp = t >> 5;
    const int warpM = warp & 1;
    const int warpN = warp >> 1;
    const int m0 = blockIdx.y * 128;
    const int n0 = blockIdx.x * 128;

    const int ar0 = t >> 2,         as0 = t & 3;
    const int ar1 = (t + 256) >> 2, as1 = (t + 256) & 3;
    const int br0 = t >> 5,         bs0 = t & 31;
    const int br1 = (t + 256) >> 5, bs1 = (t + 256) & 31;

    float acc[4][4][4];
#pragma unroll
    for (int mt = 0; mt < 4; mt++)
#pragma unroll
        for (int nt = 0; nt < 4; nt++)
#pragma unroll
            for (int c = 0; c < 4; c++) acc[mt][nt][c] = 0.f;

    {
        float4 a0 = *(const float4*)&A[(size_t)(m0 + ar0) * K + as0 * 4];
        float4 a1 = *(const float4*)&A[(size_t)(m0 + ar1) * K + as1 * 4];
        float4 b0 = *(const float4*)&Bw[(size_t)br0 * N + n0 + bs0 * 4];
        float4 b1 = *(const float4*)&Bw[(size_t)br1 * N + n0 + bs1 * 4];
        As[0][as0 * 4 + 0][ar0] = __uint_as_float(f2tf32(a0.x));
        As[0][as0 * 4 + 1][ar0] = __uint_as_float(f2tf32(a0.y));
        As[0][as0 * 4 + 2][ar0] = __uint_as_float(f2tf32(a0.z));
        As[0][as0 * 4 + 3][ar0] = __uint_as_float(f2tf32(a0.w));
        As[0][as1 * 4 + 0][ar1] = __uint_as_float(f2tf32(a1.x));
        As[0][as1 * 4 + 1][ar1] = __uint_as_float(f2tf32(a1.y));
        As[0][as1 * 4 + 2][ar1] = __uint_as_float(f2tf32(a1.z));
        As[0][as1 * 4 + 3][ar1] = __uint_as_float(f2tf32(a1.w));
        Bs[0][br0][bs0 * 4 + 0] = __uint_as_float(f2tf32(b0.x));
        Bs[0][br0][bs0 * 4 + 1] = __uint_as_float(f2tf32(b0.y));
        Bs[0][br0][bs0 * 4 + 2] = __uint_as_float(f2tf32(b0.z));
        Bs[0][br0][bs0 * 4 + 3] = __uint_as_float(f2tf32(b0.w));
        Bs[0][br1][bs1 * 4 + 0] = __uint_as_float(f2tf32(b1.x));
        Bs[0][br1][bs1 * 4 + 1] = __uint_as_float(f2tf32(b1.y));
        Bs[0][br1][bs1 * 4 + 2] = __uint_as_float(f2tf32(b1.z));
        Bs[0][br1][bs1 * 4 + 3] = __uint_as_float(f2tf32(b1.w));
    }
    __syncthreads();

    int p = 0;
    for (int kb = 16; kb <= K; kb += 16) {
        float4 a0, a1, b0, b1;
        const bool more = (kb < K);
        if (more) {
            a0 = *(const float4*)&A[(size_t)(m0 + ar0) * K + kb + as0 * 4];
            a1 = *(const float4*)&A[(size_t)(m0 + ar1) * K + kb + as1 * 4];
            b0 = *(const float4*)&Bw[(size_t)(kb + br0) * N + n0 + bs0 * 4];
            b1 = *(const float4*)&Bw[(size_t)(kb + br1) * N + n0 + bs1 * 4];
        }

#pragma unroll
        for (int ks = 0; ks < 2; ks++) {
            uint32_t a[4][4], b[4][2];
            const int ar = warpM * 64 + (lane >> 2);
            const int ac = ks * 8 + (lane & 3);
#pragma unroll
            for (int mt = 0; mt < 4; mt++) {
                a[mt][0] = __float_as_uint(As[p][ac][ar + mt * 16]);
                a[mt][1] = __float_as_uint(As[p][ac][ar + mt * 16 + 8]);
                a[mt][2] = __float_as_uint(As[p][ac + 4][ar + mt * 16]);
                a[mt][3] = __float_as_uint(As[p][ac + 4][ar + mt * 16 + 8]);
            }
            const int bk = ks * 8 + (lane & 3);
#pragma unroll
            for (int nt = 0; nt < 4; nt++) {
                int nn = warpN * 32 + nt * 8 + (lane >> 2);
                b[nt][0] = __float_as_uint(Bs[p][bk][nn]);
                b[nt][1] = __float_as_uint(Bs[p][bk + 4][nn]);
            }
#pragma unroll
            for (int mt = 0; mt < 4; mt++)
#pragma unroll
                for (int nt = 0; nt < 4; nt++)
                    mma_tf32(acc[mt][nt], a[mt], b[nt]);
        }

        if (more) {
            int q = p ^ 1;
            As[q][as0 * 4 + 0][ar0] = __uint_as_float(f2tf32(a0.x));
            As[q][as0 * 4 + 1][ar0] = __uint_as_float(f2tf32(a0.y));
            As[q][as0 * 4 + 2][ar0] = __uint_as_float(f2tf32(a0.z));
            As[q][as0 * 4 + 3][ar0] = __uint_as_float(f2tf32(a0.w));
            As[q][as1 * 4 + 0][ar1] = __uint_as_float(f2tf32(a1.x));
            As[q][as1 * 4 + 1][ar1] = __uint_as_float(f2tf32(a1.y));
            As[q][as1 * 4 + 2][ar1] = __uint_as_float(f2tf32(a1.z));
            As[q][as1 * 4 + 3][ar1] = __uint_as_float(f2tf32(a1.w));
            Bs[q][br0][bs0 * 4 + 0] = __uint_as_float(f2tf32(b0.x));
            Bs[q][br0][bs0 * 4 + 1] = __uint_as_float(f2tf32(b0.y));
            Bs[q][br0][bs0 * 4 + 2] = __uint_as_float(f2tf32(b0.z));
            Bs[q][br0][bs0 * 4 + 3] = __uint_as_float(f2tf32(b0.w));
            Bs[q][br1][bs1 * 4 + 0] = __uint_as_float(f2tf32(b1.x));
            Bs[q][br1][bs1 * 4 + 1] = __uint_as_float(f2tf32(b1.y));
            Bs[q][br1][bs1 * 4 + 2] = __uint_as_float(f2tf32(b1.z));
            Bs[q][br1][bs1 * 4 + 3] = __uint_as_float(f2tf32(b1.w));
            __syncthreads();
            p = q;
        }
    }

#pragma unroll
    for (int mt = 0; mt < 4; mt++)
#pragma unroll
        for (int nt = 0; nt < 4; nt++) {
            int n = n0 + warpN * 32 + nt * 8 + 2 * (lane & 3);
            float2 bb = *(const float2*)&bias[n];
#pragma unroll
            for (int h = 0; h < 2; h++) {
                int m = m0 + warpM * 64 + mt * 16 + (lane >> 2) + h * 8;
                float vx = acc[mt][nt][h * 2 + 0] + bb.x;
                float vy = acc[mt][nt][h * 2 + 1] + bb.y;
                float* Cp; size_t mm;
                if (m < rowSplit) { Cp = C0; mm = (size_t)m; }
                else              { Cp = C1; mm = (size_t)(m - rowSplit); }
                float2 o = {vx, vy};
                *(float2*)&Cp[mm * (size_t)N + n] = o;
            }
        }
}

// ---------------------------------------------------------------------------
// Fused refine + VQ apply. One block per row:
//  1) chunk-min argmin + exact fp32 candidate rescoring (identical to R13),
//  2) straight-through write zOut = z + (q - z) and loss (identical exprs).
// ---------------------------------------------------------------------------
#define MAXCHUNK 64

__global__ void __launch_bounds__(256) refine_apply_k(
    const ull* __restrict__ chunkmin, const float* __restrict__ Zall,
    const float* __restrict__ E, const float* __restrict__ z2,
    const float* __restrict__ e2,
    float* __restrict__ zOut, float* __restrict__ loss)
{
    __shared__ float zrow[256];
    __shared__ ull   wmin[8];
    __shared__ int   chunks[MAXCHUNK];
    __shared__ int   cnt;
    __shared__ float sthresh;
    __shared__ ull   wbest[8];
    __shared__ int   sidx;
    __shared__ float red[8];

    const int m = blockIdx.x;
    const int t = threadIdx.x;
    const int warp = t >> 5, lane = t & 31;

    zrow[t] = Zall[(size_t)m * 256 + t];
    if (t == 0) cnt = 0;
    const ull ck = chunkmin[(size_t)m * NCHUNK + t];

    ull k = ck;
#pragma unroll
    for (int off = 16; off; off >>= 1) {
        ull o = __shfl_xor_sync(0xFFFFFFFFu, k, off);
        if (o < k) k = o;
    }
    if (lane == 0) wmin[warp] = k;
    __syncthreads();
    if (t < 8) {
        ull v = wmin[t];
#pragma unroll
        for (int off = 4; off; off >>= 1) {
            ull o = __shfl_xor_sync(0xFFu, v, off);
            if (o < v) v = o;
        }
        if (t == 0) sthresh = __uint_as_float((unsigned)(v >> 32)) + MARGIN;
    }
    __syncthreads();

    if (__uint_as_float((unsigned)(ck >> 32)) <= sthresh) {
        int p = atomicAdd(&cnt, 1);
        if (p < MAXCHUNK) chunks[p] = t;
    }
    __syncthreads();

    const int nc = cnt < MAXCHUNK ? cnt : MAXCHUNK;
    const float z2m = z2[m];
    ull best = ~0ull;
    for (int g = warp; g < nc * 32; g += 8) {
        int c = chunks[g >> 5] * 32 + (g & 31);
        const float* er = E + (size_t)c * 256;
        float dot = 0.f;
#pragma unroll
        for (int d = lane; d < 256; d += 32) dot += zrow[d] * er[d];
#pragma unroll
        for (int off = 16; off; off >>= 1)
            dot += __shfl_xor_sync(0xFFFFFFFFu, dot, off);
        if (lane == 0) {
            float s = __fadd_rn(__fadd_rn(z2m, e2[c]), -2.f * dot);
            ull key = ((ull)__float_as_uint(s) << 32) | (unsigned)c;
            if (key < best) best = key;
        }
    }
    if (lane == 0) wbest[warp] = best;
    __syncthreads();
    if (t < 8) {
        ull v = wbest[t];
#pragma unroll
        for (int off = 4; off; off >>= 1) {
            ull o = __shfl_xor_sync(0xFFu, v, off);
            if (o < v) v = o;
        }
        if (t == 0) sidx = (int)(v & 0xFFFFFFFFull);
    }
    __syncthreads();

    // --- apply phase (identical fp32 expressions to vq_apply_k) ---
    const int kidx = sidx;
    float z = zrow[t];
    float q = E[(size_t)kidx * 256 + t];
    zOut[(size_t)m * 256 + t] = __fadd_rn(z, __fsub_rn(q, z));
    float diff = z - q;
    float ss = diff * diff;
#pragma unroll
    for (int off = 16; off; off >>= 1) ss += __shfl_xor_sync(0xFFFFFFFFu, ss, off);
    if (lane == 0) red[warp] = ss;
    __syncthreads();
    if (t < 8) {
        float v = red[t];
#pragma unroll
        for (int off = 4; off; off >>= 1) v += __shfl_xor_sync(0xFFu, v, off);
        if (t == 0) loss[m] = v + 0.25f * v;
    }
}

// ---------------------------------------------------------------------------
// Small kernels
// ---------------------------------------------------------------------------
__global__ void __launch_bounds__(256) e2_k(const float* __restrict__ E,
                                            float* __restrict__ e2)
{
    int w = threadIdx.x >> 5, lane = threadIdx.x & 31;
    int code = blockIdx.x * 8 + w;
    float s = 0.f;
#pragma unroll
    for (int d = lane; d < 256; d += 32) {
        float v = E[(size_t)code * 256 + d];
        s += v * v;
    }
#pragma unroll
    for (int off = 16; off; off >>= 1) s += __shfl_xor_sync(0xFFFFFFFFu, s, off);
    if (lane == 0) e2[code] = s;
}

__global__ void __launch_bounds__(256) z2_k(const float* __restrict__ Z,
                                            float* __restrict__ z2)
{
    int w = threadIdx.x >> 5, lane = threadIdx.x & 31;
    int row = blockIdx.x * 8 + w;
    const float* zr = Z + (size_t)row * 256;
    float s = 0.f;
#pragma unroll
    for (int d = lane; d < 256; d += 32) { float v = zr[d]; s += v * v; }
#pragma unroll
    for (int off = 16; off; off >>= 1) s += __shfl_xor_sync(0xFFFFFFFFu, s, off);
    if (lane == 0) z2[row] = s;
}

// ---------------------------------------------------------------------------
// Host orchestration
// ---------------------------------------------------------------------------
extern "C" void kernel_launch(void* const* d_in, const int* in_sizes, int n_in,
                              void* d_out, int out_size)
{
    const float* x_a      = (const float*)d_in[0];
    const float* x_b      = (const float*)d_in[1];
    const float* enc_a_w  = (const float*)d_in[2];
    const float* enc_a_b  = (const float*)d_in[3];
    const float* enc_a_rw = (const float*)d_in[4];
    const float* enc_a_rb = (const float*)d_in[5];
    const float* enc_b_w  = (const float*)d_in[6];
    const float* enc_b_b  = (const float*)d_in[7];
    const float* enc_b_rw = (const float*)d_in[8];
    const float* enc_b_rb = (const float*)d_in[9];
    const float* dec_a_rw = (const float*)d_in[10];
    const float* dec_a_rb = (const float*)d_in[11];
    const float* dec_a_w  = (const float*)d_in[12];
    const float* dec_a_b  = (const float*)d_in[13];
    const float* dec_b_rw = (const float*)d_in[14];
    const float* dec_b_rb = (const float*)d_in[15];
    const float* dec_b_w  = (const float*)d_in[16];
    const float* dec_b_b  = (const float*)d_in[17];
    const float* codebook = (const float*)d_in[18];

    float* out = (float*)d_out;

    float *ze, *buf0, *buf1, *buf2, *buf3, *z2, *e2;
    ull* chunk;
    cudaGetSymbolAddress((void**)&ze,    g_ze);
    cudaGetSymbolAddress((void**)&buf0,  g_buf0);
    cudaGetSymbolAddress((void**)&buf1,  g_buf1);
    cudaGetSymbolAddress((void**)&buf2,  g_buf2);
    cudaGetSymbolAddress((void**)&buf3,  g_buf3);
    cudaGetSymbolAddress((void**)&z2,    g_z2);
    cudaGetSymbolAddress((void**)&e2,    g_e2);
    cudaGetSymbolAddress((void**)&chunk, g_chunk);

    const size_t BD = (size_t)B_ * D_;
    const size_t OFF_ZA = 0;
    const size_t OFF_LA = 2ull * B_ * D_;
    const size_t OFF_RA = OFF_LA + 2ull * B_;
    const size_t OFF_RB = OFF_RA + (size_t)B_ * 4096;
    const size_t OFF_XA = OFF_RB + (size_t)B_ * 2048;
    const size_t OFF_XB = OFF_XA + (size_t)B_ * 4096;

    const dim3 blk(256);
    float* zeB = ze + BD;

    e2_k<<<KCODES / 8, blk>>>(codebook, e2);

    // --- Encoders: fp32 bit-identical chain, A+B merged per stage ---
    gemm2m_k<1><<<dim3(4, 64, 2), blk>>>(
        x_a, x_b, enc_a_w, enc_b_w, enc_a_b, enc_b_b,
        nullptr, nullptr, buf0, buf0 + BD, B_, 256, 4096, 2048);
    gemm2m_k<2><<<dim3(4, 64, 2), blk>>>(
        buf0, buf0 + BD, enc_a_rw, enc_b_rw, enc_a_rb, enc_b_rb,
        buf0, buf0 + BD, buf1, buf1 + BD, B_, 256, 256, 256);
    gemm2m_k<2><<<dim3(4, 64, 2), blk>>>(
        buf1, buf1 + BD, enc_a_rw + 65536, enc_b_rw + 65536,
        enc_a_rb + 256, enc_b_rb + 256,
        buf1, buf1 + BD, ze, zeB, B_, 256, 256, 256);

    // --- VQ: bf16 approx (double-buffered) -> chunk-min -> fused refine+apply ---
    z2_k<<<2 * B_ / 8, blk>>>(ze, z2);
    vq_bf16_k<<<dim3(KCODES / 64, 2 * B_ / 128), blk>>>(ze, codebook, e2, z2, chunk);
    refine_apply_k<<<2 * B_, blk>>>(chunk, ze, codebook, z2, e2,
                                    out + OFF_ZA, out + OFF_LA);

    // --- Decoders: merged resblocks, then double-buffered 128x128 finals ---
    gemm_tcm<<<dim3(4, 128, 2), blk>>>(
        out, dec_a_rw, dec_b_rw, dec_a_rb, dec_b_rb, out,
        buf0, buf1, nullptr, nullptr, 2 * B_, 256, 256);
    gemm_tcm<<<dim3(4, 128, 2), blk>>>(
        buf0, dec_a_rw + 65536, dec_b_rw + 65536, dec_a_rb + 256, dec_b_rb + 256,
        buf0, buf2, buf3, buf1, buf1, 2 * B_, 256, 256);

    gemm_tc2<<<dim3(32, 128), blk>>>(buf2, dec_a_w, dec_a_b,
                                     out + OFF_RA, out + OFF_XA, B_,
                                     2 * B_, 4096, 256);
    gemm_tc2<<<dim3(16, 128), blk>>>(buf3, dec_b_w, dec_b_b,
                                     out + OFF_XB, out + OFF_RB, B_,
                                     2 * B_, 2048, 256);
}